// round 1
// baseline (speedup 1.0000x reference)
#include <cuda_runtime.h>
#include <cstdint>

#define BATCH 32
#define HH 56
#define WW 56
#define NTOK (HH*WW)            // 3136
#define CH 256
#define H2 4                    // heads per branch
#define DH 32                   // head dim
#define M_ALL (BATCH*NTOK)      // 100352
#define N1 196                  // sr-downsampled tokens per image (14*14)
#define M_SR (BATCH*N1)         // 6272
#define K_SR 4096               // 4*4*256
#define SCALE 0.17677669529663687f   // 32^-0.5

// ---------------- scratch (device globals; no allocation allowed) ----------------
__device__ float g_lepe_lin[(size_t)M_ALL*CH];
__device__ float g_lepe    [(size_t)M_ALL*CH];
__device__ float g_q1      [(size_t)M_ALL*128];
__device__ float g_q2      [(size_t)M_ALL*128];
__device__ float g_kv2     [(size_t)M_ALL*CH];
__device__ float g_im2col  [(size_t)M_SR*K_SR];
__device__ float g_x1s     [(size_t)M_SR*CH];
__device__ float g_kv1     [(size_t)M_SR*CH];
__device__ float g_x1      [(size_t)M_ALL*128];
__device__ float g_x2      [(size_t)M_ALL*128];
__device__ float g_pre     [(size_t)M_ALL*CH];

// ---------------- generic SGEMM: C[M,N] = A[M,K] @ B[K,N] (+bias) ----------------
// 128x128 block tile, BK=8, 256 threads, 8x8 per-thread register tile.
// Requires M%128==0, N%128==0, K%8==0 (all call sites satisfy this).
__global__ __launch_bounds__(256, 2)
void sgemm128(const float* __restrict__ A, const float* __restrict__ Bm,
              const float* __restrict__ bias, float* __restrict__ C,
              int M, int N, int K) {
    __shared__ float As[8][132];   // padded: stride 132 (mult of 4, odd/32 banks ok)
    __shared__ float Bs[8][128];
    int tid = threadIdx.x;
    int brow = blockIdx.y * 128;
    int bcol = blockIdx.x * 128;
    int a_r = tid >> 1;            // 0..127
    int a_k = (tid & 1) * 4;       // 0 or 4
    int b_r = tid >> 5;            // 0..7
    int b_c = (tid & 31) * 4;      // 0..124
    int ty = tid >> 4;             // 0..15
    int tx = tid & 15;             // 0..15
    float acc[8][8];
    #pragma unroll
    for (int i = 0; i < 8; i++)
        #pragma unroll
        for (int j = 0; j < 8; j++) acc[i][j] = 0.f;

    const float* Arow = A + (size_t)(brow + a_r) * K + a_k;
    const float* Brow = Bm + (size_t)b_r * N + bcol + b_c;

    for (int k0 = 0; k0 < K; k0 += 8) {
        float4 av = *(const float4*)(Arow + k0);
        As[a_k + 0][a_r] = av.x;
        As[a_k + 1][a_r] = av.y;
        As[a_k + 2][a_r] = av.z;
        As[a_k + 3][a_r] = av.w;
        float4 bv = *(const float4*)(Brow + (size_t)k0 * N);
        *(float4*)&Bs[b_r][b_c] = bv;
        __syncthreads();
        #pragma unroll
        for (int kk = 0; kk < 8; kk++) {
            float a[8], b[8];
            *(float4*)(a    ) = *(const float4*)&As[kk][ty * 8];
            *(float4*)(a + 4) = *(const float4*)&As[kk][ty * 8 + 4];
            *(float4*)(b    ) = *(const float4*)&Bs[kk][tx * 8];
            *(float4*)(b + 4) = *(const float4*)&Bs[kk][tx * 8 + 4];
            #pragma unroll
            for (int i = 0; i < 8; i++)
                #pragma unroll
                for (int j = 0; j < 8; j++)
                    acc[i][j] += a[i] * b[j];
        }
        __syncthreads();
    }
    #pragma unroll
    for (int i = 0; i < 8; i++) {
        size_t r = (size_t)(brow + ty * 8 + i);
        float* Cp = C + r * N + bcol + tx * 8;
        #pragma unroll
        for (int j = 0; j < 8; j++) {
            float v = acc[i][j];
            if (bias) v += bias[bcol + tx * 8 + j];
            Cp[j] = v;
        }
    }
}

// ---------------- depthwise 3x3 conv, SAME padding, NHWC ----------------
__global__ void dwconv3x3(const float* __restrict__ in, const float* __restrict__ w,
                          const float* __restrict__ bias, float* __restrict__ out) {
    int idx = blockIdx.x * 256 + threadIdx.x;
    if (idx >= M_ALL * CH) return;
    int c = idx & 255;
    int t = idx >> 8;
    int xx = t % WW; t /= WW;
    int y  = t % HH;
    int b  = t / HH;
    float acc = bias[c];
    #pragma unroll
    for (int dy = 0; dy < 3; dy++) {
        int iy = y + dy - 1;
        if (iy < 0 || iy >= HH) continue;
        #pragma unroll
        for (int dx = 0; dx < 3; dx++) {
            int ix = xx + dx - 1;
            if (ix < 0 || ix >= WW) continue;
            acc += in[(((size_t)b * NTOK) + iy * WW + ix) * CH + c] * w[(dy * 3 + dx) * CH + c];
        }
    }
    out[idx] = acc;
}

// ---------------- im2col for the 4x4/stride-4 sr conv (non-overlapping gather) ----------------
__global__ void im2col_sr(const float* __restrict__ x, float* __restrict__ A) {
    int idx = blockIdx.x * 256 + threadIdx.x;
    if (idx >= M_SR * K_SR) return;
    int k = idx & 4095;
    int m = idx >> 12;
    int ow = m % 14; int t = m / 14;
    int oh = t % 14; int b = t / 14;
    int c = k & 255;
    int khw = k >> 8;
    int kh = khw >> 2, kw = khw & 3;
    int y = oh * 4 + kh, xx = ow * 4 + kw;
    A[idx] = x[(((size_t)b * NTOK) + y * WW + xx) * CH + c];
}

// ---------------- LayerNorm + exact GELU (in-place), one block per row of 256 ----------------
__global__ void ln_gelu(float* __restrict__ xb, const float* __restrict__ g,
                        const float* __restrict__ bb) {
    int row = blockIdx.x;
    int tid = threadIdx.x;
    float v = xb[(size_t)row * CH + tid];
    __shared__ float s1[256], s2[256];
    s1[tid] = v; s2[tid] = v * v;
    __syncthreads();
    for (int o = 128; o; o >>= 1) {
        if (tid < o) { s1[tid] += s1[tid + o]; s2[tid] += s2[tid + o]; }
        __syncthreads();
    }
    float mu  = s1[0] * (1.f / CH);
    float var = s2[0] * (1.f / CH) - mu * mu;
    float t = (v - mu) * rsqrtf(var + 1e-5f) * g[tid] + bb[tid];
    xb[(size_t)row * CH + tid] = 0.5f * t * (1.f + erff(t * 0.70710678118654752f));
}

// ---------------- branch-1 attention: per (b,h), q chunk of 32 vs 196 kv ----------------
// dynamic smem: qs[32*33] ks[196*33] vs[196*33] Ss[32*197] = 20296 floats = 81184 B
#define ATTN1_SMEM 81184
__global__ void attn1_kernel(const float* __restrict__ q1, const float* __restrict__ kv1,
                             float* __restrict__ x1) {
    extern __shared__ float sm[];
    float* qs = sm;                 // 32*33
    float* ks = qs + 32 * 33;       // 196*33
    float* vs = ks + 196 * 33;      // 196*33
    float* Ss = vs + 196 * 33;      // 32*197
    int bh = blockIdx.y; int b = bh >> 2; int h = bh & 3;
    int q0 = blockIdx.x * 32;
    int tid = threadIdx.x;

    for (int e = tid; e < 32 * 32; e += 256) {
        int i = e >> 5, dd = e & 31;
        qs[i * 33 + dd] = q1[((size_t)b * NTOK + q0 + i) * 128 + h * 32 + dd];
    }
    for (int e = tid; e < 196 * 32; e += 256) {
        int m = e >> 5, dd = e & 31;
        size_t base = ((size_t)b * N1 + m) * 256 + h * 32 + dd;
        ks[m * 33 + dd] = kv1[base];
        vs[m * 33 + dd] = kv1[base + 128];
    }
    __syncthreads();

    // scores: thread -> (query i = tid/8, key stride-8 lane dg), q held in registers
    int i  = tid >> 3;
    int dg = tid & 7;
    {
        float qreg[32];
        #pragma unroll
        for (int dd = 0; dd < 32; dd++) qreg[dd] = qs[i * 33 + dd];
        for (int mm = 0; mm < 25; mm++) {
            int m = dg + (mm << 3);
            if (m < 196) {
                float acc = 0.f;
                #pragma unroll
                for (int dd = 0; dd < 32; dd++) acc += qreg[dd] * ks[m * 33 + dd];
                Ss[i * 197 + m] = acc * SCALE;
            }
        }
    }
    __syncthreads();

    // softmax: warp w handles rows 4w..4w+3
    int warp = tid >> 5, lane = tid & 31;
    #pragma unroll
    for (int r = 0; r < 4; r++) {
        int row = warp * 4 + r;
        float mx = -1e30f;
        for (int m = lane; m < 196; m += 32) mx = fmaxf(mx, Ss[row * 197 + m]);
        #pragma unroll
        for (int o = 16; o; o >>= 1) mx = fmaxf(mx, __shfl_xor_sync(0xffffffffu, mx, o));
        float sum = 0.f;
        for (int m = lane; m < 196; m += 32) {
            float p = __expf(Ss[row * 197 + m] - mx);
            Ss[row * 197 + m] = p;
            sum += p;
        }
        #pragma unroll
        for (int o = 16; o; o >>= 1) sum += __shfl_xor_sync(0xffffffffu, sum, o);
        float inv = 1.f / sum;
        for (int m = lane; m < 196; m += 32) Ss[row * 197 + m] *= inv;
    }
    __syncthreads();

    // out = P @ V : thread (i, dg) accumulates dims dg, dg+8, dg+16, dg+24
    float acc[4] = {0.f, 0.f, 0.f, 0.f};
    for (int m = 0; m < 196; m++) {
        float p = Ss[i * 197 + m];
        #pragma unroll
        for (int j = 0; j < 4; j++) acc[j] += p * vs[m * 33 + dg + 8 * j];
    }
    size_t ob = ((size_t)b * NTOK + q0 + i) * 128 + h * 32;
    #pragma unroll
    for (int j = 0; j < 4; j++) x1[ob + dg + 8 * j] = acc[j];
}

// ---------------- branch-2 window attention: one block per (b,h,window) 49x49 ----------------
__global__ void attn2_kernel(const float* __restrict__ q2, const float* __restrict__ kv2,
                             float* __restrict__ x2) {
    __shared__ float qs[49 * 33], ks[49 * 33], vs[49 * 33], Ss[49 * 50];
    int bh = blockIdx.y; int b = bh >> 2; int h = bh & 3;
    int win = blockIdx.x; int wr = win >> 3, wc = win & 7;
    int tid = threadIdx.x;

    for (int e = tid; e < 49 * 32; e += 256) {
        int j = e >> 5, dd = e & 31;
        int row = wr * 7 + j / 7, col = wc * 7 + j % 7;
        int n = row * WW + col;
        qs[j * 33 + dd] = q2[((size_t)b * NTOK + n) * 128 + h * 32 + dd];
        size_t kb = ((size_t)b * NTOK + n) * 256 + h * 32 + dd;
        ks[j * 33 + dd] = kv2[kb];
        vs[j * 33 + dd] = kv2[kb + 128];
    }
    __syncthreads();

    for (int e = tid; e < 49 * 49; e += 256) {
        int i = e / 49, m = e % 49;
        float acc = 0.f;
        #pragma unroll
        for (int dd = 0; dd < 32; dd++) acc += qs[i * 33 + dd] * ks[m * 33 + dd];
        Ss[i * 50 + m] = acc * SCALE;
    }
    __syncthreads();

    int warp = tid >> 5, lane = tid & 31;
    for (int row = warp; row < 49; row += 8) {
        float mx = -1e30f;
        for (int m = lane; m < 49; m += 32) mx = fmaxf(mx, Ss[row * 50 + m]);
        #pragma unroll
        for (int o = 16; o; o >>= 1) mx = fmaxf(mx, __shfl_xor_sync(0xffffffffu, mx, o));
        float sum = 0.f;
        for (int m = lane; m < 49; m += 32) {
            float p = __expf(Ss[row * 50 + m] - mx);
            Ss[row * 50 + m] = p;
            sum += p;
        }
        #pragma unroll
        for (int o = 16; o; o >>= 1) sum += __shfl_xor_sync(0xffffffffu, sum, o);
        float inv = 1.f / sum;
        for (int m = lane; m < 49; m += 32) Ss[row * 50 + m] *= inv;
    }
    __syncthreads();

    int dg = tid & 7;
    for (int i = tid >> 3; i < 49; i += 32) {
        float acc[4] = {0.f, 0.f, 0.f, 0.f};
        for (int m = 0; m < 49; m++) {
            float p = Ss[i * 50 + m];
            #pragma unroll
            for (int j = 0; j < 4; j++) acc[j] += p * vs[m * 33 + dg + 8 * j];
        }
        int row = wr * 7 + i / 7, col = wc * 7 + i % 7;
        int n = row * WW + col;
        size_t ob = ((size_t)b * NTOK + n) * 128 + h * 32;
        #pragma unroll
        for (int j = 0; j < 4; j++) x2[ob + dg + 8 * j] = acc[j];
    }
}

// ---------------- concat(x1,x2) + lepe ----------------
__global__ void combine_kernel(const float* __restrict__ x1, const float* __restrict__ x2,
                               const float* __restrict__ lepe, float* __restrict__ pre) {
    int idx = blockIdx.x * 256 + threadIdx.x;
    if (idx >= M_ALL * CH) return;
    int c = idx & 255;
    int m = idx >> 8;
    float v = (c < 128) ? x1[(size_t)m * 128 + c] : x2[(size_t)m * 128 + c - 128];
    pre[idx] = v + lepe[idx];
}

// ---------------- host launch ----------------
extern "C" void kernel_launch(void* const* d_in, const int* in_sizes, int n_in,
                              void* d_out, int out_size) {
    const float* x           = (const float*)d_in[0];
    const float* lepe_lin_w  = (const float*)d_in[1];
    const float* lepe_lin_b  = (const float*)d_in[2];
    const float* lepe_conv_w = (const float*)d_in[3];
    const float* lepe_conv_b = (const float*)d_in[4];
    const float* sr_w        = (const float*)d_in[5];
    const float* sr_b        = (const float*)d_in[6];
    const float* norm_g      = (const float*)d_in[7];
    const float* norm_b      = (const float*)d_in[8];
    const float* q1_w        = (const float*)d_in[9];
    const float* kv1_w       = (const float*)d_in[10];
    const float* q2_w        = (const float*)d_in[11];
    const float* kv2_w       = (const float*)d_in[12];
    const float* proj_w      = (const float*)d_in[13];
    const float* proj_b      = (const float*)d_in[14];
    float* out = (float*)d_out;

    float *lepe_lin, *lepe, *q1, *q2, *kv2, *im2, *x1s, *kv1, *x1, *x2, *pre;
    cudaGetSymbolAddress((void**)&lepe_lin, g_lepe_lin);
    cudaGetSymbolAddress((void**)&lepe,     g_lepe);
    cudaGetSymbolAddress((void**)&q1,       g_q1);
    cudaGetSymbolAddress((void**)&q2,       g_q2);
    cudaGetSymbolAddress((void**)&kv2,      g_kv2);
    cudaGetSymbolAddress((void**)&im2,      g_im2col);
    cudaGetSymbolAddress((void**)&x1s,      g_x1s);
    cudaGetSymbolAddress((void**)&kv1,      g_kv1);
    cudaGetSymbolAddress((void**)&x1,       g_x1);
    cudaGetSymbolAddress((void**)&x2,       g_x2);
    cudaGetSymbolAddress((void**)&pre,      g_pre);

    const int EW_BLK = 256;
    int n_full = M_ALL * CH;          // 25,690,112
    int n_im   = M_SR * K_SR;         // 25,690,112

    // lepe: linear + depthwise conv
    sgemm128<<<dim3(2, M_ALL / 128), 256>>>(x, lepe_lin_w, lepe_lin_b, lepe_lin, M_ALL, 256, 256);
    dwconv3x3<<<(n_full + EW_BLK - 1) / EW_BLK, EW_BLK>>>(lepe_lin, lepe_conv_w, lepe_conv_b, lepe);

    // projections from x
    sgemm128<<<dim3(1, M_ALL / 128), 256>>>(x, q1_w,  nullptr, q1,  M_ALL, 128, 256);
    sgemm128<<<dim3(1, M_ALL / 128), 256>>>(x, q2_w,  nullptr, q2,  M_ALL, 128, 256);
    sgemm128<<<dim3(2, M_ALL / 128), 256>>>(x, kv2_w, nullptr, kv2, M_ALL, 256, 256);

    // sr conv as im2col + GEMM, then LN+GELU, then kv1
    im2col_sr<<<(n_im + EW_BLK - 1) / EW_BLK, EW_BLK>>>(x, im2);
    sgemm128<<<dim3(2, M_SR / 128), 256>>>(im2, sr_w, sr_b, x1s, M_SR, 256, K_SR);
    ln_gelu<<<M_SR, 256>>>(x1s, norm_g, norm_b);
    sgemm128<<<dim3(2, M_SR / 128), 256>>>(x1s, kv1_w, nullptr, kv1, M_SR, 256, 256);

    // attention branches
    cudaFuncSetAttribute(attn1_kernel, cudaFuncAttributeMaxDynamicSharedMemorySize, ATTN1_SMEM);
    attn1_kernel<<<dim3(NTOK / 32, BATCH * H2), 256, ATTN1_SMEM>>>(q1, kv1, x1);
    attn2_kernel<<<dim3(64, BATCH * H2), 256>>>(q2, kv2, x2);

    // concat + lepe, final projection
    combine_kernel<<<(n_full + EW_BLK - 1) / EW_BLK, EW_BLK>>>(x1, x2, lepe, pre);
    sgemm128<<<dim3(2, M_ALL / 128), 256>>>(pre, proj_w, proj_b, out, M_ALL, 256, 256);
}

// round 2
// speedup vs baseline: 1.7950x; 1.7950x over previous
#include <cuda_runtime.h>
#include <cstdint>

#define BATCH 32
#define HH 56
#define WW 56
#define NTOK (HH*WW)            // 3136
#define CH 256
#define H2 4                    // heads per branch
#define DH 32                   // head dim
#define M_ALL (BATCH*NTOK)      // 100352
#define N1 196                  // sr-downsampled tokens per image (14*14)
#define M_SR (BATCH*N1)         // 6272
#define K_SR 4096               // 4*4*256
#define SCALE 0.17677669529663687f   // 32^-0.5

// ---------------- scratch (device globals; no allocation allowed) ----------------
__device__ float g_lepe_lin[(size_t)M_ALL*CH];
__device__ float g_lepe    [(size_t)M_ALL*CH];
__device__ float g_q1      [(size_t)M_ALL*128];
__device__ float g_q2      [(size_t)M_ALL*128];
__device__ float g_kv2     [(size_t)M_ALL*CH];
__device__ float g_im2col  [(size_t)M_SR*K_SR];
__device__ float g_x1s     [(size_t)M_SR*CH];
__device__ float g_kv1     [(size_t)M_SR*CH];
__device__ float g_x1      [(size_t)M_ALL*128];
__device__ float g_x2      [(size_t)M_ALL*128];
__device__ float g_pre     [(size_t)M_ALL*CH];

// ---------------- tf32 tensor-core GEMM ----------------
// C[M,N] = A[M,K] @ B[K,N] (+bias). 128x128 CTA tile, BK=32, 256 threads.
// Warp grid 2(m) x 4(n): 64x32 warp tile = 4x4 m16n8k8 mma tiles, 4 k-steps.
// Double-buffered smem via cp.async. A: m-major stride 36; B: k-major stride 132
// (both give (4r+c)%32 fragment-load bank mapping -> conflict free).
// Requires M%128==0, N%128==0, K%32==0.

#define ASTRIDE 36
#define BSTRIDE 132
#define ABUF (128*ASTRIDE)
#define BBUF (32*BSTRIDE)
#define TG_SMEM ((2*ABUF + 2*BBUF) * 4)   // 70656 bytes

__device__ __forceinline__ uint32_t f2tf(float f) {
    uint32_t u;
    asm("cvt.rna.tf32.f32 %0, %1;" : "=r"(u) : "f"(f));
    return u;
}

#define CP16(dst, src) \
    asm volatile("cp.async.cg.shared.global [%0], [%1], 16;" :: "r"(dst), "l"(src))

#define MMA_TF32(c, a, b) \
    asm volatile("mma.sync.aligned.m16n8k8.row.col.f32.tf32.tf32.f32 " \
                 "{%0,%1,%2,%3},{%4,%5,%6,%7},{%8,%9},{%0,%1,%2,%3};" \
                 : "+f"((c)[0]), "+f"((c)[1]), "+f"((c)[2]), "+f"((c)[3]) \
                 : "r"((a)[0]), "r"((a)[1]), "r"((a)[2]), "r"((a)[3]), \
                   "r"((b)[0]), "r"((b)[1]))

__global__ __launch_bounds__(256, 2)
void tgemm128(const float* __restrict__ A, const float* __restrict__ Bm,
              const float* __restrict__ bias, float* __restrict__ C,
              int M, int N, int K) {
    extern __shared__ float sm[];
    float* Asm = sm;                 // [2][128][36]
    float* Bsm = sm + 2 * ABUF;      // [2][32][132]

    const int tid  = threadIdx.x;
    const int lane = tid & 31;
    const int warp = tid >> 5;
    const int wm = (warp >> 2) * 64;     // 0 / 64
    const int wn = (warp & 3) * 32;      // 0..96
    const int brow = blockIdx.y * 128;
    const int bcol = blockIdx.x * 128;
    const int lr = lane >> 2;            // 0..7
    const int lc = lane & 3;             // 0..3

    float acc[4][4][4];
    #pragma unroll
    for (int i = 0; i < 4; i++)
        #pragma unroll
        for (int j = 0; j < 4; j++)
            #pragma unroll
            for (int r = 0; r < 4; r++) acc[i][j][r] = 0.f;

    const int KT = K >> 5;   // K / 32

    // --- async tile loader ---
    auto issue = [&](int buf, int k0) {
        float* Ad = Asm + buf * ABUF;
        float* Bd = Bsm + buf * BBUF;
        #pragma unroll
        for (int t = 0; t < 4; t++) {
            int idx = tid + t * 256;          // 0..1023
            int row = idx >> 3, c4 = idx & 7; // A: 128 rows x 8 float4
            uint32_t d = (uint32_t)__cvta_generic_to_shared(Ad + row * ASTRIDE + c4 * 4);
            const float* s = A + (size_t)(brow + row) * K + k0 + c4 * 4;
            CP16(d, s);
        }
        #pragma unroll
        for (int t = 0; t < 4; t++) {
            int idx = tid + t * 256;
            int kr = idx >> 5, c4 = idx & 31;  // B: 32 rows x 32 float4
            uint32_t d = (uint32_t)__cvta_generic_to_shared(Bd + kr * BSTRIDE + c4 * 4);
            const float* s = Bm + (size_t)(k0 + kr) * N + bcol + c4 * 4;
            CP16(d, s);
        }
        asm volatile("cp.async.commit_group;" ::);
    };

    issue(0, 0);
    int buf = 0;
    for (int kt = 0; kt < KT; kt++) {
        asm volatile("cp.async.wait_group 0;" ::);
        __syncthreads();
        if (kt + 1 < KT) issue(buf ^ 1, (kt + 1) << 5);

        const float* Ad = Asm + buf * ABUF;
        const float* Bd = Bsm + buf * BBUF;
        #pragma unroll
        for (int ks = 0; ks < 4; ks++) {
            const int k = ks * 8;
            uint32_t af[4][4], bf[4][2];
            #pragma unroll
            for (int mi = 0; mi < 4; mi++) {
                int r0 = wm + mi * 16 + lr;
                af[mi][0] = f2tf(Ad[r0 * ASTRIDE + k + lc]);
                af[mi][1] = f2tf(Ad[(r0 + 8) * ASTRIDE + k + lc]);
                af[mi][2] = f2tf(Ad[r0 * ASTRIDE + k + 4 + lc]);
                af[mi][3] = f2tf(Ad[(r0 + 8) * ASTRIDE + k + 4 + lc]);
            }
            #pragma unroll
            for (int nj = 0; nj < 4; nj++) {
                int cc = wn + nj * 8 + lr;
                bf[nj][0] = f2tf(Bd[(k + lc) * BSTRIDE + cc]);
                bf[nj][1] = f2tf(Bd[(k + 4 + lc) * BSTRIDE + cc]);
            }
            #pragma unroll
            for (int mi = 0; mi < 4; mi++)
                #pragma unroll
                for (int nj = 0; nj < 4; nj++)
                    MMA_TF32(acc[mi][nj], af[mi], bf[nj]);
        }
        buf ^= 1;
    }

    // epilogue: c0 (r, 2c), c1 (r, 2c+1), c2 (r+8, 2c), c3 (r+8, 2c+1)
    #pragma unroll
    for (int mi = 0; mi < 4; mi++) {
        #pragma unroll
        for (int nj = 0; nj < 4; nj++) {
            int r0 = brow + wm + mi * 16 + lr;
            int c0 = bcol + wn + nj * 8 + lc * 2;
            float b0 = 0.f, b1 = 0.f;
            if (bias) { b0 = bias[c0]; b1 = bias[c0 + 1]; }
            float2 v0 = make_float2(acc[mi][nj][0] + b0, acc[mi][nj][1] + b1);
            float2 v1 = make_float2(acc[mi][nj][2] + b0, acc[mi][nj][3] + b1);
            *(float2*)&C[(size_t)r0 * N + c0] = v0;
            *(float2*)&C[(size_t)(r0 + 8) * N + c0] = v1;
        }
    }
}

// ---------------- depthwise 3x3 conv, SAME padding, NHWC ----------------
__global__ void dwconv3x3(const float* __restrict__ in, const float* __restrict__ w,
                          const float* __restrict__ bias, float* __restrict__ out) {
    int idx = blockIdx.x * 256 + threadIdx.x;
    if (idx >= M_ALL * CH) return;
    int c = idx & 255;
    int t = idx >> 8;
    int xx = t % WW; t /= WW;
    int y  = t % HH;
    int b  = t / HH;
    float acc = bias[c];
    #pragma unroll
    for (int dy = 0; dy < 3; dy++) {
        int iy = y + dy - 1;
        if (iy < 0 || iy >= HH) continue;
        #pragma unroll
        for (int dx = 0; dx < 3; dx++) {
            int ix = xx + dx - 1;
            if (ix < 0 || ix >= WW) continue;
            acc += in[(((size_t)b * NTOK) + iy * WW + ix) * CH + c] * w[(dy * 3 + dx) * CH + c];
        }
    }
    out[idx] = acc;
}

// ---------------- im2col for the 4x4/stride-4 sr conv ----------------
__global__ void im2col_sr(const float* __restrict__ x, float* __restrict__ A) {
    int idx = blockIdx.x * 256 + threadIdx.x;
    if (idx >= M_SR * K_SR) return;
    int k = idx & 4095;
    int m = idx >> 12;
    int ow = m % 14; int t = m / 14;
    int oh = t % 14; int b = t / 14;
    int c = k & 255;
    int khw = k >> 8;
    int kh = khw >> 2, kw = khw & 3;
    int y = oh * 4 + kh, xx = ow * 4 + kw;
    A[idx] = x[(((size_t)b * NTOK) + y * WW + xx) * CH + c];
}

// ---------------- LayerNorm + exact GELU (in-place) ----------------
__global__ void ln_gelu(float* __restrict__ xb, const float* __restrict__ g,
                        const float* __restrict__ bb) {
    int row = blockIdx.x;
    int tid = threadIdx.x;
    float v = xb[(size_t)row * CH + tid];
    __shared__ float s1[256], s2[256];
    s1[tid] = v; s2[tid] = v * v;
    __syncthreads();
    for (int o = 128; o; o >>= 1) {
        if (tid < o) { s1[tid] += s1[tid + o]; s2[tid] += s2[tid + o]; }
        __syncthreads();
    }
    float mu  = s1[0] * (1.f / CH);
    float var = s2[0] * (1.f / CH) - mu * mu;
    float t = (v - mu) * rsqrtf(var + 1e-5f) * g[tid] + bb[tid];
    xb[(size_t)row * CH + tid] = 0.5f * t * (1.f + erff(t * 0.70710678118654752f));
}

// ---------------- branch-1 attention ----------------
#define ATTN1_SMEM 81184
__global__ void attn1_kernel(const float* __restrict__ q1, const float* __restrict__ kv1,
                             float* __restrict__ x1) {
    extern __shared__ float smf[];
    float* qs = smf;                // 32*33
    float* ks = qs + 32 * 33;       // 196*33
    float* vs = ks + 196 * 33;      // 196*33
    float* Ss = vs + 196 * 33;      // 32*197
    int bh = blockIdx.y; int b = bh >> 2; int h = bh & 3;
    int q0 = blockIdx.x * 32;
    int tid = threadIdx.x;

    for (int e = tid; e < 32 * 32; e += 256) {
        int i = e >> 5, dd = e & 31;
        qs[i * 33 + dd] = q1[((size_t)b * NTOK + q0 + i) * 128 + h * 32 + dd];
    }
    for (int e = tid; e < 196 * 32; e += 256) {
        int m = e >> 5, dd = e & 31;
        size_t base = ((size_t)b * N1 + m) * 256 + h * 32 + dd;
        ks[m * 33 + dd] = kv1[base];
        vs[m * 33 + dd] = kv1[base + 128];
    }
    __syncthreads();

    int i  = tid >> 3;
    int dg = tid & 7;
    {
        float qreg[32];
        #pragma unroll
        for (int dd = 0; dd < 32; dd++) qreg[dd] = qs[i * 33 + dd];
        for (int mm = 0; mm < 25; mm++) {
            int m = dg + (mm << 3);
            if (m < 196) {
                float acc = 0.f;
                #pragma unroll
                for (int dd = 0; dd < 32; dd++) acc += qreg[dd] * ks[m * 33 + dd];
                Ss[i * 197 + m] = acc * SCALE;
            }
        }
    }
    __syncthreads();

    int warp = tid >> 5, lane = tid & 31;
    #pragma unroll
    for (int r = 0; r < 4; r++) {
        int row = warp * 4 + r;
        float mx = -1e30f;
        for (int m = lane; m < 196; m += 32) mx = fmaxf(mx, Ss[row * 197 + m]);
        #pragma unroll
        for (int o = 16; o; o >>= 1) mx = fmaxf(mx, __shfl_xor_sync(0xffffffffu, mx, o));
        float sum = 0.f;
        for (int m = lane; m < 196; m += 32) {
            float p = __expf(Ss[row * 197 + m] - mx);
            Ss[row * 197 + m] = p;
            sum += p;
        }
        #pragma unroll
        for (int o = 16; o; o >>= 1) sum += __shfl_xor_sync(0xffffffffu, sum, o);
        float inv = 1.f / sum;
        for (int m = lane; m < 196; m += 32) Ss[row * 197 + m] *= inv;
    }
    __syncthreads();

    float acc[4] = {0.f, 0.f, 0.f, 0.f};
    for (int m = 0; m < 196; m++) {
        float p = Ss[i * 197 + m];
        #pragma unroll
        for (int j = 0; j < 4; j++) acc[j] += p * vs[m * 33 + dg + 8 * j];
    }
    size_t ob = ((size_t)b * NTOK + q0 + i) * 128 + h * 32;
    #pragma unroll
    for (int j = 0; j < 4; j++) x1[ob + dg + 8 * j] = acc[j];
}

// ---------------- branch-2 window attention ----------------
__global__ void attn2_kernel(const float* __restrict__ q2, const float* __restrict__ kv2,
                             float* __restrict__ x2) {
    __shared__ float qs[49 * 33], ks[49 * 33], vs[49 * 33], Ss[49 * 50];
    int bh = blockIdx.y; int b = bh >> 2; int h = bh & 3;
    int win = blockIdx.x; int wr = win >> 3, wc = win & 7;
    int tid = threadIdx.x;

    for (int e = tid; e < 49 * 32; e += 256) {
        int j = e >> 5, dd = e & 31;
        int row = wr * 7 + j / 7, col = wc * 7 + j % 7;
        int n = row * WW + col;
        qs[j * 33 + dd] = q2[((size_t)b * NTOK + n) * 128 + h * 32 + dd];
        size_t kb = ((size_t)b * NTOK + n) * 256 + h * 32 + dd;
        ks[j * 33 + dd] = kv2[kb];
        vs[j * 33 + dd] = kv2[kb + 128];
    }
    __syncthreads();

    for (int e = tid; e < 49 * 49; e += 256) {
        int i = e / 49, m = e % 49;
        float acc = 0.f;
        #pragma unroll
        for (int dd = 0; dd < 32; dd++) acc += qs[i * 33 + dd] * ks[m * 33 + dd];
        Ss[i * 50 + m] = acc * SCALE;
    }
    __syncthreads();

    int warp = tid >> 5, lane = tid & 31;
    for (int row = warp; row < 49; row += 8) {
        float mx = -1e30f;
        for (int m = lane; m < 49; m += 32) mx = fmaxf(mx, Ss[row * 50 + m]);
        #pragma unroll
        for (int o = 16; o; o >>= 1) mx = fmaxf(mx, __shfl_xor_sync(0xffffffffu, mx, o));
        float sum = 0.f;
        for (int m = lane; m < 49; m += 32) {
            float p = __expf(Ss[row * 50 + m] - mx);
            Ss[row * 50 + m] = p;
            sum += p;
        }
        #pragma unroll
        for (int o = 16; o; o >>= 1) sum += __shfl_xor_sync(0xffffffffu, sum, o);
        float inv = 1.f / sum;
        for (int m = lane; m < 49; m += 32) Ss[row * 50 + m] *= inv;
    }
    __syncthreads();

    int dg = tid & 7;
    for (int i = tid >> 3; i < 49; i += 32) {
        float acc[4] = {0.f, 0.f, 0.f, 0.f};
        for (int m = 0; m < 49; m++) {
            float p = Ss[i * 50 + m];
            #pragma unroll
            for (int j = 0; j < 4; j++) acc[j] += p * vs[m * 33 + dg + 8 * j];
        }
        int row = wr * 7 + i / 7, col = wc * 7 + i % 7;
        int n = row * WW + col;
        size_t ob = ((size_t)b * NTOK + n) * 128 + h * 32;
        #pragma unroll
        for (int j = 0; j < 4; j++) x2[ob + dg + 8 * j] = acc[j];
    }
}

// ---------------- concat(x1,x2) + lepe ----------------
__global__ void combine_kernel(const float* __restrict__ x1, const float* __restrict__ x2,
                               const float* __restrict__ lepe, float* __restrict__ pre) {
    int idx = blockIdx.x * 256 + threadIdx.x;
    if (idx >= M_ALL * CH) return;
    int c = idx & 255;
    int m = idx >> 8;
    float v = (c < 128) ? x1[(size_t)m * 128 + c] : x2[(size_t)m * 128 + c - 128];
    pre[idx] = v + lepe[idx];
}

// ---------------- host launch ----------------
extern "C" void kernel_launch(void* const* d_in, const int* in_sizes, int n_in,
                              void* d_out, int out_size) {
    const float* x           = (const float*)d_in[0];
    const float* lepe_lin_w  = (const float*)d_in[1];
    const float* lepe_lin_b  = (const float*)d_in[2];
    const float* lepe_conv_w = (const float*)d_in[3];
    const float* lepe_conv_b = (const float*)d_in[4];
    const float* sr_w        = (const float*)d_in[5];
    const float* sr_b        = (const float*)d_in[6];
    const float* norm_g      = (const float*)d_in[7];
    const float* norm_b      = (const float*)d_in[8];
    const float* q1_w        = (const float*)d_in[9];
    const float* kv1_w       = (const float*)d_in[10];
    const float* q2_w        = (const float*)d_in[11];
    const float* kv2_w       = (const float*)d_in[12];
    const float* proj_w      = (const float*)d_in[13];
    const float* proj_b      = (const float*)d_in[14];
    float* out = (float*)d_out;

    float *lepe_lin, *lepe, *q1, *q2, *kv2, *im2, *x1s, *kv1, *x1, *x2, *pre;
    cudaGetSymbolAddress((void**)&lepe_lin, g_lepe_lin);
    cudaGetSymbolAddress((void**)&lepe,     g_lepe);
    cudaGetSymbolAddress((void**)&q1,       g_q1);
    cudaGetSymbolAddress((void**)&q2,       g_q2);
    cudaGetSymbolAddress((void**)&kv2,      g_kv2);
    cudaGetSymbolAddress((void**)&im2,      g_im2col);
    cudaGetSymbolAddress((void**)&x1s,      g_x1s);
    cudaGetSymbolAddress((void**)&kv1,      g_kv1);
    cudaGetSymbolAddress((void**)&x1,       g_x1);
    cudaGetSymbolAddress((void**)&x2,       g_x2);
    cudaGetSymbolAddress((void**)&pre,      g_pre);

    static bool attr_done = false;
    // setting attributes every call is idempotent and not captured into the graph
    cudaFuncSetAttribute(tgemm128, cudaFuncAttributeMaxDynamicSharedMemorySize, TG_SMEM);
    cudaFuncSetAttribute(attn1_kernel, cudaFuncAttributeMaxDynamicSharedMemorySize, ATTN1_SMEM);
    (void)attr_done;

    const int EW_BLK = 256;
    int n_full = M_ALL * CH;          // 25,690,112
    int n_im   = M_SR * K_SR;         // 25,690,112

    // lepe: linear + depthwise conv
    tgemm128<<<dim3(2, M_ALL / 128), 256, TG_SMEM>>>(x, lepe_lin_w, lepe_lin_b, lepe_lin, M_ALL, 256, 256);
    dwconv3x3<<<(n_full + EW_BLK - 1) / EW_BLK, EW_BLK>>>(lepe_lin, lepe_conv_w, lepe_conv_b, lepe);

    // projections from x
    tgemm128<<<dim3(1, M_ALL / 128), 256, TG_SMEM>>>(x, q1_w,  nullptr, q1,  M_ALL, 128, 256);
    tgemm128<<<dim3(1, M_ALL / 128), 256, TG_SMEM>>>(x, q2_w,  nullptr, q2,  M_ALL, 128, 256);
    tgemm128<<<dim3(2, M_ALL / 128), 256, TG_SMEM>>>(x, kv2_w, nullptr, kv2, M_ALL, 256, 256);

    // sr conv as im2col + GEMM, then LN+GELU, then kv1
    im2col_sr<<<(n_im + EW_BLK - 1) / EW_BLK, EW_BLK>>>(x, im2);
    tgemm128<<<dim3(2, M_SR / 128), 256, TG_SMEM>>>(im2, sr_w, sr_b, x1s, M_SR, 256, K_SR);
    ln_gelu<<<M_SR, 256>>>(x1s, norm_g, norm_b);
    tgemm128<<<dim3(2, M_SR / 128), 256, TG_SMEM>>>(x1s, kv1_w, nullptr, kv1, M_SR, 256, 256);

    // attention branches
    attn1_kernel<<<dim3(NTOK / 32, BATCH * H2), 256, ATTN1_SMEM>>>(q1, kv1, x1);
    attn2_kernel<<<dim3(64, BATCH * H2), 256>>>(q2, kv2, x2);

    // concat + lepe, final projection
    combine_kernel<<<(n_full + EW_BLK - 1) / EW_BLK, EW_BLK>>>(x1, x2, lepe, pre);
    tgemm128<<<dim3(2, M_ALL / 128), 256, TG_SMEM>>>(pre, proj_w, proj_b, out, M_ALL, 256, 256);
}

// round 3
// speedup vs baseline: 2.3603x; 1.3150x over previous
#include <cuda_runtime.h>
#include <cstdint>

#define BATCH 32
#define HH 56
#define WW 56
#define NTOK (HH*WW)            // 3136
#define CH 256
#define H2 4
#define DH 32
#define M_ALL (BATCH*NTOK)      // 100352
#define N1 196
#define M_SR (BATCH*N1)         // 6272
#define K_SR 4096
#define SCALE 0.17677669529663687f

// ---------------- scratch ----------------
__device__ float g_lepe_lin[(size_t)M_ALL*CH];
__device__ float g_lepe    [(size_t)M_ALL*CH];
__device__ float g_q1      [(size_t)M_ALL*128];
__device__ float g_q2      [(size_t)M_ALL*128];
__device__ float g_kv2     [(size_t)M_ALL*CH];
__device__ float g_x1s     [(size_t)M_SR*CH];
__device__ float g_kv1     [(size_t)M_SR*CH];
__device__ float g_x1      [(size_t)M_ALL*128];
__device__ float g_x2      [(size_t)M_ALL*128];

// ---------------- common MMA helpers ----------------
__device__ __forceinline__ uint32_t f2tf(float f) {
    uint32_t u;
    asm("cvt.rna.tf32.f32 %0, %1;" : "=r"(u) : "f"(f));
    return u;
}
#define CP16(dst, src) \
    asm volatile("cp.async.cg.shared.global [%0], [%1], 16;" :: "r"(dst), "l"(src))
#define MMA_TF32(c, a, b) \
    asm volatile("mma.sync.aligned.m16n8k8.row.col.f32.tf32.tf32.f32 " \
                 "{%0,%1,%2,%3},{%4,%5,%6,%7},{%8,%9},{%0,%1,%2,%3};" \
                 : "+f"((c)[0]), "+f"((c)[1]), "+f"((c)[2]), "+f"((c)[3]) \
                 : "r"((a)[0]), "r"((a)[1]), "r"((a)[2]), "r"((a)[3]), \
                   "r"((b)[0]), "r"((b)[1]))

#define ASTRIDE 36
#define BSTRIDE 132
#define ABUF (128*ASTRIDE)
#define BBUF (32*BSTRIDE)
#define TG_SMEM ((2*ABUF + 2*BBUF) * 4)   // 70656 bytes

// ============ generic tf32 GEMM: C[M,N]=A@B (+bias), tiles 128x128xBK32 ============
__global__ __launch_bounds__(256, 2)
void tgemm128(const float* __restrict__ A, const float* __restrict__ Bm,
              const float* __restrict__ bias, float* __restrict__ C,
              int M, int N, int K) {
    extern __shared__ float sm[];
    float* Asm = sm;
    float* Bsm = sm + 2 * ABUF;
    const int tid  = threadIdx.x;
    const int lane = tid & 31;
    const int warp = tid >> 5;
    const int wm = (warp >> 2) * 64;
    const int wn = (warp & 3) * 32;
    const int brow = blockIdx.y * 128;
    const int bcol = blockIdx.x * 128;
    const int lr = lane >> 2;
    const int lc = lane & 3;

    float acc[4][4][4];
    #pragma unroll
    for (int i = 0; i < 4; i++)
        #pragma unroll
        for (int j = 0; j < 4; j++)
            #pragma unroll
            for (int r = 0; r < 4; r++) acc[i][j][r] = 0.f;

    const int KT = K >> 5;
    auto issue = [&](int buf, int k0) {
        float* Ad = Asm + buf * ABUF;
        float* Bd = Bsm + buf * BBUF;
        #pragma unroll
        for (int t = 0; t < 4; t++) {
            int idx = tid + t * 256;
            int row = idx >> 3, c4 = idx & 7;
            uint32_t d = (uint32_t)__cvta_generic_to_shared(Ad + row * ASTRIDE + c4 * 4);
            const float* s = A + (size_t)(brow + row) * K + k0 + c4 * 4;
            CP16(d, s);
        }
        #pragma unroll
        for (int t = 0; t < 4; t++) {
            int idx = tid + t * 256;
            int kr = idx >> 5, c4 = idx & 31;
            uint32_t d = (uint32_t)__cvta_generic_to_shared(Bd + kr * BSTRIDE + c4 * 4);
            const float* s = Bm + (size_t)(k0 + kr) * N + bcol + c4 * 4;
            CP16(d, s);
        }
        asm volatile("cp.async.commit_group;" ::);
    };

    issue(0, 0);
    int buf = 0;
    for (int kt = 0; kt < KT; kt++) {
        asm volatile("cp.async.wait_group 0;" ::);
        __syncthreads();
        if (kt + 1 < KT) issue(buf ^ 1, (kt + 1) << 5);
        const float* Ad = Asm + buf * ABUF;
        const float* Bd = Bsm + buf * BBUF;
        #pragma unroll
        for (int ks = 0; ks < 4; ks++) {
            const int k = ks * 8;
            uint32_t af[4][4], bf[4][2];
            #pragma unroll
            for (int mi = 0; mi < 4; mi++) {
                int r0 = wm + mi * 16 + lr;
                af[mi][0] = f2tf(Ad[r0 * ASTRIDE + k + lc]);
                af[mi][1] = f2tf(Ad[(r0 + 8) * ASTRIDE + k + lc]);
                af[mi][2] = f2tf(Ad[r0 * ASTRIDE + k + 4 + lc]);
                af[mi][3] = f2tf(Ad[(r0 + 8) * ASTRIDE + k + 4 + lc]);
            }
            #pragma unroll
            for (int nj = 0; nj < 4; nj++) {
                int cc = wn + nj * 8 + lr;
                bf[nj][0] = f2tf(Bd[(k + lc) * BSTRIDE + cc]);
                bf[nj][1] = f2tf(Bd[(k + 4 + lc) * BSTRIDE + cc]);
            }
            #pragma unroll
            for (int mi = 0; mi < 4; mi++)
                #pragma unroll
                for (int nj = 0; nj < 4; nj++)
                    MMA_TF32(acc[mi][nj], af[mi], bf[nj]);
        }
        buf ^= 1;
    }
    #pragma unroll
    for (int mi = 0; mi < 4; mi++) {
        #pragma unroll
        for (int nj = 0; nj < 4; nj++) {
            int r0 = brow + wm + mi * 16 + lr;
            int c0 = bcol + wn + nj * 8 + lc * 2;
            float b0 = 0.f, b1 = 0.f;
            if (bias) { b0 = bias[c0]; b1 = bias[c0 + 1]; }
            *(float2*)&C[(size_t)r0 * N + c0] = make_float2(acc[mi][nj][0] + b0, acc[mi][nj][1] + b1);
            *(float2*)&C[(size_t)(r0 + 8) * N + c0] = make_float2(acc[mi][nj][2] + b0, acc[mi][nj][3] + b1);
        }
    }
}

// ============ sr-conv GEMM with fused im2col gather (M=6272, N=256, K=4096) ============
__global__ __launch_bounds__(256, 2)
void tgemm_sr(const float* __restrict__ xin, const float* __restrict__ Bm,
              const float* __restrict__ bias, float* __restrict__ C) {
    const int N = 256, K = 4096;
    extern __shared__ float sm[];
    float* Asm = sm;
    float* Bsm = sm + 2 * ABUF;
    const int tid  = threadIdx.x;
    const int lane = tid & 31;
    const int warp = tid >> 5;
    const int wm = (warp >> 2) * 64;
    const int wn = (warp & 3) * 32;
    const int brow = blockIdx.y * 128;
    const int bcol = blockIdx.x * 128;
    const int lr = lane >> 2;
    const int lc = lane & 3;
    const int c4 = tid & 7;

    // per-thread patch base pointers for the 4 A rows it loads
    const float* px[4];
    #pragma unroll
    for (int t = 0; t < 4; t++) {
        int m = brow + (tid >> 3) + t * 32;
        int b = m / 196, rem = m % 196;
        int oh = rem / 14, ow = rem % 14;
        px[t] = xin + ((size_t)((b * 56 + oh * 4) * 56 + ow * 4)) * 256;
    }

    float acc[4][4][4];
    #pragma unroll
    for (int i = 0; i < 4; i++)
        #pragma unroll
        for (int j = 0; j < 4; j++)
            #pragma unroll
            for (int r = 0; r < 4; r++) acc[i][j][r] = 0.f;

    const int KT = K >> 5;   // 128
    auto issue = [&](int buf, int k0) {
        float* Ad = Asm + buf * ABUF;
        float* Bd = Bsm + buf * BBUF;
        int kk = k0 + c4 * 4;
        int kh = kk >> 10, kw = (kk >> 8) & 3, c = kk & 255;
        int off = (kh * 56 + kw) * 256 + c;
        #pragma unroll
        for (int t = 0; t < 4; t++) {
            int row = (tid >> 3) + t * 32;
            uint32_t d = (uint32_t)__cvta_generic_to_shared(Ad + row * ASTRIDE + c4 * 4);
            CP16(d, px[t] + off);
        }
        #pragma unroll
        for (int t = 0; t < 4; t++) {
            int idx = tid + t * 256;
            int kr = idx >> 5, cc4 = idx & 31;
            uint32_t d = (uint32_t)__cvta_generic_to_shared(Bd + kr * BSTRIDE + cc4 * 4);
            const float* s = Bm + (size_t)(k0 + kr) * N + bcol + cc4 * 4;
            CP16(d, s);
        }
        asm volatile("cp.async.commit_group;" ::);
    };

    issue(0, 0);
    int buf = 0;
    for (int kt = 0; kt < KT; kt++) {
        asm volatile("cp.async.wait_group 0;" ::);
        __syncthreads();
        if (kt + 1 < KT) issue(buf ^ 1, (kt + 1) << 5);
        const float* Ad = Asm + buf * ABUF;
        const float* Bd = Bsm + buf * BBUF;
        #pragma unroll
        for (int ks = 0; ks < 4; ks++) {
            const int k = ks * 8;
            uint32_t af[4][4], bf[4][2];
            #pragma unroll
            for (int mi = 0; mi < 4; mi++) {
                int r0 = wm + mi * 16 + lr;
                af[mi][0] = f2tf(Ad[r0 * ASTRIDE + k + lc]);
                af[mi][1] = f2tf(Ad[(r0 + 8) * ASTRIDE + k + lc]);
                af[mi][2] = f2tf(Ad[r0 * ASTRIDE + k + 4 + lc]);
                af[mi][3] = f2tf(Ad[(r0 + 8) * ASTRIDE + k + 4 + lc]);
            }
            #pragma unroll
            for (int nj = 0; nj < 4; nj++) {
                int cc = wn + nj * 8 + lr;
                bf[nj][0] = f2tf(Bd[(k + lc) * BSTRIDE + cc]);
                bf[nj][1] = f2tf(Bd[(k + 4 + lc) * BSTRIDE + cc]);
            }
            #pragma unroll
            for (int mi = 0; mi < 4; mi++)
                #pragma unroll
                for (int nj = 0; nj < 4; nj++)
                    MMA_TF32(acc[mi][nj], af[mi], bf[nj]);
        }
        buf ^= 1;
    }
    #pragma unroll
    for (int mi = 0; mi < 4; mi++) {
        #pragma unroll
        for (int nj = 0; nj < 4; nj++) {
            int r0 = brow + wm + mi * 16 + lr;
            int c0 = bcol + wn + nj * 8 + lc * 2;
            float b0 = bias[c0], b1 = bias[c0 + 1];
            *(float2*)&C[(size_t)r0 * N + c0] = make_float2(acc[mi][nj][0] + b0, acc[mi][nj][1] + b1);
            *(float2*)&C[(size_t)(r0 + 8) * N + c0] = make_float2(acc[mi][nj][2] + b0, acc[mi][nj][3] + b1);
        }
    }
}

// ============ proj GEMM with fused concat(x1,x2)+lepe A (M=M_ALL, N=K=256) ============
__global__ __launch_bounds__(256, 2)
void tgemm_proj(const float* __restrict__ x1, const float* __restrict__ x2,
                const float* __restrict__ lepe, const float* __restrict__ Bm,
                const float* __restrict__ bias, float* __restrict__ C) {
    const int N = 256, K = 256;
    extern __shared__ float sm[];
    float* Asm = sm;
    float* Bsm = sm + 2 * ABUF;
    const int tid  = threadIdx.x;
    const int lane = tid & 31;
    const int warp = tid >> 5;
    const int wm = (warp >> 2) * 64;
    const int wn = (warp & 3) * 32;
    const int brow = blockIdx.y * 128;
    const int bcol = blockIdx.x * 128;
    const int lr = lane >> 2;
    const int lc = lane & 3;
    const int c4 = tid & 7;

    float acc[4][4][4];
    #pragma unroll
    for (int i = 0; i < 4; i++)
        #pragma unroll
        for (int j = 0; j < 4; j++)
            #pragma unroll
            for (int r = 0; r < 4; r++) acc[i][j][r] = 0.f;

    auto issueB = [&](int buf, int k0) {
        float* Bd = Bsm + buf * BBUF;
        #pragma unroll
        for (int t = 0; t < 4; t++) {
            int idx = tid + t * 256;
            int kr = idx >> 5, cc4 = idx & 31;
            uint32_t d = (uint32_t)__cvta_generic_to_shared(Bd + kr * BSTRIDE + cc4 * 4);
            const float* s = Bm + (size_t)(k0 + kr) * N + bcol + cc4 * 4;
            CP16(d, s);
        }
        asm volatile("cp.async.commit_group;" ::);
    };
    float4 ra[4];
    auto loadA = [&](int k0) {
        int kk = k0 + c4 * 4;
        #pragma unroll
        for (int t = 0; t < 4; t++) {
            size_t m = (size_t)(brow + (tid >> 3) + t * 32);
            float4 a;
            if (kk < 128) a = *(const float4*)&x1[m * 128 + kk];
            else          a = *(const float4*)&x2[m * 128 + kk - 128];
            float4 l = *(const float4*)&lepe[m * 256 + kk];
            a.x += l.x; a.y += l.y; a.z += l.z; a.w += l.w;
            ra[t] = a;
        }
    };
    auto storeA = [&](int buf) {
        float* Ad = Asm + buf * ABUF;
        #pragma unroll
        for (int t = 0; t < 4; t++)
            *(float4*)&Ad[((tid >> 3) + t * 32) * ASTRIDE + c4 * 4] = ra[t];
    };

    issueB(0, 0);
    loadA(0);
    int buf = 0;
    const int KT = K >> 5;   // 8
    for (int kt = 0; kt < KT; kt++) {
        storeA(buf);
        asm volatile("cp.async.wait_group 0;" ::);
        __syncthreads();
        if (kt + 1 < KT) { issueB(buf ^ 1, (kt + 1) << 5); loadA((kt + 1) << 5); }
        const float* Ad = Asm + buf * ABUF;
        const float* Bd = Bsm + buf * BBUF;
        #pragma unroll
        for (int ks = 0; ks < 4; ks++) {
            const int k = ks * 8;
            uint32_t af[4][4], bf[4][2];
            #pragma unroll
            for (int mi = 0; mi < 4; mi++) {
                int r0 = wm + mi * 16 + lr;
                af[mi][0] = f2tf(Ad[r0 * ASTRIDE + k + lc]);
                af[mi][1] = f2tf(Ad[(r0 + 8) * ASTRIDE + k + lc]);
                af[mi][2] = f2tf(Ad[r0 * ASTRIDE + k + 4 + lc]);
                af[mi][3] = f2tf(Ad[(r0 + 8) * ASTRIDE + k + 4 + lc]);
            }
            #pragma unroll
            for (int nj = 0; nj < 4; nj++) {
                int cc = wn + nj * 8 + lr;
                bf[nj][0] = f2tf(Bd[(k + lc) * BSTRIDE + cc]);
                bf[nj][1] = f2tf(Bd[(k + 4 + lc) * BSTRIDE + cc]);
            }
            #pragma unroll
            for (int mi = 0; mi < 4; mi++)
                #pragma unroll
                for (int nj = 0; nj < 4; nj++)
                    MMA_TF32(acc[mi][nj], af[mi], bf[nj]);
        }
        buf ^= 1;
        __syncthreads();   // protect Asm[buf] reuse before next storeA
    }
    #pragma unroll
    for (int mi = 0; mi < 4; mi++) {
        #pragma unroll
        for (int nj = 0; nj < 4; nj++) {
            int r0 = brow + wm + mi * 16 + lr;
            int c0 = bcol + wn + nj * 8 + lc * 2;
            float b0 = bias[c0], b1 = bias[c0 + 1];
            *(float2*)&C[(size_t)r0 * N + c0] = make_float2(acc[mi][nj][0] + b0, acc[mi][nj][1] + b1);
            *(float2*)&C[(size_t)(r0 + 8) * N + c0] = make_float2(acc[mi][nj][2] + b0, acc[mi][nj][3] + b1);
        }
    }
}

// ============ depthwise 3x3, register y-walk ============
__global__ void dwconv3x3(const float* __restrict__ in, const float* __restrict__ w,
                          const float* __restrict__ bias, float* __restrict__ out) {
    int idx = blockIdx.x * 256 + threadIdx.x;   // (b, xx, c)
    int c = idx & 255;
    int t = idx >> 8;
    int xx = t % WW, b = t / WW;
    float wt[9];
    #pragma unroll
    for (int i = 0; i < 9; i++) wt[i] = w[i * 256 + c];
    float bz = bias[c];
    const float* base = in + (size_t)b * NTOK * 256 + c;
    float* ob = out + (size_t)b * NTOK * 256 + c;
    bool xl = xx > 0, xr = xx < WW - 1;

    float rA[3] = {0.f, 0.f, 0.f}, rB[3], rC[3];
    {
        const float* rp = base;
        rB[0] = xl ? rp[(xx - 1) * 256] : 0.f;
        rB[1] = rp[xx * 256];
        rB[2] = xr ? rp[(xx + 1) * 256] : 0.f;
    }
    for (int y = 0; y < HH; y++) {
        if (y + 1 < HH) {
            const float* rp = base + (size_t)(y + 1) * WW * 256;
            rC[0] = xl ? rp[(xx - 1) * 256] : 0.f;
            rC[1] = rp[xx * 256];
            rC[2] = xr ? rp[(xx + 1) * 256] : 0.f;
        } else { rC[0] = rC[1] = rC[2] = 0.f; }
        float acc = bz
            + wt[0] * rA[0] + wt[1] * rA[1] + wt[2] * rA[2]
            + wt[3] * rB[0] + wt[4] * rB[1] + wt[5] * rB[2]
            + wt[6] * rC[0] + wt[7] * rC[1] + wt[8] * rC[2];
        ob[(size_t)(y * WW + xx) * 256] = acc;
        rA[0] = rB[0]; rA[1] = rB[1]; rA[2] = rB[2];
        rB[0] = rC[0]; rB[1] = rC[1]; rB[2] = rC[2];
    }
}

// ============ LayerNorm + exact GELU ============
__global__ void ln_gelu(float* __restrict__ xb, const float* __restrict__ g,
                        const float* __restrict__ bb) {
    int row = blockIdx.x;
    int tid = threadIdx.x;
    float v = xb[(size_t)row * CH + tid];
    __shared__ float s1[256], s2[256];
    s1[tid] = v; s2[tid] = v * v;
    __syncthreads();
    for (int o = 128; o; o >>= 1) {
        if (tid < o) { s1[tid] += s1[tid + o]; s2[tid] += s2[tid + o]; }
        __syncthreads();
    }
    float mu  = s1[0] * (1.f / CH);
    float var = s2[0] * (1.f / CH) - mu * mu;
    float tt = (v - mu) * rsqrtf(var + 1e-5f) * g[tid] + bb[tid];
    xb[(size_t)row * CH + tid] = 0.5f * tt * (1.f + erff(tt * 0.70710678118654752f));
}

// ============ branch-1 attention, tensor-core version ============
// CTA: 64 q-rows vs all 196 kv, per (b,h). grid (49, 128), 256 threads.
// smem: Qs[64][36], Ks[32][228] (K^T, cols 196..227 zero), Vs[200][36] (rows 196..199 zero), Ss[64][228]
#define A1_SMEM ((64*36 + 32*228 + 200*36 + 64*228)*4)
__global__ __launch_bounds__(256, 1)
void attn1_mma(const float* __restrict__ q1, const float* __restrict__ kv1,
               float* __restrict__ x1) {
    extern __shared__ float sm[];
    float* Qs = sm;                  // 64*36
    float* Ks = Qs + 64 * 36;        // 32*228
    float* Vs = Ks + 32 * 228;       // 200*36
    float* Ss = Vs + 200 * 36;       // 64*228
    int bh = blockIdx.y, b = bh >> 2, h = bh & 3;
    int q0 = blockIdx.x * 64;
    int tid = threadIdx.x, lane = tid & 31, warp = tid >> 5;
    int lr = lane >> 2, lc = lane & 3;

    for (int e = tid; e < 64 * 8; e += 256) {
        int r = e >> 3, c4 = e & 7;
        float4 v = *(const float4*)&q1[((size_t)b * NTOK + q0 + r) * 128 + h * 32 + c4 * 4];
        *(float4*)&Qs[r * 36 + c4 * 4] = v;
    }
    for (int e = tid; e < 196 * 32; e += 256) {
        int m = e >> 5, dd = e & 31;
        size_t base = ((size_t)b * N1 + m) * 256 + h * 32 + dd;
        Ks[dd * 228 + m] = kv1[base];
        Vs[m * 36 + dd]  = kv1[base + 128];
    }
    for (int e = tid; e < 32 * 32; e += 256) {
        int k = e >> 5, c = e & 31;
        Ks[k * 228 + 196 + c] = 0.f;
    }
    if (tid < 128) {
        int m = 196 + (tid >> 5), dd = tid & 31;
        Vs[m * 36 + dd] = 0.f;
    }
    __syncthreads();

    // ---- scores: S[64, 224] = Q @ K^T, warp grid 2(m) x 4(n), warp tile 32x56 ----
    {
        int wm = (warp >> 2) * 32, wn = (warp & 3) * 56;
        float acc[2][7][4];
        #pragma unroll
        for (int i = 0; i < 2; i++)
            #pragma unroll
            for (int j = 0; j < 7; j++)
                #pragma unroll
                for (int r = 0; r < 4; r++) acc[i][j][r] = 0.f;
        #pragma unroll
        for (int ks = 0; ks < 4; ks++) {
            const int k = ks * 8;
            uint32_t af[2][4], bf[7][2];
            #pragma unroll
            for (int mi = 0; mi < 2; mi++) {
                int r0 = wm + mi * 16 + lr;
                af[mi][0] = f2tf(Qs[r0 * 36 + k + lc]);
                af[mi][1] = f2tf(Qs[(r0 + 8) * 36 + k + lc]);
                af[mi][2] = f2tf(Qs[r0 * 36 + k + 4 + lc]);
                af[mi][3] = f2tf(Qs[(r0 + 8) * 36 + k + 4 + lc]);
            }
            #pragma unroll
            for (int nj = 0; nj < 7; nj++) {
                int cc = wn + nj * 8 + lr;
                bf[nj][0] = f2tf(Ks[(k + lc) * 228 + cc]);
                bf[nj][1] = f2tf(Ks[(k + 4 + lc) * 228 + cc]);
            }
            #pragma unroll
            for (int mi = 0; mi < 2; mi++)
                #pragma unroll
                for (int nj = 0; nj < 7; nj++)
                    MMA_TF32(acc[mi][nj], af[mi], bf[nj]);
        }
        #pragma unroll
        for (int mi = 0; mi < 2; mi++)
            #pragma unroll
            for (int nj = 0; nj < 7; nj++) {
                int r0 = wm + mi * 16 + lr;
                int c0 = wn + nj * 8 + lc * 2;
                Ss[r0 * 228 + c0]           = acc[mi][nj][0] * SCALE;
                Ss[r0 * 228 + c0 + 1]       = acc[mi][nj][1] * SCALE;
                Ss[(r0 + 8) * 228 + c0]     = acc[mi][nj][2] * SCALE;
                Ss[(r0 + 8) * 228 + c0 + 1] = acc[mi][nj][3] * SCALE;
            }
    }
    __syncthreads();

    // ---- softmax over cols 0..195 (cols 196..199 stay exactly 0 -> P=0) ----
    #pragma unroll
    for (int r = 0; r < 8; r++) {
        int row = warp * 8 + r;
        float mx = -1e30f;
        for (int m = lane; m < 196; m += 32) mx = fmaxf(mx, Ss[row * 228 + m]);
        #pragma unroll
        for (int o = 16; o; o >>= 1) mx = fmaxf(mx, __shfl_xor_sync(0xffffffffu, mx, o));
        float sum = 0.f;
        for (int m = lane; m < 196; m += 32) {
            float p = __expf(Ss[row * 228 + m] - mx);
            Ss[row * 228 + m] = p;
            sum += p;
        }
        #pragma unroll
        for (int o = 16; o; o >>= 1) sum += __shfl_xor_sync(0xffffffffu, sum, o);
        float inv = 1.f / sum;
        for (int m = lane; m < 196; m += 32) Ss[row * 228 + m] *= inv;
    }
    __syncthreads();

    // ---- out = P[64,200] @ V[200,32], warp grid 4(m) x 2(n), warp tile 16x16 ----
    {
        int wm = (warp >> 1) * 16, wn = (warp & 1) * 16;
        float acc[2][4];
        #pragma unroll
        for (int j = 0; j < 2; j++)
            #pragma unroll
            for (int r = 0; r < 4; r++) acc[j][r] = 0.f;
        #pragma unroll 5
        for (int ks = 0; ks < 25; ks++) {
            const int k = ks * 8;
            uint32_t af[4], bf[2][2];
            af[0] = f2tf(Ss[(wm + lr) * 228 + k + lc]);
            af[1] = f2tf(Ss[(wm + 8 + lr) * 228 + k + lc]);
            af[2] = f2tf(Ss[(wm + lr) * 228 + k + 4 + lc]);
            af[3] = f2tf(Ss[(wm + 8 + lr) * 228 + k + 4 + lc]);
            #pragma unroll
            for (int nj = 0; nj < 2; nj++) {
                int cc = wn + nj * 8 + lr;
                bf[nj][0] = f2tf(Vs[(k + lc) * 36 + cc]);
                bf[nj][1] = f2tf(Vs[(k + 4 + lc) * 36 + cc]);
            }
            MMA_TF32(acc[0], af, bf[0]);
            MMA_TF32(acc[1], af, bf[1]);
        }
        #pragma unroll
        for (int nj = 0; nj < 2; nj++) {
            int r0 = q0 + wm + lr;
            int c0 = wn + nj * 8 + lc * 2;
            *(float2*)&x1[((size_t)b * NTOK + r0) * 128 + h * 32 + c0] =
                make_float2(acc[nj][0], acc[nj][1]);
            *(float2*)&x1[((size_t)b * NTOK + r0 + 8) * 128 + h * 32 + c0] =
                make_float2(acc[nj][2], acc[nj][3]);
        }
    }
}

// ============ branch-2 window attention (unchanged) ============
__global__ void attn2_kernel(const float* __restrict__ q2, const float* __restrict__ kv2,
                             float* __restrict__ x2) {
    __shared__ float qs[49 * 33], ks[49 * 33], vs[49 * 33], Ss[49 * 50];
    int bh = blockIdx.y; int b = bh >> 2; int h = bh & 3;
    int win = blockIdx.x; int wr = win >> 3, wc = win & 7;
    int tid = threadIdx.x;

    for (int e = tid; e < 49 * 32; e += 256) {
        int j = e >> 5, dd = e & 31;
        int row = wr * 7 + j / 7, col = wc * 7 + j % 7;
        int n = row * WW + col;
        qs[j * 33 + dd] = q2[((size_t)b * NTOK + n) * 128 + h * 32 + dd];
        size_t kb = ((size_t)b * NTOK + n) * 256 + h * 32 + dd;
        ks[j * 33 + dd] = kv2[kb];
        vs[j * 33 + dd] = kv2[kb + 128];
    }
    __syncthreads();

    for (int e = tid; e < 49 * 49; e += 256) {
        int i = e / 49, m = e % 49;
        float acc = 0.f;
        #pragma unroll
        for (int dd = 0; dd < 32; dd++) acc += qs[i * 33 + dd] * ks[m * 33 + dd];
        Ss[i * 50 + m] = acc * SCALE;
    }
    __syncthreads();

    int warp = tid >> 5, lane = tid & 31;
    for (int row = warp; row < 49; row += 8) {
        float mx = -1e30f;
        for (int m = lane; m < 49; m += 32) mx = fmaxf(mx, Ss[row * 50 + m]);
        #pragma unroll
        for (int o = 16; o; o >>= 1) mx = fmaxf(mx, __shfl_xor_sync(0xffffffffu, mx, o));
        float sum = 0.f;
        for (int m = lane; m < 49; m += 32) {
            float p = __expf(Ss[row * 50 + m] - mx);
            Ss[row * 50 + m] = p;
            sum += p;
        }
        #pragma unroll
        for (int o = 16; o; o >>= 1) sum += __shfl_xor_sync(0xffffffffu, sum, o);
        float inv = 1.f / sum;
        for (int m = lane; m < 49; m += 32) Ss[row * 50 + m] *= inv;
    }
    __syncthreads();

    int dg = tid & 7;
    for (int i = tid >> 3; i < 49; i += 32) {
        float acc[4] = {0.f, 0.f, 0.f, 0.f};
        for (int m = 0; m < 49; m++) {
            float p = Ss[i * 50 + m];
            #pragma unroll
            for (int j = 0; j < 4; j++) acc[j] += p * vs[m * 33 + dg + 8 * j];
        }
        int row = wr * 7 + i / 7, col = wc * 7 + i % 7;
        int n = row * WW + col;
        size_t ob = ((size_t)b * NTOK + n) * 128 + h * 32;
        #pragma unroll
        for (int j = 0; j < 4; j++) x2[ob + dg + 8 * j] = acc[j];
    }
}

// ---------------- host launch ----------------
extern "C" void kernel_launch(void* const* d_in, const int* in_sizes, int n_in,
                              void* d_out, int out_size) {
    const float* x           = (const float*)d_in[0];
    const float* lepe_lin_w  = (const float*)d_in[1];
    const float* lepe_lin_b  = (const float*)d_in[2];
    const float* lepe_conv_w = (const float*)d_in[3];
    const float* lepe_conv_b = (const float*)d_in[4];
    const float* sr_w        = (const float*)d_in[5];
    const float* sr_b        = (const float*)d_in[6];
    const float* norm_g      = (const float*)d_in[7];
    const float* norm_b      = (const float*)d_in[8];
    const float* q1_w        = (const float*)d_in[9];
    const float* kv1_w       = (const float*)d_in[10];
    const float* q2_w        = (const float*)d_in[11];
    const float* kv2_w       = (const float*)d_in[12];
    const float* proj_w      = (const float*)d_in[13];
    const float* proj_b      = (const float*)d_in[14];
    float* out = (float*)d_out;

    float *lepe_lin, *lepe, *q1, *q2, *kv2, *x1s, *kv1, *x1, *x2;
    cudaGetSymbolAddress((void**)&lepe_lin, g_lepe_lin);
    cudaGetSymbolAddress((void**)&lepe,     g_lepe);
    cudaGetSymbolAddress((void**)&q1,       g_q1);
    cudaGetSymbolAddress((void**)&q2,       g_q2);
    cudaGetSymbolAddress((void**)&kv2,      g_kv2);
    cudaGetSymbolAddress((void**)&x1s,      g_x1s);
    cudaGetSymbolAddress((void**)&kv1,      g_kv1);
    cudaGetSymbolAddress((void**)&x1,       g_x1);
    cudaGetSymbolAddress((void**)&x2,       g_x2);

    cudaFuncSetAttribute(tgemm128,   cudaFuncAttributeMaxDynamicSharedMemorySize, TG_SMEM);
    cudaFuncSetAttribute(tgemm_sr,   cudaFuncAttributeMaxDynamicSharedMemorySize, TG_SMEM);
    cudaFuncSetAttribute(tgemm_proj, cudaFuncAttributeMaxDynamicSharedMemorySize, TG_SMEM);
    cudaFuncSetAttribute(attn1_mma,  cudaFuncAttributeMaxDynamicSharedMemorySize, A1_SMEM);

    // lepe: linear + depthwise conv
    tgemm128<<<dim3(2, M_ALL / 128), 256, TG_SMEM>>>(x, lepe_lin_w, lepe_lin_b, lepe_lin, M_ALL, 256, 256);
    dwconv3x3<<<(BATCH * WW * CH) / 256, 256>>>(lepe_lin, lepe_conv_w, lepe_conv_b, lepe);

    // projections from x
    tgemm128<<<dim3(1, M_ALL / 128), 256, TG_SMEM>>>(x, q1_w,  nullptr, q1,  M_ALL, 128, 256);
    tgemm128<<<dim3(1, M_ALL / 128), 256, TG_SMEM>>>(x, q2_w,  nullptr, q2,  M_ALL, 128, 256);
    tgemm128<<<dim3(2, M_ALL / 128), 256, TG_SMEM>>>(x, kv2_w, nullptr, kv2, M_ALL, 256, 256);

    // sr conv (fused im2col) -> LN+GELU -> kv1
    tgemm_sr<<<dim3(2, M_SR / 128), 256, TG_SMEM>>>(x, sr_w, sr_b, x1s);
    ln_gelu<<<M_SR, 256>>>(x1s, norm_g, norm_b);
    tgemm128<<<dim3(2, M_SR / 128), 256, TG_SMEM>>>(x1s, kv1_w, nullptr, kv1, M_SR, 256, 256);

    // attention branches
    attn1_mma<<<dim3(NTOK / 64, BATCH * H2), 256, A1_SMEM>>>(q1, kv1, x1);
    attn2_kernel<<<dim3(64, BATCH * H2), 256>>>(q2, kv2, x2);

    // fused concat+lepe + final projection
    tgemm_proj<<<dim3(2, M_ALL / 128), 256, TG_SMEM>>>(x1, x2, lepe, proj_w, proj_b, out);
}

// round 4
// speedup vs baseline: 3.2735x; 1.3869x over previous
#include <cuda_runtime.h>
#include <cstdint>

#define BATCH 32
#define HH 56
#define WW 56
#define NTOK (HH*WW)            // 3136
#define CH 256
#define H2 4
#define M_ALL (BATCH*NTOK)      // 100352
#define N1 196
#define M_SR (BATCH*N1)         // 6272
#define SCALE 0.17677669529663687f

// ---------------- scratch ----------------
__device__ float g_pack  [(size_t)M_ALL*768];   // [lepe_lin | q1 | q2 | kv2]
__device__ float g_lepe  [(size_t)M_ALL*CH];
__device__ float g_wpack [(size_t)256*768];
__device__ float g_bpack [768];
__device__ float g_srp   [(size_t)4*M_SR*CH];   // split-K partials
__device__ float g_x1s   [(size_t)M_SR*CH];
__device__ float g_kv1   [(size_t)M_SR*CH];
__device__ float g_x1    [(size_t)M_ALL*128];
__device__ float g_x2    [(size_t)M_ALL*128];

// ---------------- common MMA helpers ----------------
__device__ __forceinline__ uint32_t f2tf(float f) {
    uint32_t u;
    asm("cvt.rna.tf32.f32 %0, %1;" : "=r"(u) : "f"(f));
    return u;
}
#define CP16(dst, src) \
    asm volatile("cp.async.cg.shared.global [%0], [%1], 16;" :: "r"(dst), "l"(src))
#define MMA_TF32(c, a, b) \
    asm volatile("mma.sync.aligned.m16n8k8.row.col.f32.tf32.tf32.f32 " \
                 "{%0,%1,%2,%3},{%4,%5,%6,%7},{%8,%9},{%0,%1,%2,%3};" \
                 : "+f"((c)[0]), "+f"((c)[1]), "+f"((c)[2]), "+f"((c)[3]) \
                 : "r"((a)[0]), "r"((a)[1]), "r"((a)[2]), "r"((a)[3]), \
                   "r"((b)[0]), "r"((b)[1]))

#define ASTRIDE 36
#define BSTRIDE 132
#define ABUF (128*ASTRIDE)
#define BBUF (32*BSTRIDE)
#define TG_SMEM ((2*ABUF + 2*BBUF) * 4)   // 70656 bytes

// ============ weight/bias packing for the merged projection GEMM ============
__global__ void pack_weights(const float* __restrict__ lw, const float* __restrict__ lb,
                             const float* __restrict__ q1w, const float* __restrict__ q2w,
                             const float* __restrict__ kvw,
                             float* __restrict__ wp, float* __restrict__ bp) {
    int idx = blockIdx.x * 256 + threadIdx.x;
    if (idx < 768) bp[idx] = (idx < 256) ? lb[idx] : 0.f;
    if (idx >= 256 * 768) return;
    int k = idx / 768, c = idx % 768;
    float v;
    if (c < 256)      v = lw[k * 256 + c];
    else if (c < 384) v = q1w[k * 128 + (c - 256)];
    else if (c < 512) v = q2w[k * 128 + (c - 384)];
    else              v = kvw[k * 256 + (c - 512)];
    wp[idx] = v;
}

// ============ generic tf32 GEMM: C[M,N]=A@B (+bias) ============
__global__ __launch_bounds__(256, 2)
void tgemm128(const float* __restrict__ A, const float* __restrict__ Bm,
              const float* __restrict__ bias, float* __restrict__ C,
              int M, int N, int K) {
    extern __shared__ float sm[];
    float* Asm = sm;
    float* Bsm = sm + 2 * ABUF;
    const int tid  = threadIdx.x;
    const int lane = tid & 31;
    const int warp = tid >> 5;
    const int wm = (warp >> 2) * 64;
    const int wn = (warp & 3) * 32;
    const int brow = blockIdx.y * 128;
    const int bcol = blockIdx.x * 128;
    const int lr = lane >> 2;
    const int lc = lane & 3;

    float acc[4][4][4];
    #pragma unroll
    for (int i = 0; i < 4; i++)
        #pragma unroll
        for (int j = 0; j < 4; j++)
            #pragma unroll
            for (int r = 0; r < 4; r++) acc[i][j][r] = 0.f;

    const int KT = K >> 5;
    auto issue = [&](int buf, int k0) {
        float* Ad = Asm + buf * ABUF;
        float* Bd = Bsm + buf * BBUF;
        #pragma unroll
        for (int t = 0; t < 4; t++) {
            int idx = tid + t * 256;
            int row = idx >> 3, c4 = idx & 7;
            uint32_t d = (uint32_t)__cvta_generic_to_shared(Ad + row * ASTRIDE + c4 * 4);
            CP16(d, A + (size_t)(brow + row) * K + k0 + c4 * 4);
        }
        #pragma unroll
        for (int t = 0; t < 4; t++) {
            int idx = tid + t * 256;
            int kr = idx >> 5, c4 = idx & 31;
            uint32_t d = (uint32_t)__cvta_generic_to_shared(Bd + kr * BSTRIDE + c4 * 4);
            CP16(d, Bm + (size_t)(k0 + kr) * N + bcol + c4 * 4);
        }
        asm volatile("cp.async.commit_group;" ::);
    };

    issue(0, 0);
    int buf = 0;
    for (int kt = 0; kt < KT; kt++) {
        asm volatile("cp.async.wait_group 0;" ::);
        __syncthreads();
        if (kt + 1 < KT) issue(buf ^ 1, (kt + 1) << 5);
        const float* Ad = Asm + buf * ABUF;
        const float* Bd = Bsm + buf * BBUF;
        #pragma unroll
        for (int ks = 0; ks < 4; ks++) {
            const int k = ks * 8;
            uint32_t af[4][4], bf[4][2];
            #pragma unroll
            for (int mi = 0; mi < 4; mi++) {
                int r0 = wm + mi * 16 + lr;
                af[mi][0] = f2tf(Ad[r0 * ASTRIDE + k + lc]);
                af[mi][1] = f2tf(Ad[(r0 + 8) * ASTRIDE + k + lc]);
                af[mi][2] = f2tf(Ad[r0 * ASTRIDE + k + 4 + lc]);
                af[mi][3] = f2tf(Ad[(r0 + 8) * ASTRIDE + k + 4 + lc]);
            }
            #pragma unroll
            for (int nj = 0; nj < 4; nj++) {
                int cc = wn + nj * 8 + lr;
                bf[nj][0] = f2tf(Bd[(k + lc) * BSTRIDE + cc]);
                bf[nj][1] = f2tf(Bd[(k + 4 + lc) * BSTRIDE + cc]);
            }
            #pragma unroll
            for (int mi = 0; mi < 4; mi++)
                #pragma unroll
                for (int nj = 0; nj < 4; nj++)
                    MMA_TF32(acc[mi][nj], af[mi], bf[nj]);
        }
        buf ^= 1;
    }
    #pragma unroll
    for (int mi = 0; mi < 4; mi++) {
        #pragma unroll
        for (int nj = 0; nj < 4; nj++) {
            int r0 = brow + wm + mi * 16 + lr;
            int c0 = bcol + wn + nj * 8 + lc * 2;
            float b0 = 0.f, b1 = 0.f;
            if (bias) { b0 = bias[c0]; b1 = bias[c0 + 1]; }
            *(float2*)&C[(size_t)r0 * N + c0] = make_float2(acc[mi][nj][0] + b0, acc[mi][nj][1] + b1);
            *(float2*)&C[(size_t)(r0 + 8) * N + c0] = make_float2(acc[mi][nj][2] + b0, acc[mi][nj][3] + b1);
        }
    }
}

// ============ sr-conv GEMM, fused im2col, split-K x4 ============
__global__ __launch_bounds__(256, 2)
void tgemm_sr_split(const float* __restrict__ xin, const float* __restrict__ Bm,
                    float* __restrict__ Cp) {
    const int N = 256;
    const int kc = blockIdx.z;                 // 0..3, K chunk of 1024
    float* C = Cp + (size_t)kc * M_SR * 256;
    extern __shared__ float sm[];
    float* Asm = sm;
    float* Bsm = sm + 2 * ABUF;
    const int tid  = threadIdx.x;
    const int lane = tid & 31;
    const int warp = tid >> 5;
    const int wm = (warp >> 2) * 64;
    const int wn = (warp & 3) * 32;
    const int brow = blockIdx.y * 128;
    const int bcol = blockIdx.x * 128;
    const int lr = lane >> 2;
    const int lc = lane & 3;
    const int c4 = tid & 7;

    const float* px[4];
    #pragma unroll
    for (int t = 0; t < 4; t++) {
        int m = brow + (tid >> 3) + t * 32;
        int b = m / 196, rem = m % 196;
        int oh = rem / 14, ow = rem % 14;
        px[t] = xin + ((size_t)((b * 56 + oh * 4) * 56 + ow * 4)) * 256;
    }

    float acc[4][4][4];
    #pragma unroll
    for (int i = 0; i < 4; i++)
        #pragma unroll
        for (int j = 0; j < 4; j++)
            #pragma unroll
            for (int r = 0; r < 4; r++) acc[i][j][r] = 0.f;

    const int KT = 32;   // 1024 / 32
    auto issue = [&](int buf, int k0) {
        float* Ad = Asm + buf * ABUF;
        float* Bd = Bsm + buf * BBUF;
        int kk = kc * 1024 + k0 + c4 * 4;
        int kh = kk >> 10, kw = (kk >> 8) & 3, c = kk & 255;
        int off = (kh * 56 + kw) * 256 + c;
        #pragma unroll
        for (int t = 0; t < 4; t++) {
            int row = (tid >> 3) + t * 32;
            uint32_t d = (uint32_t)__cvta_generic_to_shared(Ad + row * ASTRIDE + c4 * 4);
            CP16(d, px[t] + off);
        }
        #pragma unroll
        for (int t = 0; t < 4; t++) {
            int idx = tid + t * 256;
            int kr = idx >> 5, cc4 = idx & 31;
            uint32_t d = (uint32_t)__cvta_generic_to_shared(Bd + kr * BSTRIDE + cc4 * 4);
            CP16(d, Bm + (size_t)(kc * 1024 + k0 + kr) * N + bcol + cc4 * 4);
        }
        asm volatile("cp.async.commit_group;" ::);
    };

    issue(0, 0);
    int buf = 0;
    for (int kt = 0; kt < KT; kt++) {
        asm volatile("cp.async.wait_group 0;" ::);
        __syncthreads();
        if (kt + 1 < KT) issue(buf ^ 1, (kt + 1) << 5);
        const float* Ad = Asm + buf * ABUF;
        const float* Bd = Bsm + buf * BBUF;
        #pragma unroll
        for (int ks = 0; ks < 4; ks++) {
            const int k = ks * 8;
            uint32_t af[4][4], bf[4][2];
            #pragma unroll
            for (int mi = 0; mi < 4; mi++) {
                int r0 = wm + mi * 16 + lr;
                af[mi][0] = f2tf(Ad[r0 * ASTRIDE + k + lc]);
                af[mi][1] = f2tf(Ad[(r0 + 8) * ASTRIDE + k + lc]);
                af[mi][2] = f2tf(Ad[r0 * ASTRIDE + k + 4 + lc]);
                af[mi][3] = f2tf(Ad[(r0 + 8) * ASTRIDE + k + 4 + lc]);
            }
            #pragma unroll
            for (int nj = 0; nj < 4; nj++) {
                int cc = wn + nj * 8 + lr;
                bf[nj][0] = f2tf(Bd[(k + lc) * BSTRIDE + cc]);
                bf[nj][1] = f2tf(Bd[(k + 4 + lc) * BSTRIDE + cc]);
            }
            #pragma unroll
            for (int mi = 0; mi < 4; mi++)
                #pragma unroll
                for (int nj = 0; nj < 4; nj++)
                    MMA_TF32(acc[mi][nj], af[mi], bf[nj]);
        }
        buf ^= 1;
    }
    #pragma unroll
    for (int mi = 0; mi < 4; mi++) {
        #pragma unroll
        for (int nj = 0; nj < 4; nj++) {
            int r0 = brow + wm + mi * 16 + lr;
            int c0 = bcol + wn + nj * 8 + lc * 2;
            *(float2*)&C[(size_t)r0 * 256 + c0] = make_float2(acc[mi][nj][0], acc[mi][nj][1]);
            *(float2*)&C[(size_t)(r0 + 8) * 256 + c0] = make_float2(acc[mi][nj][2], acc[mi][nj][3]);
        }
    }
}

// ============ proj GEMM with fused concat(x1,x2)+lepe A ============
__global__ __launch_bounds__(256, 2)
void tgemm_proj(const float* __restrict__ x1, const float* __restrict__ x2,
                const float* __restrict__ lepe, const float* __restrict__ Bm,
                const float* __restrict__ bias, float* __restrict__ C) {
    const int N = 256, K = 256;
    extern __shared__ float sm[];
    float* Asm = sm;
    float* Bsm = sm + 2 * ABUF;
    const int tid  = threadIdx.x;
    const int lane = tid & 31;
    const int warp = tid >> 5;
    const int wm = (warp >> 2) * 64;
    const int wn = (warp & 3) * 32;
    const int brow = blockIdx.y * 128;
    const int bcol = blockIdx.x * 128;
    const int lr = lane >> 2;
    const int lc = lane & 3;
    const int c4 = tid & 7;

    float acc[4][4][4];
    #pragma unroll
    for (int i = 0; i < 4; i++)
        #pragma unroll
        for (int j = 0; j < 4; j++)
            #pragma unroll
            for (int r = 0; r < 4; r++) acc[i][j][r] = 0.f;

    auto issueB = [&](int buf, int k0) {
        float* Bd = Bsm + buf * BBUF;
        #pragma unroll
        for (int t = 0; t < 4; t++) {
            int idx = tid + t * 256;
            int kr = idx >> 5, cc4 = idx & 31;
            uint32_t d = (uint32_t)__cvta_generic_to_shared(Bd + kr * BSTRIDE + cc4 * 4);
            CP16(d, Bm + (size_t)(k0 + kr) * N + bcol + cc4 * 4);
        }
        asm volatile("cp.async.commit_group;" ::);
    };
    float4 ra[4];
    auto loadA = [&](int k0) {
        int kk = k0 + c4 * 4;
        #pragma unroll
        for (int t = 0; t < 4; t++) {
            size_t m = (size_t)(brow + (tid >> 3) + t * 32);
            float4 a;
            if (kk < 128) a = *(const float4*)&x1[m * 128 + kk];
            else          a = *(const float4*)&x2[m * 128 + kk - 128];
            float4 l = *(const float4*)&lepe[m * 256 + kk];
            a.x += l.x; a.y += l.y; a.z += l.z; a.w += l.w;
            ra[t] = a;
        }
    };
    auto storeA = [&](int buf) {
        float* Ad = Asm + buf * ABUF;
        #pragma unroll
        for (int t = 0; t < 4; t++)
            *(float4*)&Ad[((tid >> 3) + t * 32) * ASTRIDE + c4 * 4] = ra[t];
    };

    issueB(0, 0);
    loadA(0);
    int buf = 0;
    const int KT = K >> 5;
    for (int kt = 0; kt < KT; kt++) {
        storeA(buf);
        asm volatile("cp.async.wait_group 0;" ::);
        __syncthreads();
        if (kt + 1 < KT) { issueB(buf ^ 1, (kt + 1) << 5); loadA((kt + 1) << 5); }
        const float* Ad = Asm + buf * ABUF;
        const float* Bd = Bsm + buf * BBUF;
        #pragma unroll
        for (int ks = 0; ks < 4; ks++) {
            const int k = ks * 8;
            uint32_t af[4][4], bf[4][2];
            #pragma unroll
            for (int mi = 0; mi < 4; mi++) {
                int r0 = wm + mi * 16 + lr;
                af[mi][0] = f2tf(Ad[r0 * ASTRIDE + k + lc]);
                af[mi][1] = f2tf(Ad[(r0 + 8) * ASTRIDE + k + lc]);
                af[mi][2] = f2tf(Ad[r0 * ASTRIDE + k + 4 + lc]);
                af[mi][3] = f2tf(Ad[(r0 + 8) * ASTRIDE + k + 4 + lc]);
            }
            #pragma unroll
            for (int nj = 0; nj < 4; nj++) {
                int cc = wn + nj * 8 + lr;
                bf[nj][0] = f2tf(Bd[(k + lc) * BSTRIDE + cc]);
                bf[nj][1] = f2tf(Bd[(k + 4 + lc) * BSTRIDE + cc]);
            }
            #pragma unroll
            for (int mi = 0; mi < 4; mi++)
                #pragma unroll
                for (int nj = 0; nj < 4; nj++)
                    MMA_TF32(acc[mi][nj], af[mi], bf[nj]);
        }
        buf ^= 1;
        __syncthreads();
    }
    #pragma unroll
    for (int mi = 0; mi < 4; mi++) {
        #pragma unroll
        for (int nj = 0; nj < 4; nj++) {
            int r0 = brow + wm + mi * 16 + lr;
            int c0 = bcol + wn + nj * 8 + lc * 2;
            float b0 = bias[c0], b1 = bias[c0 + 1];
            *(float2*)&C[(size_t)r0 * N + c0] = make_float2(acc[mi][nj][0] + b0, acc[mi][nj][1] + b1);
            *(float2*)&C[(size_t)(r0 + 8) * N + c0] = make_float2(acc[mi][nj][2] + b0, acc[mi][nj][3] + b1);
        }
    }
}

// ============ depthwise 3x3, register y-walk (reads packed cols 0..255) ============
__global__ void dwconv3x3(const float* __restrict__ in, const float* __restrict__ w,
                          const float* __restrict__ bias, float* __restrict__ out) {
    int idx = blockIdx.x * 256 + threadIdx.x;
    int c = idx & 255;
    int t = idx >> 8;
    int xx = t % WW, b = t / WW;
    float wt[9];
    #pragma unroll
    for (int i = 0; i < 9; i++) wt[i] = w[i * 256 + c];
    float bz = bias[c];
    const float* base = in + (size_t)b * NTOK * 768 + c;
    float* ob = out + (size_t)b * NTOK * 256 + c;
    bool xl = xx > 0, xr = xx < WW - 1;

    float rA[3] = {0.f, 0.f, 0.f}, rB[3], rC[3];
    {
        const float* rp = base;
        rB[0] = xl ? rp[(xx - 1) * 768] : 0.f;
        rB[1] = rp[xx * 768];
        rB[2] = xr ? rp[(xx + 1) * 768] : 0.f;
    }
    for (int y = 0; y < HH; y++) {
        if (y + 1 < HH) {
            const float* rp = base + (size_t)(y + 1) * WW * 768;
            rC[0] = xl ? rp[(xx - 1) * 768] : 0.f;
            rC[1] = rp[xx * 768];
            rC[2] = xr ? rp[(xx + 1) * 768] : 0.f;
        } else { rC[0] = rC[1] = rC[2] = 0.f; }
        float acc = bz
            + wt[0] * rA[0] + wt[1] * rA[1] + wt[2] * rA[2]
            + wt[3] * rB[0] + wt[4] * rB[1] + wt[5] * rB[2]
            + wt[6] * rC[0] + wt[7] * rC[1] + wt[8] * rC[2];
        ob[(size_t)(y * WW + xx) * 256] = acc;
        rA[0] = rB[0]; rA[1] = rB[1]; rA[2] = rB[2];
        rB[0] = rC[0]; rB[1] = rC[1]; rB[2] = rC[2];
    }
}

// ============ split-K reduce + bias + LayerNorm + exact GELU ============
__global__ void ln_gelu4(const float* __restrict__ p, const float* __restrict__ srb,
                         const float* __restrict__ g, const float* __restrict__ bb,
                         float* __restrict__ xb) {
    int row = blockIdx.x;
    int tid = threadIdx.x;
    const size_t S = (size_t)M_SR * 256;
    size_t off = (size_t)row * 256 + tid;
    float v = p[off] + p[S + off] + p[2 * S + off] + p[3 * S + off] + srb[tid];
    __shared__ float s1[256], s2[256];
    s1[tid] = v; s2[tid] = v * v;
    __syncthreads();
    for (int o = 128; o; o >>= 1) {
        if (tid < o) { s1[tid] += s1[tid + o]; s2[tid] += s2[tid + o]; }
        __syncthreads();
    }
    float mu  = s1[0] * (1.f / CH);
    float var = s2[0] * (1.f / CH) - mu * mu;
    float tt = (v - mu) * rsqrtf(var + 1e-5f) * g[tid] + bb[tid];
    xb[off] = 0.5f * tt * (1.f + erff(tt * 0.70710678118654752f));
}

// ============ branch-1 attention (MMA), S aliased over Q/K -> occ 2 ============
// layout: Qs[64][36]@0, Ks[32][228]@2304, Ss[64][228]@0 (alias), Vs[200][36]@14592
#define A1_SMEM ((14592 + 7200) * 4)   // 87168 B
__global__ __launch_bounds__(256, 2)
void attn1_mma(const float* __restrict__ pack, const float* __restrict__ kv1,
               float* __restrict__ x1) {
    extern __shared__ float sm[];
    float* Qs = sm;
    float* Ks = sm + 2304;
    float* Ss = sm;
    float* Vs = sm + 14592;
    int bh = blockIdx.y, b = bh >> 2, h = bh & 3;
    int q0 = blockIdx.x * 64;
    int tid = threadIdx.x, lane = tid & 31, warp = tid >> 5;
    int lr = lane >> 2, lc = lane & 3;

    for (int e = tid; e < 64 * 8; e += 256) {
        int r = e >> 3, c4 = e & 7;
        float4 v = *(const float4*)&pack[((size_t)b * NTOK + q0 + r) * 768 + 256 + h * 32 + c4 * 4];
        *(float4*)&Qs[r * 36 + c4 * 4] = v;
    }
    for (int e = tid; e < 196 * 32; e += 256) {
        int m = e >> 5, dd = e & 31;
        size_t base = ((size_t)b * N1 + m) * 256 + h * 32 + dd;
        Ks[dd * 228 + m] = kv1[base];
        Vs[m * 36 + dd]  = kv1[base + 128];
    }
    for (int e = tid; e < 32 * 32; e += 256) {
        int k = e >> 5, c = e & 31;
        Ks[k * 228 + 196 + c] = 0.f;
    }
    if (tid < 128) {
        int m = 196 + (tid >> 5), dd = tid & 31;
        Vs[m * 36 + dd] = 0.f;
    }
    __syncthreads();

    // scores S[64,224] = Q @ K^T, warp grid 2x4, tile 32x56
    {
        int wm = (warp >> 2) * 32, wn = (warp & 3) * 56;
        float acc[2][7][4];
        #pragma unroll
        for (int i = 0; i < 2; i++)
            #pragma unroll
            for (int j = 0; j < 7; j++)
                #pragma unroll
                for (int r = 0; r < 4; r++) acc[i][j][r] = 0.f;
        #pragma unroll
        for (int ks = 0; ks < 4; ks++) {
            const int k = ks * 8;
            uint32_t af[2][4], bf[7][2];
            #pragma unroll
            for (int mi = 0; mi < 2; mi++) {
                int r0 = wm + mi * 16 + lr;
                af[mi][0] = f2tf(Qs[r0 * 36 + k + lc]);
                af[mi][1] = f2tf(Qs[(r0 + 8) * 36 + k + lc]);
                af[mi][2] = f2tf(Qs[r0 * 36 + k + 4 + lc]);
                af[mi][3] = f2tf(Qs[(r0 + 8) * 36 + k + 4 + lc]);
            }
            #pragma unroll
            for (int nj = 0; nj < 7; nj++) {
                int cc = wn + nj * 8 + lr;
                bf[nj][0] = f2tf(Ks[(k + lc) * 228 + cc]);
                bf[nj][1] = f2tf(Ks[(k + 4 + lc) * 228 + cc]);
            }
            #pragma unroll
            for (int mi = 0; mi < 2; mi++)
                #pragma unroll
                for (int nj = 0; nj < 7; nj++)
                    MMA_TF32(acc[mi][nj], af[mi], bf[nj]);
        }
        __syncthreads();   // Q/K reads done before S overwrites them
        #pragma unroll
        for (int mi = 0; mi < 2; mi++)
            #pragma unroll
            for (int nj = 0; nj < 7; nj++) {
                int r0 = wm + mi * 16 + lr;
                int c0 = wn + nj * 8 + lc * 2;
                Ss[r0 * 228 + c0]           = acc[mi][nj][0] * SCALE;
                Ss[r0 * 228 + c0 + 1]       = acc[mi][nj][1] * SCALE;
                Ss[(r0 + 8) * 228 + c0]     = acc[mi][nj][2] * SCALE;
                Ss[(r0 + 8) * 228 + c0 + 1] = acc[mi][nj][3] * SCALE;
            }
    }
    __syncthreads();

    // softmax over cols 0..195 (196..223 stay 0)
    #pragma unroll
    for (int r = 0; r < 8; r++) {
        int row = warp * 8 + r;
        float mx = -1e30f;
        for (int m = lane; m < 196; m += 32) mx = fmaxf(mx, Ss[row * 228 + m]);
        #pragma unroll
        for (int o = 16; o; o >>= 1) mx = fmaxf(mx, __shfl_xor_sync(0xffffffffu, mx, o));
        float sum = 0.f;
        for (int m = lane; m < 196; m += 32) {
            float p = __expf(Ss[row * 228 + m] - mx);
            Ss[row * 228 + m] = p;
            sum += p;
        }
        #pragma unroll
        for (int o = 16; o; o >>= 1) sum += __shfl_xor_sync(0xffffffffu, sum, o);
        float inv = 1.f / sum;
        for (int m = lane; m < 196; m += 32) Ss[row * 228 + m] *= inv;
    }
    __syncthreads();

    // out = P[64,200] @ V[200,32], warp grid 4x2, tile 16x16
    {
        int wm = (warp >> 1) * 16, wn = (warp & 1) * 16;
        float acc[2][4];
        #pragma unroll
        for (int j = 0; j < 2; j++)
            #pragma unroll
            for (int r = 0; r < 4; r++) acc[j][r] = 0.f;
        #pragma unroll 5
        for (int ks = 0; ks < 25; ks++) {
            const int k = ks * 8;
            uint32_t af[4], bf[2][2];
            af[0] = f2tf(Ss[(wm + lr) * 228 + k + lc]);
            af[1] = f2tf(Ss[(wm + 8 + lr) * 228 + k + lc]);
            af[2] = f2tf(Ss[(wm + lr) * 228 + k + 4 + lc]);
            af[3] = f2tf(Ss[(wm + 8 + lr) * 228 + k + 4 + lc]);
            #pragma unroll
            for (int nj = 0; nj < 2; nj++) {
                int cc = wn + nj * 8 + lr;
                bf[nj][0] = f2tf(Vs[(k + lc) * 36 + cc]);
                bf[nj][1] = f2tf(Vs[(k + 4 + lc) * 36 + cc]);
            }
            MMA_TF32(acc[0], af, bf[0]);
            MMA_TF32(acc[1], af, bf[1]);
        }
        #pragma unroll
        for (int nj = 0; nj < 2; nj++) {
            int r0 = q0 + wm + lr;
            int c0 = wn + nj * 8 + lc * 2;
            *(float2*)&x1[((size_t)b * NTOK + r0) * 128 + h * 32 + c0] =
                make_float2(acc[nj][0], acc[nj][1]);
            *(float2*)&x1[((size_t)b * NTOK + r0 + 8) * 128 + h * 32 + c0] =
                make_float2(acc[nj][2], acc[nj][3]);
        }
    }
}

// ============ branch-2 window attention (MMA), 2 windows/CTA ============
// per window (floats): alias region 4480 = Qs[64][36](2304)+Kt[32][68](2176); Ss[64][68](4352) aliases it
//                      Vs[56][36](2016) at +4480.  WSZ=6496 floats; 2 windows = 51968 B
#define A2_WSZ 6496
#define A2_SMEM (2 * A2_WSZ * 4)
__global__ __launch_bounds__(256, 4)
void attn2_mma(const float* __restrict__ pack, float* __restrict__ x2) {
    extern __shared__ float sm[];
    int bh = blockIdx.y, b = bh >> 2, h = bh & 3;
    int tid = threadIdx.x, lane = tid & 31, warp = tid >> 5;
    int wslot = warp >> 2, w4 = warp & 3;
    int lr = lane >> 2, lc = lane & 3;
    int win = blockIdx.x * 2 + wslot;
    int wr = win >> 3, wc = win & 7;
    float* base = sm + wslot * A2_WSZ;
    float* Qs = base;            // [64][36]
    float* Kt = base + 2304;     // [32][68]
    float* Ss = base;            // [64][68] alias
    float* Vs = base + 4480;     // [56][36]
    int wt = tid & 127;          // 128 threads per window

    for (int e = wt; e < 64 * 8; e += 128) {
        int r = e >> 3, c4 = e & 7;
        float4 v = make_float4(0.f, 0.f, 0.f, 0.f);
        if (r < 49) {
            int n = (wr * 7 + r / 7) * 56 + wc * 7 + r % 7;
            v = *(const float4*)&pack[((size_t)b * NTOK + n) * 768 + 384 + h * 32 + c4 * 4];
        }
        *(float4*)&Qs[r * 36 + c4 * 4] = v;
    }
    for (int e = wt; e < 56 * 32; e += 128) {
        int m = e >> 5, dd = e & 31;
        float kk = 0.f, vv = 0.f;
        if (m < 49) {
            int n = (wr * 7 + m / 7) * 56 + wc * 7 + m % 7;
            size_t rb = ((size_t)b * NTOK + n) * 768 + 512 + h * 32 + dd;
            kk = pack[rb];
            vv = pack[rb + 128];
        }
        Kt[dd * 68 + m] = kk;
        Vs[m * 36 + dd] = vv;
    }
    __syncthreads();

    // scores: warp w4 rows [w4*16, +16), cols 0..55
    int wm = w4 * 16;
    {
        float acc[7][4];
        #pragma unroll
        for (int j = 0; j < 7; j++)
            #pragma unroll
            for (int r = 0; r < 4; r++) acc[j][r] = 0.f;
        #pragma unroll
        for (int ks = 0; ks < 4; ks++) {
            const int k = ks * 8;
            uint32_t af[4], bf[7][2];
            af[0] = f2tf(Qs[(wm + lr) * 36 + k + lc]);
            af[1] = f2tf(Qs[(wm + 8 + lr) * 36 + k + lc]);
            af[2] = f2tf(Qs[(wm + lr) * 36 + k + 4 + lc]);
            af[3] = f2tf(Qs[(wm + 8 + lr) * 36 + k + 4 + lc]);
            #pragma unroll
            for (int nj = 0; nj < 7; nj++) {
                int cc = nj * 8 + lr;
                bf[nj][0] = f2tf(Kt[(k + lc) * 68 + cc]);
                bf[nj][1] = f2tf(Kt[(k + 4 + lc) * 68 + cc]);
            }
            #pragma unroll
            for (int nj = 0; nj < 7; nj++)
                MMA_TF32(acc[nj], af, bf[nj]);
        }
        __syncthreads();   // Q/K reads done before S overwrites
        #pragma unroll
        for (int nj = 0; nj < 7; nj++) {
            int c0 = nj * 8 + lc * 2;
            Ss[(wm + lr) * 68 + c0]           = acc[nj][0] * SCALE;
            Ss[(wm + lr) * 68 + c0 + 1]       = acc[nj][1] * SCALE;
            Ss[(wm + 8 + lr) * 68 + c0]       = acc[nj][2] * SCALE;
            Ss[(wm + 8 + lr) * 68 + c0 + 1]   = acc[nj][3] * SCALE;
        }
    }
    __syncthreads();

    // softmax rows < 49 over cols 0..48 (cols 49..55 are exactly 0 -> P=0, V rows 0 too)
    for (int row = w4; row < 49; row += 4) {
        float mx = -1e30f;
        for (int m = lane; m < 49; m += 32) mx = fmaxf(mx, Ss[row * 68 + m]);
        #pragma unroll
        for (int o = 16; o; o >>= 1) mx = fmaxf(mx, __shfl_xor_sync(0xffffffffu, mx, o));
        float sum = 0.f;
        for (int m = lane; m < 49; m += 32) {
            float p = __expf(Ss[row * 68 + m] - mx);
            Ss[row * 68 + m] = p;
            sum += p;
        }
        #pragma unroll
        for (int o = 16; o; o >>= 1) sum += __shfl_xor_sync(0xffffffffu, sum, o);
        float inv = 1.f / sum;
        for (int m = lane; m < 49; m += 32) Ss[row * 68 + m] *= inv;
    }
    __syncthreads();

    // out = P[64,56] @ V[56,32]
    {
        float acc[4][4];
        #pragma unroll
        for (int j = 0; j < 4; j++)
            #pragma unroll
            for (int r = 0; r < 4; r++) acc[j][r] = 0.f;
        #pragma unroll
        for (int ks = 0; ks < 7; ks++) {
            const int k = ks * 8;
            uint32_t af[4], bf[4][2];
            af[0] = f2tf(Ss[(wm + lr) * 68 + k + lc]);
            af[1] = f2tf(Ss[(wm + 8 + lr) * 68 + k + lc]);
            af[2] = f2tf(Ss[(wm + lr) * 68 + k + 4 + lc]);
            af[3] = f2tf(Ss[(wm + 8 + lr) * 68 + k + 4 + lc]);
            #pragma unroll
            for (int nj = 0; nj < 4; nj++) {
                int cc = nj * 8 + lr;
                bf[nj][0] = f2tf(Vs[(k + lc) * 36 + cc]);
                bf[nj][1] = f2tf(Vs[(k + 4 + lc) * 36 + cc]);
            }
            #pragma unroll
            for (int nj = 0; nj < 4; nj++)
                MMA_TF32(acc[nj], af, bf[nj]);
        }
        int r1 = wm + lr, r2 = wm + 8 + lr;
        #pragma unroll
        for (int nj = 0; nj < 4; nj++) {
            int c0 = nj * 8 + lc * 2;
            if (r1 < 49) {
                int n = (wr * 7 + r1 / 7) * 56 + wc * 7 + r1 % 7;
                *(float2*)&x2[((size_t)b * NTOK + n) * 128 + h * 32 + c0] =
                    make_float2(acc[nj][0], acc[nj][1]);
            }
            if (r2 < 49) {
                int n = (wr * 7 + r2 / 7) * 56 + wc * 7 + r2 % 7;
                *(float2*)&x2[((size_t)b * NTOK + n) * 128 + h * 32 + c0] =
                    make_float2(acc[nj][2], acc[nj][3]);
            }
        }
    }
}

// ---------------- host launch ----------------
extern "C" void kernel_launch(void* const* d_in, const int* in_sizes, int n_in,
                              void* d_out, int out_size) {
    const float* x           = (const float*)d_in[0];
    const float* lepe_lin_w  = (const float*)d_in[1];
    const float* lepe_lin_b  = (const float*)d_in[2];
    const float* lepe_conv_w = (const float*)d_in[3];
    const float* lepe_conv_b = (const float*)d_in[4];
    const float* sr_w        = (const float*)d_in[5];
    const float* sr_b        = (const float*)d_in[6];
    const float* norm_g      = (const float*)d_in[7];
    const float* norm_b      = (const float*)d_in[8];
    const float* q1_w        = (const float*)d_in[9];
    const float* kv1_w       = (const float*)d_in[10];
    const float* q2_w        = (const float*)d_in[11];
    const float* kv2_w       = (const float*)d_in[12];
    const float* proj_w      = (const float*)d_in[13];
    const float* proj_b      = (const float*)d_in[14];
    float* out = (float*)d_out;

    float *pack, *lepe, *wpack, *bpack, *srp, *x1s, *kv1, *x1, *x2;
    cudaGetSymbolAddress((void**)&pack,  g_pack);
    cudaGetSymbolAddress((void**)&lepe,  g_lepe);
    cudaGetSymbolAddress((void**)&wpack, g_wpack);
    cudaGetSymbolAddress((void**)&bpack, g_bpack);
    cudaGetSymbolAddress((void**)&srp,   g_srp);
    cudaGetSymbolAddress((void**)&x1s,   g_x1s);
    cudaGetSymbolAddress((void**)&kv1,   g_kv1);
    cudaGetSymbolAddress((void**)&x1,    g_x1);
    cudaGetSymbolAddress((void**)&x2,    g_x2);

    cudaFuncSetAttribute(tgemm128,       cudaFuncAttributeMaxDynamicSharedMemorySize, TG_SMEM);
    cudaFuncSetAttribute(tgemm_sr_split, cudaFuncAttributeMaxDynamicSharedMemorySize, TG_SMEM);
    cudaFuncSetAttribute(tgemm_proj,     cudaFuncAttributeMaxDynamicSharedMemorySize, TG_SMEM);
    cudaFuncSetAttribute(attn1_mma,      cudaFuncAttributeMaxDynamicSharedMemorySize, A1_SMEM);
    cudaFuncSetAttribute(attn2_mma,      cudaFuncAttributeMaxDynamicSharedMemorySize, A2_SMEM);

    // pack weights, merged projection GEMM (lepe_lin | q1 | q2 | kv2)
    pack_weights<<<768, 256>>>(lepe_lin_w, lepe_lin_b, q1_w, q2_w, kv2_w, wpack, bpack);
    tgemm128<<<dim3(6, M_ALL / 128), 256, TG_SMEM>>>(x, wpack, bpack, pack, M_ALL, 768, 256);

    // lepe depthwise conv (reads packed cols 0..255)
    dwconv3x3<<<(BATCH * WW * CH) / 256, 256>>>(pack, lepe_conv_w, lepe_conv_b, lepe);

    // sr conv: fused im2col, split-K x4 -> reduce+LN+GELU -> kv1
    tgemm_sr_split<<<dim3(2, M_SR / 128, 4), 256, TG_SMEM>>>(x, sr_w, srp);
    ln_gelu4<<<M_SR, 256>>>(srp, sr_b, norm_g, norm_b, x1s);
    tgemm128<<<dim3(2, M_SR / 128), 256, TG_SMEM>>>(x1s, kv1_w, nullptr, kv1, M_SR, 256, 256);

    // attention branches
    attn1_mma<<<dim3(NTOK / 64, BATCH * H2), 256, A1_SMEM>>>(pack, kv1, x1);
    attn2_mma<<<dim3(32, BATCH * H2), 256, A2_SMEM>>>(pack, x2);

    // fused concat+lepe + final projection
    tgemm_proj<<<dim3(2, M_ALL / 128), 256, TG_SMEM>>>(x1, x2, lepe, proj_w, proj_b, out);
}

// round 5
// speedup vs baseline: 3.3573x; 1.0256x over previous
#include <cuda_runtime.h>
#include <cstdint>

#define BATCH 32
#define HH 56
#define WW 56
#define NTOK (HH*WW)            // 3136
#define CH 256
#define H2 4
#define M_ALL (BATCH*NTOK)      // 100352
#define N1 196
#define M_SR (BATCH*N1)         // 6272
#define SCALE 0.17677669529663687f

// ---------------- scratch ----------------
__device__ float g_pack  [(size_t)M_ALL*768];   // [lepe_lin | q1 | q2 | kv2]
__device__ float g_lepe  [(size_t)M_ALL*CH];
__device__ float g_wpack [(size_t)256*768];
__device__ float g_bpack [768];
__device__ float g_srw   [(size_t)4096*256];    // rounded sr weights
__device__ float g_kv1w  [(size_t)256*256];
__device__ float g_projw [(size_t)256*256];
__device__ float g_srp   [(size_t)4*M_SR*CH];   // split-K partials
__device__ float g_x1s   [(size_t)M_SR*CH];
__device__ float g_kv1   [(size_t)M_SR*CH];
__device__ float g_x1    [(size_t)M_ALL*128];
__device__ float g_x2    [(size_t)M_ALL*128];

// ---------------- common MMA helpers ----------------
__device__ __forceinline__ uint32_t f2tf(float f) {
    uint32_t u;
    asm("cvt.rna.tf32.f32 %0, %1;" : "=r"(u) : "f"(f));
    return u;
}
__device__ __forceinline__ float rndf(float f) { return __uint_as_float(f2tf(f)); }
template<bool CVT>
__device__ __forceinline__ uint32_t ldtf(float f) {
    return CVT ? f2tf(f) : __float_as_uint(f);
}
#define CP16(dst, src) \
    asm volatile("cp.async.cg.shared.global [%0], [%1], 16;" :: "r"(dst), "l"(src))
#define MMA_TF32(c, a, b) \
    asm volatile("mma.sync.aligned.m16n8k8.row.col.f32.tf32.tf32.f32 " \
                 "{%0,%1,%2,%3},{%4,%5,%6,%7},{%8,%9},{%0,%1,%2,%3};" \
                 : "+f"((c)[0]), "+f"((c)[1]), "+f"((c)[2]), "+f"((c)[3]) \
                 : "r"((a)[0]), "r"((a)[1]), "r"((a)[2]), "r"((a)[3]), \
                   "r"((b)[0]), "r"((b)[1]))

#define ASTRIDE 36
#define BSTRIDE 132
#define ABUF (128*ASTRIDE)
#define BBUF (32*BSTRIDE)
#define TG_SMEM ((2*ABUF + 2*BBUF) * 4)   // 70656 bytes

// ============ weight prep: pack + pre-round to tf32 ============
__global__ void pack_weights(const float* __restrict__ lw, const float* __restrict__ lb,
                             const float* __restrict__ q1w, const float* __restrict__ q2w,
                             const float* __restrict__ kvw,
                             float* __restrict__ wp, float* __restrict__ bp) {
    int idx = blockIdx.x * 256 + threadIdx.x;
    if (idx < 768) bp[idx] = (idx < 256) ? lb[idx] : 0.f;
    if (idx >= 256 * 768) return;
    int k = idx / 768, c = idx % 768;
    float v;
    if (c < 256)      v = lw[k * 256 + c];
    else if (c < 384) v = q1w[k * 128 + (c - 256)];
    else if (c < 512) v = q2w[k * 128 + (c - 384)];
    else              v = kvw[k * 256 + (c - 512)];
    wp[idx] = rndf(v);
}

__global__ void round_weights(const float* __restrict__ sw, const float* __restrict__ kw,
                              const float* __restrict__ pw,
                              float* __restrict__ so, float* __restrict__ ko,
                              float* __restrict__ po) {
    int i = blockIdx.x * 256 + threadIdx.x;
    if (i < 4096 * 256) so[i] = rndf(sw[i]);
    if (i < 256 * 256) { ko[i] = rndf(kw[i]); po[i] = rndf(pw[i]); }
}

// ============ generic tf32 GEMM: C[M,N]=A@B (+bias) ============
template<bool CA, bool CB>
__global__ __launch_bounds__(256, 2)
void tgemm128(const float* __restrict__ A, const float* __restrict__ Bm,
              const float* __restrict__ bias, float* __restrict__ C,
              int M, int N, int K) {
    extern __shared__ float sm[];
    float* Asm = sm;
    float* Bsm = sm + 2 * ABUF;
    const int tid  = threadIdx.x;
    const int lane = tid & 31;
    const int warp = tid >> 5;
    const int wm = (warp >> 2) * 64;
    const int wn = (warp & 3) * 32;
    const int brow = blockIdx.y * 128;
    const int bcol = blockIdx.x * 128;
    const int lr = lane >> 2;
    const int lc = lane & 3;

    float acc[4][4][4];
    #pragma unroll
    for (int i = 0; i < 4; i++)
        #pragma unroll
        for (int j = 0; j < 4; j++)
            #pragma unroll
            for (int r = 0; r < 4; r++) acc[i][j][r] = 0.f;

    const int KT = K >> 5;
    auto issue = [&](int buf, int k0) {
        float* Ad = Asm + buf * ABUF;
        float* Bd = Bsm + buf * BBUF;
        #pragma unroll
        for (int t = 0; t < 4; t++) {
            int idx = tid + t * 256;
            int row = idx >> 3, c4 = idx & 7;
            uint32_t d = (uint32_t)__cvta_generic_to_shared(Ad + row * ASTRIDE + c4 * 4);
            CP16(d, A + (size_t)(brow + row) * K + k0 + c4 * 4);
        }
        #pragma unroll
        for (int t = 0; t < 4; t++) {
            int idx = tid + t * 256;
            int kr = idx >> 5, c4 = idx & 31;
            uint32_t d = (uint32_t)__cvta_generic_to_shared(Bd + kr * BSTRIDE + c4 * 4);
            CP16(d, Bm + (size_t)(k0 + kr) * N + bcol + c4 * 4);
        }
        asm volatile("cp.async.commit_group;" ::);
    };

    issue(0, 0);
    int buf = 0;
    for (int kt = 0; kt < KT; kt++) {
        asm volatile("cp.async.wait_group 0;" ::);
        __syncthreads();
        if (kt + 1 < KT) issue(buf ^ 1, (kt + 1) << 5);
        const float* Ad = Asm + buf * ABUF;
        const float* Bd = Bsm + buf * BBUF;
        #pragma unroll
        for (int ks = 0; ks < 4; ks++) {
            const int k = ks * 8;
            uint32_t af[4][4], bf[4][2];
            #pragma unroll
            for (int mi = 0; mi < 4; mi++) {
                int r0 = wm + mi * 16 + lr;
                af[mi][0] = ldtf<CA>(Ad[r0 * ASTRIDE + k + lc]);
                af[mi][1] = ldtf<CA>(Ad[(r0 + 8) * ASTRIDE + k + lc]);
                af[mi][2] = ldtf<CA>(Ad[r0 * ASTRIDE + k + 4 + lc]);
                af[mi][3] = ldtf<CA>(Ad[(r0 + 8) * ASTRIDE + k + 4 + lc]);
            }
            #pragma unroll
            for (int nj = 0; nj < 4; nj++) {
                int cc = wn + nj * 8 + lr;
                bf[nj][0] = ldtf<CB>(Bd[(k + lc) * BSTRIDE + cc]);
                bf[nj][1] = ldtf<CB>(Bd[(k + 4 + lc) * BSTRIDE + cc]);
            }
            #pragma unroll
            for (int mi = 0; mi < 4; mi++)
                #pragma unroll
                for (int nj = 0; nj < 4; nj++)
                    MMA_TF32(acc[mi][nj], af[mi], bf[nj]);
        }
        buf ^= 1;
    }
    #pragma unroll
    for (int mi = 0; mi < 4; mi++) {
        #pragma unroll
        for (int nj = 0; nj < 4; nj++) {
            int r0 = brow + wm + mi * 16 + lr;
            int c0 = bcol + wn + nj * 8 + lc * 2;
            float b0 = 0.f, b1 = 0.f;
            if (bias) { b0 = bias[c0]; b1 = bias[c0 + 1]; }
            *(float2*)&C[(size_t)r0 * N + c0] = make_float2(acc[mi][nj][0] + b0, acc[mi][nj][1] + b1);
            *(float2*)&C[(size_t)(r0 + 8) * N + c0] = make_float2(acc[mi][nj][2] + b0, acc[mi][nj][3] + b1);
        }
    }
}

// ============ sr-conv GEMM, fused im2col, split-K x4 (B pre-rounded) ============
__global__ __launch_bounds__(256, 2)
void tgemm_sr_split(const float* __restrict__ xin, const float* __restrict__ Bm,
                    float* __restrict__ Cp) {
    const int N = 256;
    const int kc = blockIdx.z;
    float* C = Cp + (size_t)kc * M_SR * 256;
    extern __shared__ float sm[];
    float* Asm = sm;
    float* Bsm = sm + 2 * ABUF;
    const int tid  = threadIdx.x;
    const int lane = tid & 31;
    const int warp = tid >> 5;
    const int wm = (warp >> 2) * 64;
    const int wn = (warp & 3) * 32;
    const int brow = blockIdx.y * 128;
    const int bcol = blockIdx.x * 128;
    const int lr = lane >> 2;
    const int lc = lane & 3;
    const int c4 = tid & 7;

    const float* px[4];
    #pragma unroll
    for (int t = 0; t < 4; t++) {
        int m = brow + (tid >> 3) + t * 32;
        int b = m / 196, rem = m % 196;
        int oh = rem / 14, ow = rem % 14;
        px[t] = xin + ((size_t)((b * 56 + oh * 4) * 56 + ow * 4)) * 256;
    }

    float acc[4][4][4];
    #pragma unroll
    for (int i = 0; i < 4; i++)
        #pragma unroll
        for (int j = 0; j < 4; j++)
            #pragma unroll
            for (int r = 0; r < 4; r++) acc[i][j][r] = 0.f;

    const int KT = 32;
    auto issue = [&](int buf, int k0) {
        float* Ad = Asm + buf * ABUF;
        float* Bd = Bsm + buf * BBUF;
        int kk = kc * 1024 + k0 + c4 * 4;
        int kh = kk >> 10, kw = (kk >> 8) & 3, c = kk & 255;
        int off = (kh * 56 + kw) * 256 + c;
        #pragma unroll
        for (int t = 0; t < 4; t++) {
            int row = (tid >> 3) + t * 32;
            uint32_t d = (uint32_t)__cvta_generic_to_shared(Ad + row * ASTRIDE + c4 * 4);
            CP16(d, px[t] + off);
        }
        #pragma unroll
        for (int t = 0; t < 4; t++) {
            int idx = tid + t * 256;
            int kr = idx >> 5, cc4 = idx & 31;
            uint32_t d = (uint32_t)__cvta_generic_to_shared(Bd + kr * BSTRIDE + cc4 * 4);
            CP16(d, Bm + (size_t)(kc * 1024 + k0 + kr) * N + bcol + cc4 * 4);
        }
        asm volatile("cp.async.commit_group;" ::);
    };

    issue(0, 0);
    int buf = 0;
    for (int kt = 0; kt < KT; kt++) {
        asm volatile("cp.async.wait_group 0;" ::);
        __syncthreads();
        if (kt + 1 < KT) issue(buf ^ 1, (kt + 1) << 5);
        const float* Ad = Asm + buf * ABUF;
        const float* Bd = Bsm + buf * BBUF;
        #pragma unroll
        for (int ks = 0; ks < 4; ks++) {
            const int k = ks * 8;
            uint32_t af[4][4], bf[4][2];
            #pragma unroll
            for (int mi = 0; mi < 4; mi++) {
                int r0 = wm + mi * 16 + lr;
                af[mi][0] = f2tf(Ad[r0 * ASTRIDE + k + lc]);
                af[mi][1] = f2tf(Ad[(r0 + 8) * ASTRIDE + k + lc]);
                af[mi][2] = f2tf(Ad[r0 * ASTRIDE + k + 4 + lc]);
                af[mi][3] = f2tf(Ad[(r0 + 8) * ASTRIDE + k + 4 + lc]);
            }
            #pragma unroll
            for (int nj = 0; nj < 4; nj++) {
                int cc = wn + nj * 8 + lr;
                bf[nj][0] = __float_as_uint(Bd[(k + lc) * BSTRIDE + cc]);
                bf[nj][1] = __float_as_uint(Bd[(k + 4 + lc) * BSTRIDE + cc]);
            }
            #pragma unroll
            for (int mi = 0; mi < 4; mi++)
                #pragma unroll
                for (int nj = 0; nj < 4; nj++)
                    MMA_TF32(acc[mi][nj], af[mi], bf[nj]);
        }
        buf ^= 1;
    }
    #pragma unroll
    for (int mi = 0; mi < 4; mi++) {
        #pragma unroll
        for (int nj = 0; nj < 4; nj++) {
            int r0 = brow + wm + mi * 16 + lr;
            int c0 = bcol + wn + nj * 8 + lc * 2;
            *(float2*)&C[(size_t)r0 * 256 + c0] = make_float2(acc[mi][nj][0], acc[mi][nj][1]);
            *(float2*)&C[(size_t)(r0 + 8) * 256 + c0] = make_float2(acc[mi][nj][2], acc[mi][nj][3]);
        }
    }
}

// ============ proj GEMM with fused concat(x1,x2)+lepe A (rounded in loadA) ============
__global__ __launch_bounds__(256, 2)
void tgemm_proj(const float* __restrict__ x1, const float* __restrict__ x2,
                const float* __restrict__ lepe, const float* __restrict__ Bm,
                const float* __restrict__ bias, float* __restrict__ C) {
    const int N = 256, K = 256;
    extern __shared__ float sm[];
    float* Asm = sm;
    float* Bsm = sm + 2 * ABUF;
    const int tid  = threadIdx.x;
    const int lane = tid & 31;
    const int warp = tid >> 5;
    const int wm = (warp >> 2) * 64;
    const int wn = (warp & 3) * 32;
    const int brow = blockIdx.y * 128;
    const int bcol = blockIdx.x * 128;
    const int lr = lane >> 2;
    const int lc = lane & 3;
    const int c4 = tid & 7;

    float acc[4][4][4];
    #pragma unroll
    for (int i = 0; i < 4; i++)
        #pragma unroll
        for (int j = 0; j < 4; j++)
            #pragma unroll
            for (int r = 0; r < 4; r++) acc[i][j][r] = 0.f;

    auto issueB = [&](int buf, int k0) {
        float* Bd = Bsm + buf * BBUF;
        #pragma unroll
        for (int t = 0; t < 4; t++) {
            int idx = tid + t * 256;
            int kr = idx >> 5, cc4 = idx & 31;
            uint32_t d = (uint32_t)__cvta_generic_to_shared(Bd + kr * BSTRIDE + cc4 * 4);
            CP16(d, Bm + (size_t)(k0 + kr) * N + bcol + cc4 * 4);
        }
        asm volatile("cp.async.commit_group;" ::);
    };
    float4 ra[4];
    auto loadA = [&](int k0) {
        int kk = k0 + c4 * 4;
        #pragma unroll
        for (int t = 0; t < 4; t++) {
            size_t m = (size_t)(brow + (tid >> 3) + t * 32);
            float4 a;
            if (kk < 128) a = *(const float4*)&x1[m * 128 + kk];
            else          a = *(const float4*)&x2[m * 128 + kk - 128];
            float4 l = *(const float4*)&lepe[m * 256 + kk];
            a.x = rndf(a.x + l.x); a.y = rndf(a.y + l.y);
            a.z = rndf(a.z + l.z); a.w = rndf(a.w + l.w);
            ra[t] = a;
        }
    };
    auto storeA = [&](int buf) {
        float* Ad = Asm + buf * ABUF;
        #pragma unroll
        for (int t = 0; t < 4; t++)
            *(float4*)&Ad[((tid >> 3) + t * 32) * ASTRIDE + c4 * 4] = ra[t];
    };

    issueB(0, 0);
    loadA(0);
    int buf = 0;
    const int KT = K >> 5;
    for (int kt = 0; kt < KT; kt++) {
        storeA(buf);
        asm volatile("cp.async.wait_group 0;" ::);
        __syncthreads();
        if (kt + 1 < KT) { issueB(buf ^ 1, (kt + 1) << 5); loadA((kt + 1) << 5); }
        const float* Ad = Asm + buf * ABUF;
        const float* Bd = Bsm + buf * BBUF;
        #pragma unroll
        for (int ks = 0; ks < 4; ks++) {
            const int k = ks * 8;
            uint32_t af[4][4], bf[4][2];
            #pragma unroll
            for (int mi = 0; mi < 4; mi++) {
                int r0 = wm + mi * 16 + lr;
                af[mi][0] = __float_as_uint(Ad[r0 * ASTRIDE + k + lc]);
                af[mi][1] = __float_as_uint(Ad[(r0 + 8) * ASTRIDE + k + lc]);
                af[mi][2] = __float_as_uint(Ad[r0 * ASTRIDE + k + 4 + lc]);
                af[mi][3] = __float_as_uint(Ad[(r0 + 8) * ASTRIDE + k + 4 + lc]);
            }
            #pragma unroll
            for (int nj = 0; nj < 4; nj++) {
                int cc = wn + nj * 8 + lr;
                bf[nj][0] = __float_as_uint(Bd[(k + lc) * BSTRIDE + cc]);
                bf[nj][1] = __float_as_uint(Bd[(k + 4 + lc) * BSTRIDE + cc]);
            }
            #pragma unroll
            for (int mi = 0; mi < 4; mi++)
                #pragma unroll
                for (int nj = 0; nj < 4; nj++)
                    MMA_TF32(acc[mi][nj], af[mi], bf[nj]);
        }
        buf ^= 1;
        __syncthreads();
    }
    #pragma unroll
    for (int mi = 0; mi < 4; mi++) {
        #pragma unroll
        for (int nj = 0; nj < 4; nj++) {
            int r0 = brow + wm + mi * 16 + lr;
            int c0 = bcol + wn + nj * 8 + lc * 2;
            float b0 = bias[c0], b1 = bias[c0 + 1];
            *(float2*)&C[(size_t)r0 * N + c0] = make_float2(acc[mi][nj][0] + b0, acc[mi][nj][1] + b1);
            *(float2*)&C[(size_t)(r0 + 8) * N + c0] = make_float2(acc[mi][nj][2] + b0, acc[mi][nj][3] + b1);
        }
    }
}

// ============ depthwise 3x3, register y-walk ============
__global__ void dwconv3x3(const float* __restrict__ in, const float* __restrict__ w,
                          const float* __restrict__ bias, float* __restrict__ out) {
    int idx = blockIdx.x * 256 + threadIdx.x;
    int c = idx & 255;
    int t = idx >> 8;
    int xx = t % WW, b = t / WW;
    float wt[9];
    #pragma unroll
    for (int i = 0; i < 9; i++) wt[i] = w[i * 256 + c];
    float bz = bias[c];
    const float* base = in + (size_t)b * NTOK * 768 + c;
    float* ob = out + (size_t)b * NTOK * 256 + c;
    bool xl = xx > 0, xr = xx < WW - 1;

    float rA[3] = {0.f, 0.f, 0.f}, rB[3], rC[3];
    {
        const float* rp = base;
        rB[0] = xl ? rp[(xx - 1) * 768] : 0.f;
        rB[1] = rp[xx * 768];
        rB[2] = xr ? rp[(xx + 1) * 768] : 0.f;
    }
    for (int y = 0; y < HH; y++) {
        if (y + 1 < HH) {
            const float* rp = base + (size_t)(y + 1) * WW * 768;
            rC[0] = xl ? rp[(xx - 1) * 768] : 0.f;
            rC[1] = rp[xx * 768];
            rC[2] = xr ? rp[(xx + 1) * 768] : 0.f;
        } else { rC[0] = rC[1] = rC[2] = 0.f; }
        float acc = bz
            + wt[0] * rA[0] + wt[1] * rA[1] + wt[2] * rA[2]
            + wt[3] * rB[0] + wt[4] * rB[1] + wt[5] * rB[2]
            + wt[6] * rC[0] + wt[7] * rC[1] + wt[8] * rC[2];
        ob[(size_t)(y * WW + xx) * 256] = acc;
        rA[0] = rB[0]; rA[1] = rB[1]; rA[2] = rB[2];
        rB[0] = rC[0]; rB[1] = rC[1]; rB[2] = rC[2];
    }
}

// ============ split-K reduce + bias + LayerNorm + GELU (output pre-rounded) ============
__global__ void ln_gelu4(const float* __restrict__ p, const float* __restrict__ srb,
                         const float* __restrict__ g, const float* __restrict__ bb,
                         float* __restrict__ xb) {
    int row = blockIdx.x;
    int tid = threadIdx.x;
    const size_t S = (size_t)M_SR * 256;
    size_t off = (size_t)row * 256 + tid;
    float v = p[off] + p[S + off] + p[2 * S + off] + p[3 * S + off] + srb[tid];
    __shared__ float s1[256], s2[256];
    s1[tid] = v; s2[tid] = v * v;
    __syncthreads();
    for (int o = 128; o; o >>= 1) {
        if (tid < o) { s1[tid] += s1[tid + o]; s2[tid] += s2[tid + o]; }
        __syncthreads();
    }
    float mu  = s1[0] * (1.f / CH);
    float var = s2[0] * (1.f / CH) - mu * mu;
    float tt = (v - mu) * rsqrtf(var + 1e-5f) * g[tid] + bb[tid];
    xb[off] = rndf(0.5f * tt * (1.f + erff(tt * 0.70710678118654752f)));
}

// ============ branch-1 attention (MMA), operands pre-rounded at fill ============
#define A1_SMEM ((14592 + 7200) * 4)   // 87168 B
__global__ __launch_bounds__(256, 2)
void attn1_mma(const float* __restrict__ pack, const float* __restrict__ kv1,
               float* __restrict__ x1) {
    extern __shared__ float sm[];
    float* Qs = sm;
    float* Ks = sm + 2304;
    float* Ss = sm;
    float* Vs = sm + 14592;
    int bh = blockIdx.y, b = bh >> 2, h = bh & 3;
    int q0 = blockIdx.x * 64;
    int tid = threadIdx.x, lane = tid & 31, warp = tid >> 5;
    int lr = lane >> 2, lc = lane & 3;

    for (int e = tid; e < 64 * 8; e += 256) {
        int r = e >> 3, c4 = e & 7;
        float4 v = *(const float4*)&pack[((size_t)b * NTOK + q0 + r) * 768 + 256 + h * 32 + c4 * 4];
        v.x = rndf(v.x); v.y = rndf(v.y); v.z = rndf(v.z); v.w = rndf(v.w);
        *(float4*)&Qs[r * 36 + c4 * 4] = v;
    }
    for (int e = tid; e < 196 * 32; e += 256) {
        int m = e >> 5, dd = e & 31;
        size_t base = ((size_t)b * N1 + m) * 256 + h * 32 + dd;
        Ks[dd * 228 + m] = rndf(kv1[base]);
        Vs[m * 36 + dd]  = rndf(kv1[base + 128]);
    }
    for (int e = tid; e < 32 * 32; e += 256) {
        int k = e >> 5, c = e & 31;
        Ks[k * 228 + 196 + c] = 0.f;
    }
    if (tid < 128) {
        int m = 196 + (tid >> 5), dd = tid & 31;
        Vs[m * 36 + dd] = 0.f;
    }
    __syncthreads();

    // scores S[64,224] = Q @ K^T
    {
        int wm = (warp >> 2) * 32, wn = (warp & 3) * 56;
        float acc[2][7][4];
        #pragma unroll
        for (int i = 0; i < 2; i++)
            #pragma unroll
            for (int j = 0; j < 7; j++)
                #pragma unroll
                for (int r = 0; r < 4; r++) acc[i][j][r] = 0.f;
        #pragma unroll
        for (int ks = 0; ks < 4; ks++) {
            const int k = ks * 8;
            uint32_t af[2][4], bf[7][2];
            #pragma unroll
            for (int mi = 0; mi < 2; mi++) {
                int r0 = wm + mi * 16 + lr;
                af[mi][0] = __float_as_uint(Qs[r0 * 36 + k + lc]);
                af[mi][1] = __float_as_uint(Qs[(r0 + 8) * 36 + k + lc]);
                af[mi][2] = __float_as_uint(Qs[r0 * 36 + k + 4 + lc]);
                af[mi][3] = __float_as_uint(Qs[(r0 + 8) * 36 + k + 4 + lc]);
            }
            #pragma unroll
            for (int nj = 0; nj < 7; nj++) {
                int cc = wn + nj * 8 + lr;
                bf[nj][0] = __float_as_uint(Ks[(k + lc) * 228 + cc]);
                bf[nj][1] = __float_as_uint(Ks[(k + 4 + lc) * 228 + cc]);
            }
            #pragma unroll
            for (int mi = 0; mi < 2; mi++)
                #pragma unroll
                for (int nj = 0; nj < 7; nj++)
                    MMA_TF32(acc[mi][nj], af[mi], bf[nj]);
        }
        __syncthreads();
        #pragma unroll
        for (int mi = 0; mi < 2; mi++)
            #pragma unroll
            for (int nj = 0; nj < 7; nj++) {
                int r0 = wm + mi * 16 + lr;
                int c0 = wn + nj * 8 + lc * 2;
                Ss[r0 * 228 + c0]           = acc[mi][nj][0] * SCALE;
                Ss[r0 * 228 + c0 + 1]       = acc[mi][nj][1] * SCALE;
                Ss[(r0 + 8) * 228 + c0]     = acc[mi][nj][2] * SCALE;
                Ss[(r0 + 8) * 228 + c0 + 1] = acc[mi][nj][3] * SCALE;
            }
    }
    __syncthreads();

    // softmax (P rounded at final store)
    #pragma unroll
    for (int r = 0; r < 8; r++) {
        int row = warp * 8 + r;
        float mx = -1e30f;
        for (int m = lane; m < 196; m += 32) mx = fmaxf(mx, Ss[row * 228 + m]);
        #pragma unroll
        for (int o = 16; o; o >>= 1) mx = fmaxf(mx, __shfl_xor_sync(0xffffffffu, mx, o));
        float sum = 0.f;
        for (int m = lane; m < 196; m += 32) {
            float p = __expf(Ss[row * 228 + m] - mx);
            Ss[row * 228 + m] = p;
            sum += p;
        }
        #pragma unroll
        for (int o = 16; o; o >>= 1) sum += __shfl_xor_sync(0xffffffffu, sum, o);
        float inv = 1.f / sum;
        for (int m = lane; m < 196; m += 32) Ss[row * 228 + m] = rndf(Ss[row * 228 + m] * inv);
    }
    __syncthreads();

    // out = P[64,200] @ V[200,32]
    {
        int wm = (warp >> 1) * 16, wn = (warp & 1) * 16;
        float acc[2][4];
        #pragma unroll
        for (int j = 0; j < 2; j++)
            #pragma unroll
            for (int r = 0; r < 4; r++) acc[j][r] = 0.f;
        #pragma unroll 5
        for (int ks = 0; ks < 25; ks++) {
            const int k = ks * 8;
            uint32_t af[4], bf[2][2];
            af[0] = __float_as_uint(Ss[(wm + lr) * 228 + k + lc]);
            af[1] = __float_as_uint(Ss[(wm + 8 + lr) * 228 + k + lc]);
            af[2] = __float_as_uint(Ss[(wm + lr) * 228 + k + 4 + lc]);
            af[3] = __float_as_uint(Ss[(wm + 8 + lr) * 228 + k + 4 + lc]);
            #pragma unroll
            for (int nj = 0; nj < 2; nj++) {
                int cc = wn + nj * 8 + lr;
                bf[nj][0] = __float_as_uint(Vs[(k + lc) * 36 + cc]);
                bf[nj][1] = __float_as_uint(Vs[(k + 4 + lc) * 36 + cc]);
            }
            MMA_TF32(acc[0], af, bf[0]);
            MMA_TF32(acc[1], af, bf[1]);
        }
        #pragma unroll
        for (int nj = 0; nj < 2; nj++) {
            int r0 = q0 + wm + lr;
            int c0 = wn + nj * 8 + lc * 2;
            *(float2*)&x1[((size_t)b * NTOK + r0) * 128 + h * 32 + c0] =
                make_float2(acc[nj][0], acc[nj][1]);
            *(float2*)&x1[((size_t)b * NTOK + r0 + 8) * 128 + h * 32 + c0] =
                make_float2(acc[nj][2], acc[nj][3]);
        }
    }
}

// ============ branch-2 window attention (MMA), 2 windows/CTA ============
#define A2_WSZ 6496
#define A2_SMEM (2 * A2_WSZ * 4)
__global__ __launch_bounds__(256, 4)
void attn2_mma(const float* __restrict__ pack, float* __restrict__ x2) {
    extern __shared__ float sm[];
    int bh = blockIdx.y, b = bh >> 2, h = bh & 3;
    int tid = threadIdx.x, lane = tid & 31, warp = tid >> 5;
    int wslot = warp >> 2, w4 = warp & 3;
    int lr = lane >> 2, lc = lane & 3;
    int win = blockIdx.x * 2 + wslot;
    int wr = win >> 3, wc = win & 7;
    float* base = sm + wslot * A2_WSZ;
    float* Qs = base;
    float* Kt = base + 2304;
    float* Ss = base;
    float* Vs = base + 4480;
    int wt = tid & 127;

    for (int e = wt; e < 64 * 8; e += 128) {
        int r = e >> 3, c4 = e & 7;
        float4 v = make_float4(0.f, 0.f, 0.f, 0.f);
        if (r < 49) {
            int n = (wr * 7 + r / 7) * 56 + wc * 7 + r % 7;
            v = *(const float4*)&pack[((size_t)b * NTOK + n) * 768 + 384 + h * 32 + c4 * 4];
            v.x = rndf(v.x); v.y = rndf(v.y); v.z = rndf(v.z); v.w = rndf(v.w);
        }
        *(float4*)&Qs[r * 36 + c4 * 4] = v;
    }
    for (int e = wt; e < 56 * 32; e += 128) {
        int m = e >> 5, dd = e & 31;
        float kk = 0.f, vv = 0.f;
        if (m < 49) {
            int n = (wr * 7 + m / 7) * 56 + wc * 7 + m % 7;
            size_t rb = ((size_t)b * NTOK + n) * 768 + 512 + h * 32 + dd;
            kk = rndf(pack[rb]);
            vv = rndf(pack[rb + 128]);
        }
        Kt[dd * 68 + m] = kk;
        Vs[m * 36 + dd] = vv;
    }
    __syncthreads();

    int wm = w4 * 16;
    {
        float acc[7][4];
        #pragma unroll
        for (int j = 0; j < 7; j++)
            #pragma unroll
            for (int r = 0; r < 4; r++) acc[j][r] = 0.f;
        #pragma unroll
        for (int ks = 0; ks < 4; ks++) {
            const int k = ks * 8;
            uint32_t af[4], bf[7][2];
            af[0] = __float_as_uint(Qs[(wm + lr) * 36 + k + lc]);
            af[1] = __float_as_uint(Qs[(wm + 8 + lr) * 36 + k + lc]);
            af[2] = __float_as_uint(Qs[(wm + lr) * 36 + k + 4 + lc]);
            af[3] = __float_as_uint(Qs[(wm + 8 + lr) * 36 + k + 4 + lc]);
            #pragma unroll
            for (int nj = 0; nj < 7; nj++) {
                int cc = nj * 8 + lr;
                bf[nj][0] = __float_as_uint(Kt[(k + lc) * 68 + cc]);
                bf[nj][1] = __float_as_uint(Kt[(k + 4 + lc) * 68 + cc]);
            }
            #pragma unroll
            for (int nj = 0; nj < 7; nj++)
                MMA_TF32(acc[nj], af, bf[nj]);
        }
        __syncthreads();
        #pragma unroll
        for (int nj = 0; nj < 7; nj++) {
            int c0 = nj * 8 + lc * 2;
            Ss[(wm + lr) * 68 + c0]           = acc[nj][0] * SCALE;
            Ss[(wm + lr) * 68 + c0 + 1]       = acc[nj][1] * SCALE;
            Ss[(wm + 8 + lr) * 68 + c0]       = acc[nj][2] * SCALE;
            Ss[(wm + 8 + lr) * 68 + c0 + 1]   = acc[nj][3] * SCALE;
        }
    }
    __syncthreads();

    for (int row = w4; row < 49; row += 4) {
        float mx = -1e30f;
        for (int m = lane; m < 49; m += 32) mx = fmaxf(mx, Ss[row * 68 + m]);
        #pragma unroll
        for (int o = 16; o; o >>= 1) mx = fmaxf(mx, __shfl_xor_sync(0xffffffffu, mx, o));
        float sum = 0.f;
        for (int m = lane; m < 49; m += 32) {
            float p = __expf(Ss[row * 68 + m] - mx);
            Ss[row * 68 + m] = p;
            sum += p;
        }
        #pragma unroll
        for (int o = 16; o; o >>= 1) sum += __shfl_xor_sync(0xffffffffu, sum, o);
        float inv = 1.f / sum;
        for (int m = lane; m < 49; m += 32) Ss[row * 68 + m] = rndf(Ss[row * 68 + m] * inv);
    }
    __syncthreads();

    {
        float acc[4][4];
        #pragma unroll
        for (int j = 0; j < 4; j++)
            #pragma unroll
            for (int r = 0; r < 4; r++) acc[j][r] = 0.f;
        #pragma unroll
        for (int ks = 0; ks < 7; ks++) {
            const int k = ks * 8;
            uint32_t af[4], bf[4][2];
            af[0] = __float_as_uint(Ss[(wm + lr) * 68 + k + lc]);
            af[1] = __float_as_uint(Ss[(wm + 8 + lr) * 68 + k + lc]);
            af[2] = __float_as_uint(Ss[(wm + lr) * 68 + k + 4 + lc]);
            af[3] = __float_as_uint(Ss[(wm + 8 + lr) * 68 + k + 4 + lc]);
            #pragma unroll
            for (int nj = 0; nj < 4; nj++) {
                int cc = nj * 8 + lr;
                bf[nj][0] = __float_as_uint(Vs[(k + lc) * 36 + cc]);
                bf[nj][1] = __float_as_uint(Vs[(k + 4 + lc) * 36 + cc]);
            }
            #pragma unroll
            for (int nj = 0; nj < 4; nj++)
                MMA_TF32(acc[nj], af, bf[nj]);
        }
        int r1 = wm + lr, r2 = wm + 8 + lr;
        #pragma unroll
        for (int nj = 0; nj < 4; nj++) {
            int c0 = nj * 8 + lc * 2;
            if (r1 < 49) {
                int n = (wr * 7 + r1 / 7) * 56 + wc * 7 + r1 % 7;
                *(float2*)&x2[((size_t)b * NTOK + n) * 128 + h * 32 + c0] =
                    make_float2(acc[nj][0], acc[nj][1]);
            }
            if (r2 < 49) {
                int n = (wr * 7 + r2 / 7) * 56 + wc * 7 + r2 % 7;
                *(float2*)&x2[((size_t)b * NTOK + n) * 128 + h * 32 + c0] =
                    make_float2(acc[nj][2], acc[nj][3]);
            }
        }
    }
}

// ---------------- host launch (fork/join streams inside capture) ----------------
extern "C" void kernel_launch(void* const* d_in, const int* in_sizes, int n_in,
                              void* d_out, int out_size) {
    const float* x           = (const float*)d_in[0];
    const float* lepe_lin_w  = (const float*)d_in[1];
    const float* lepe_lin_b  = (const float*)d_in[2];
    const float* lepe_conv_w = (const float*)d_in[3];
    const float* lepe_conv_b = (const float*)d_in[4];
    const float* sr_w        = (const float*)d_in[5];
    const float* sr_b        = (const float*)d_in[6];
    const float* norm_g      = (const float*)d_in[7];
    const float* norm_b      = (const float*)d_in[8];
    const float* q1_w        = (const float*)d_in[9];
    const float* kv1_w       = (const float*)d_in[10];
    const float* q2_w        = (const float*)d_in[11];
    const float* kv2_w       = (const float*)d_in[12];
    const float* proj_w      = (const float*)d_in[13];
    const float* proj_b      = (const float*)d_in[14];
    float* out = (float*)d_out;

    float *pack, *lepe, *wpack, *bpack, *srw, *kv1w, *projw, *srp, *x1s, *kv1, *x1, *x2;
    cudaGetSymbolAddress((void**)&pack,  g_pack);
    cudaGetSymbolAddress((void**)&lepe,  g_lepe);
    cudaGetSymbolAddress((void**)&wpack, g_wpack);
    cudaGetSymbolAddress((void**)&bpack, g_bpack);
    cudaGetSymbolAddress((void**)&srw,   g_srw);
    cudaGetSymbolAddress((void**)&kv1w,  g_kv1w);
    cudaGetSymbolAddress((void**)&projw, g_projw);
    cudaGetSymbolAddress((void**)&srp,   g_srp);
    cudaGetSymbolAddress((void**)&x1s,   g_x1s);
    cudaGetSymbolAddress((void**)&kv1,   g_kv1);
    cudaGetSymbolAddress((void**)&x1,    g_x1);
    cudaGetSymbolAddress((void**)&x2,    g_x2);

    cudaFuncSetAttribute(tgemm128<true,false>,  cudaFuncAttributeMaxDynamicSharedMemorySize, TG_SMEM);
    cudaFuncSetAttribute(tgemm128<false,false>, cudaFuncAttributeMaxDynamicSharedMemorySize, TG_SMEM);
    cudaFuncSetAttribute(tgemm_sr_split, cudaFuncAttributeMaxDynamicSharedMemorySize, TG_SMEM);
    cudaFuncSetAttribute(tgemm_proj,     cudaFuncAttributeMaxDynamicSharedMemorySize, TG_SMEM);
    cudaFuncSetAttribute(attn1_mma,      cudaFuncAttributeMaxDynamicSharedMemorySize, A1_SMEM);
    cudaFuncSetAttribute(attn2_mma,      cudaFuncAttributeMaxDynamicSharedMemorySize, A2_SMEM);

    // side stream + events, created once (outside any capture), reused every call
    static cudaStream_t s1 = nullptr;
    static cudaEvent_t evF = nullptr, evP = nullptr, evJ = nullptr;
    if (!s1) {
        cudaStreamCreateWithFlags(&s1, cudaStreamNonBlocking);
        cudaEventCreateWithFlags(&evF, cudaEventDisableTiming);
        cudaEventCreateWithFlags(&evP, cudaEventDisableTiming);
        cudaEventCreateWithFlags(&evJ, cudaEventDisableTiming);
    }

    // weight prep on main stream
    pack_weights<<<768, 256>>>(lepe_lin_w, lepe_lin_b, q1_w, q2_w, kv2_w, wpack, bpack);
    round_weights<<<4096, 256>>>(sr_w, kv1_w, proj_w, srw, kv1w, projw);

    // fork: sr chain on s1 (independent of pack until attn1)
    cudaEventRecord(evF, 0);
    cudaStreamWaitEvent(s1, evF, 0);
    tgemm_sr_split<<<dim3(2, M_SR / 128, 4), 256, TG_SMEM, s1>>>(x, srw, srp);
    ln_gelu4<<<M_SR, 256, 0, s1>>>(srp, sr_b, norm_g, norm_b, x1s);
    tgemm128<false,false><<<dim3(2, M_SR / 128), 256, TG_SMEM, s1>>>(x1s, kv1w, nullptr, kv1, M_SR, 256, 256);

    // main stream: merged projection GEMM, then its consumers
    tgemm128<true,false><<<dim3(6, M_ALL / 128), 256, TG_SMEM>>>(x, wpack, bpack, pack, M_ALL, 768, 256);
    cudaEventRecord(evP, 0);
    dwconv3x3<<<(BATCH * WW * CH) / 256, 256>>>(pack, lepe_conv_w, lepe_conv_b, lepe);
    attn2_mma<<<dim3(32, BATCH * H2), 256, A2_SMEM>>>(pack, x2);

    // attn1 on s1 after pack is ready
    cudaStreamWaitEvent(s1, evP, 0);
    attn1_mma<<<dim3(NTOK / 64, BATCH * H2), 256, A1_SMEM, s1>>>(pack, kv1, x1);
    cudaEventRecord(evJ, s1);

    // join + final projection
    cudaStreamWaitEvent(0, evJ, 0);
    tgemm_proj<<<dim3(2, M_ALL / 128), 256, TG_SMEM>>>(x1, x2, lepe, projw, proj_b, out);
}

// round 7
// speedup vs baseline: 3.9034x; 1.1627x over previous
#include <cuda_runtime.h>
#include <cuda_fp16.h>
#include <cstdint>

#define BATCH 32
#define HH 56
#define WW 56
#define NTOK (HH*WW)            // 3136
#define CH 256
#define H2 4
#define M_ALL (BATCH*NTOK)      // 100352
#define N1 196
#define M_SR (BATCH*N1)         // 6272
#define SCALE 0.17677669529663687f

// ---------------- scratch ----------------
__device__ __half g_xh    [(size_t)M_ALL*256];
__device__ __half g_wpackT[(size_t)768*256];
__device__ float  g_bpack [768];
__device__ __half g_srwT  [(size_t)256*4096];
__device__ __half g_kv1wT [(size_t)256*256];
__device__ __half g_projwT[(size_t)256*256];
__device__ float  g_pack  [(size_t)M_ALL*768];   // [lepe_lin | q1 | q2 | kv2]
__device__ float  g_lepe  [(size_t)M_ALL*CH];
__device__ float  g_srp   [(size_t)4*M_SR*CH];
__device__ __half g_x1s   [(size_t)M_SR*CH];
__device__ float  g_kv1   [(size_t)M_SR*CH];
__device__ float  g_x1    [(size_t)M_ALL*128];
__device__ float  g_x2    [(size_t)M_ALL*128];

// ---------------- helpers ----------------
__device__ __forceinline__ uint32_t f2tf(float f) {
    uint32_t u;
    asm("cvt.rna.tf32.f32 %0, %1;" : "=r"(u) : "f"(f));
    return u;
}
__device__ __forceinline__ float rndf(float f) { return __uint_as_float(f2tf(f)); }
#define CP16(dst, src) \
    asm volatile("cp.async.cg.shared.global [%0], [%1], 16;" :: "r"(dst), "l"(src))
#define MMA_TF32(c, a, b) \
    asm volatile("mma.sync.aligned.m16n8k8.row.col.f32.tf32.tf32.f32 " \
                 "{%0,%1,%2,%3},{%4,%5,%6,%7},{%8,%9},{%0,%1,%2,%3};" \
                 : "+f"((c)[0]), "+f"((c)[1]), "+f"((c)[2]), "+f"((c)[3]) \
                 : "r"((a)[0]), "r"((a)[1]), "r"((a)[2]), "r"((a)[3]), \
                   "r"((b)[0]), "r"((b)[1]))
#define MMA_F16(c, a, b) \
    asm volatile("mma.sync.aligned.m16n8k16.row.col.f32.f16.f16.f32 " \
                 "{%0,%1,%2,%3},{%4,%5,%6,%7},{%8,%9},{%0,%1,%2,%3};" \
                 : "+f"((c)[0]), "+f"((c)[1]), "+f"((c)[2]), "+f"((c)[3]) \
                 : "r"((a)[0]), "r"((a)[1]), "r"((a)[2]), "r"((a)[3]), \
                   "r"((b)[0]), "r"((b)[1]))

// fp16 GEMM tile constants: A and B smem tiles both [128][40] halves
#define HSTR 40
#define HBUF (128*HSTR)                 // 5120 halves = 10240 B
#define TH_SMEM (4*HBUF*2)              // 40960 B

// ============ prep kernels ============
__global__ void cvt_x(const float* __restrict__ x, __half* __restrict__ xh) {
    size_t i = (size_t)blockIdx.x * 256 + threadIdx.x;   // one float4 per thread
    float4 v = ((const float4*)x)[i];
    __half2* o = (__half2*)xh;
    o[2 * i]     = __floats2half2_rn(v.x, v.y);
    o[2 * i + 1] = __floats2half2_rn(v.z, v.w);
}

__global__ void pack_weightsT(const float* __restrict__ lw, const float* __restrict__ lb,
                              const float* __restrict__ q1w, const float* __restrict__ q2w,
                              const float* __restrict__ kvw,
                              __half* __restrict__ wt, float* __restrict__ bp) {
    int idx = blockIdx.x * 256 + threadIdx.x;   // 768*256
    if (idx < 768) bp[idx] = (idx < 256) ? lb[idx] : 0.f;
    if (idx >= 768 * 256) return;
    int c = idx >> 8, k = idx & 255;
    float v;
    if (c < 256)      v = lw[k * 256 + c];
    else if (c < 384) v = q1w[k * 128 + (c - 256)];
    else if (c < 512) v = q2w[k * 128 + (c - 384)];
    else              v = kvw[k * 256 + (c - 512)];
    wt[idx] = __float2half_rn(v);   // wt[c][k]
}

__global__ void roundT(const float* __restrict__ sw, const float* __restrict__ kw,
                       const float* __restrict__ pw,
                       __half* __restrict__ st, __half* __restrict__ kt,
                       __half* __restrict__ pt) {
    int i = blockIdx.x * 256 + threadIdx.x;
    if (i < 256 * 4096) {
        int c = i >> 12, k = i & 4095;
        st[i] = __float2half_rn(sw[k * 256 + c]);
    }
    if (i < 256 * 256) {
        int c = i >> 8, k = i & 255;
        kt[i] = __float2half_rn(kw[k * 256 + c]);
        pt[i] = __float2half_rn(pw[k * 256 + c]);
    }
}

// ============ fp16 GEMM: C[M,N] = A[M,K] @ Bt[N,K]^T (+bias) ============
// 128x128 tile, BK=32, 256 threads, warps 2x4 (64x32), m16n8k16.
__global__ __launch_bounds__(256, 2)
void tgemm_h(const __half* __restrict__ A, const __half* __restrict__ Bt,
             const float* __restrict__ bias, float* __restrict__ C,
             int M, int N, int K) {
    extern __shared__ __half hs[];
    const int tid  = threadIdx.x;
    const int lane = tid & 31;
    const int warp = tid >> 5;
    const int wm = (warp >> 2) * 64;
    const int wn = (warp & 3) * 32;
    const int brow = blockIdx.y * 128;
    const int bcol = blockIdx.x * 128;
    const int lr = lane >> 2;
    const int lc = lane & 3;
    const int arow = tid >> 2;      // 0..63 (+64 for second)
    const int c16 = tid & 3;        // 16B chunk within row (8 halves)

    float acc[4][4][4];
    #pragma unroll
    for (int i = 0; i < 4; i++)
        #pragma unroll
        for (int j = 0; j < 4; j++)
            #pragma unroll
            for (int r = 0; r < 4; r++) acc[i][j][r] = 0.f;

    const int KT = K >> 5;
    auto issue = [&](int buf, int k0) {
        __half* Ad = hs + buf * HBUF;
        __half* Bd = hs + 2 * HBUF + buf * HBUF;
        #pragma unroll
        for (int i = 0; i < 2; i++) {
            int row = arow + i * 64;
            uint32_t d = (uint32_t)__cvta_generic_to_shared(Ad + row * HSTR + c16 * 8);
            CP16(d, A + (size_t)(brow + row) * K + k0 + c16 * 8);
        }
        #pragma unroll
        for (int i = 0; i < 2; i++) {
            int row = arow + i * 64;
            uint32_t d = (uint32_t)__cvta_generic_to_shared(Bd + row * HSTR + c16 * 8);
            CP16(d, Bt + (size_t)(bcol + row) * K + k0 + c16 * 8);
        }
        asm volatile("cp.async.commit_group;" ::);
    };

    issue(0, 0);
    int buf = 0;
    for (int kt = 0; kt < KT; kt++) {
        asm volatile("cp.async.wait_group 0;" ::);
        __syncthreads();
        if (kt + 1 < KT) issue(buf ^ 1, (kt + 1) << 5);
        const __half* Ad = hs + buf * HBUF;
        const __half* Bd = hs + 2 * HBUF + buf * HBUF;
        #pragma unroll
        for (int ks = 0; ks < 2; ks++) {
            const int kb = ks * 16 + 2 * lc;
            uint32_t af[4][4], bf[4][2];
            #pragma unroll
            for (int mi = 0; mi < 4; mi++) {
                int r0 = wm + mi * 16 + lr;
                af[mi][0] = *(const uint32_t*)(Ad + r0 * HSTR + kb);
                af[mi][1] = *(const uint32_t*)(Ad + (r0 + 8) * HSTR + kb);
                af[mi][2] = *(const uint32_t*)(Ad + r0 * HSTR + kb + 8);
                af[mi][3] = *(const uint32_t*)(Ad + (r0 + 8) * HSTR + kb + 8);
            }
            #pragma unroll
            for (int nj = 0; nj < 4; nj++) {
                int cc = wn + nj * 8 + lr;
                bf[nj][0] = *(const uint32_t*)(Bd + cc * HSTR + kb);
                bf[nj][1] = *(const uint32_t*)(Bd + cc * HSTR + kb + 8);
            }
            #pragma unroll
            for (int mi = 0; mi < 4; mi++)
                #pragma unroll
                for (int nj = 0; nj < 4; nj++)
                    MMA_F16(acc[mi][nj], af[mi], bf[nj]);
        }
        buf ^= 1;
    }
    #pragma unroll
    for (int mi = 0; mi < 4; mi++) {
        #pragma unroll
        for (int nj = 0; nj < 4; nj++) {
            int r0 = brow + wm + mi * 16 + lr;
            int c0 = bcol + wn + nj * 8 + lc * 2;
            float b0 = 0.f, b1 = 0.f;
            if (bias) { b0 = bias[c0]; b1 = bias[c0 + 1]; }
            *(float2*)&C[(size_t)r0 * N + c0] = make_float2(acc[mi][nj][0] + b0, acc[mi][nj][1] + b1);
            *(float2*)&C[(size_t)(r0 + 8) * N + c0] = make_float2(acc[mi][nj][2] + b0, acc[mi][nj][3] + b1);
        }
    }
}

// ============ fp16 sr-conv GEMM, fused im2col over xh, split-K x4 ============
__global__ __launch_bounds__(256, 2)
void tgemm_sr_h(const __half* __restrict__ xh, const __half* __restrict__ Bt,
                float* __restrict__ Cp) {
    const int kc = blockIdx.z;
    float* C = Cp + (size_t)kc * M_SR * 256;
    extern __shared__ __half hs[];
    const int tid  = threadIdx.x;
    const int lane = tid & 31;
    const int warp = tid >> 5;
    const int wm = (warp >> 2) * 64;
    const int wn = (warp & 3) * 32;
    const int brow = blockIdx.y * 128;
    const int bcol = blockIdx.x * 128;
    const int lr = lane >> 2;
    const int lc = lane & 3;
    const int arow = tid >> 2;
    const int c16 = tid & 3;

    const __half* px[2];
    #pragma unroll
    for (int i = 0; i < 2; i++) {
        int m = brow + arow + i * 64;
        int b = m / 196, rem = m % 196;
        int oh = rem / 14, ow = rem % 14;
        px[i] = xh + ((size_t)((b * 56 + oh * 4) * 56 + ow * 4)) * 256;
    }

    float acc[4][4][4];
    #pragma unroll
    for (int i = 0; i < 4; i++)
        #pragma unroll
        for (int j = 0; j < 4; j++)
            #pragma unroll
            for (int r = 0; r < 4; r++) acc[i][j][r] = 0.f;

    const int KT = 32;   // 1024/32
    auto issue = [&](int buf, int k0) {
        __half* Ad = hs + buf * HBUF;
        __half* Bd = hs + 2 * HBUF + buf * HBUF;
        int kk = kc * 1024 + k0 + c16 * 8;
        int kh = kk >> 10, kw = (kk >> 8) & 3, c = kk & 255;
        int off = (kh * 56 + kw) * 256 + c;
        #pragma unroll
        for (int i = 0; i < 2; i++) {
            int row = arow + i * 64;
            uint32_t d = (uint32_t)__cvta_generic_to_shared(Ad + row * HSTR + c16 * 8);
            CP16(d, px[i] + off);
        }
        #pragma unroll
        for (int i = 0; i < 2; i++) {
            int row = arow + i * 64;
            uint32_t d = (uint32_t)__cvta_generic_to_shared(Bd + row * HSTR + c16 * 8);
            CP16(d, Bt + (size_t)(bcol + row) * 4096 + kc * 1024 + k0 + c16 * 8);
        }
        asm volatile("cp.async.commit_group;" ::);
    };

    issue(0, 0);
    int buf = 0;
    for (int kt = 0; kt < KT; kt++) {
        asm volatile("cp.async.wait_group 0;" ::);
        __syncthreads();
        if (kt + 1 < KT) issue(buf ^ 1, (kt + 1) << 5);
        const __half* Ad = hs + buf * HBUF;
        const __half* Bd = hs + 2 * HBUF + buf * HBUF;
        #pragma unroll
        for (int ks = 0; ks < 2; ks++) {
            const int kb = ks * 16 + 2 * lc;
            uint32_t af[4][4], bf[4][2];
            #pragma unroll
            for (int mi = 0; mi < 4; mi++) {
                int r0 = wm + mi * 16 + lr;
                af[mi][0] = *(const uint32_t*)(Ad + r0 * HSTR + kb);
                af[mi][1] = *(const uint32_t*)(Ad + (r0 + 8) * HSTR + kb);
                af[mi][2] = *(const uint32_t*)(Ad + r0 * HSTR + kb + 8);
                af[mi][3] = *(const uint32_t*)(Ad + (r0 + 8) * HSTR + kb + 8);
            }
            #pragma unroll
            for (int nj = 0; nj < 4; nj++) {
                int cc = wn + nj * 8 + lr;
                bf[nj][0] = *(const uint32_t*)(Bd + cc * HSTR + kb);
                bf[nj][1] = *(const uint32_t*)(Bd + cc * HSTR + kb + 8);
            }
            #pragma unroll
            for (int mi = 0; mi < 4; mi++)
                #pragma unroll
                for (int nj = 0; nj < 4; nj++)
                    MMA_F16(acc[mi][nj], af[mi], bf[nj]);
        }
        buf ^= 1;
    }
    #pragma unroll
    for (int mi = 0; mi < 4; mi++) {
        #pragma unroll
        for (int nj = 0; nj < 4; nj++) {
            int r0 = brow + wm + mi * 16 + lr;
            int c0 = bcol + wn + nj * 8 + lc * 2;
            *(float2*)&C[(size_t)r0 * 256 + c0] = make_float2(acc[mi][nj][0], acc[mi][nj][1]);
            *(float2*)&C[(size_t)(r0 + 8) * 256 + c0] = make_float2(acc[mi][nj][2], acc[mi][nj][3]);
        }
    }
}

// ============ fp16 proj GEMM with fused concat(x1,x2)+lepe ============
__global__ __launch_bounds__(256, 2)
void tgemm_proj_h(const float* __restrict__ x1, const float* __restrict__ x2,
                  const float* __restrict__ lepe, const __half* __restrict__ Bt,
                  const float* __restrict__ bias, float* __restrict__ C) {
    const int N = 256, K = 256;
    extern __shared__ __half hs[];
    const int tid  = threadIdx.x;
    const int lane = tid & 31;
    const int warp = tid >> 5;
    const int wm = (warp >> 2) * 64;
    const int wn = (warp & 3) * 32;
    const int brow = blockIdx.y * 128;
    const int bcol = blockIdx.x * 128;
    const int lr = lane >> 2;
    const int lc = lane & 3;
    const int arow = tid >> 2;
    const int c16 = tid & 3;

    float acc[4][4][4];
    #pragma unroll
    for (int i = 0; i < 4; i++)
        #pragma unroll
        for (int j = 0; j < 4; j++)
            #pragma unroll
            for (int r = 0; r < 4; r++) acc[i][j][r] = 0.f;

    auto issueB = [&](int buf, int k0) {
        __half* Bd = hs + 2 * HBUF + buf * HBUF;
        #pragma unroll
        for (int i = 0; i < 2; i++) {
            int row = arow + i * 64;
            uint32_t d = (uint32_t)__cvta_generic_to_shared(Bd + row * HSTR + c16 * 8);
            CP16(d, Bt + (size_t)(bcol + row) * K + k0 + c16 * 8);
        }
        asm volatile("cp.async.commit_group;" ::);
    };

    uint2 ra[2], raHi[2];   // 16 halves = this thread's two 16B A chunks
    auto loadA = [&](int k0) {
        int kk = k0 + c16 * 8;
        #pragma unroll
        for (int i = 0; i < 2; i++) {
            size_t m = (size_t)(brow + arow + i * 64);
            float4 a0, a1;
            if (kk < 128) {
                a0 = *(const float4*)&x1[m * 128 + kk];
                a1 = *(const float4*)&x1[m * 128 + kk + 4];
            } else {
                a0 = *(const float4*)&x2[m * 128 + kk - 128];
                a1 = *(const float4*)&x2[m * 128 + kk - 124];
            }
            float4 l0 = *(const float4*)&lepe[m * 256 + kk];
            float4 l1 = *(const float4*)&lepe[m * 256 + kk + 4];
            __half2 h0 = __floats2half2_rn(a0.x + l0.x, a0.y + l0.y);
            __half2 h1 = __floats2half2_rn(a0.z + l0.z, a0.w + l0.w);
            __half2 h2 = __floats2half2_rn(a1.x + l1.x, a1.y + l1.y);
            __half2 h3 = __floats2half2_rn(a1.z + l1.z, a1.w + l1.w);
            ra[i].x = *(uint32_t*)&h0;  ra[i].y = *(uint32_t*)&h1;
            raHi[i].x = *(uint32_t*)&h2; raHi[i].y = *(uint32_t*)&h3;
        }
    };
    auto storeA = [&](int buf) {
        __half* Ad = hs + buf * HBUF;
        #pragma unroll
        for (int i = 0; i < 2; i++) {
            uint4 v; v.x = ra[i].x; v.y = ra[i].y; v.z = raHi[i].x; v.w = raHi[i].y;
            *(uint4*)(Ad + (arow + i * 64) * HSTR + c16 * 8) = v;
        }
    };

    issueB(0, 0);
    loadA(0);
    int buf = 0;
    const int KT = K >> 5;   // 8
    for (int kt = 0; kt < KT; kt++) {
        storeA(buf);
        asm volatile("cp.async.wait_group 0;" ::);
        __syncthreads();
        if (kt + 1 < KT) { issueB(buf ^ 1, (kt + 1) << 5); loadA((kt + 1) << 5); }
        const __half* Ad = hs + buf * HBUF;
        const __half* Bd = hs + 2 * HBUF + buf * HBUF;
        #pragma unroll
        for (int ks = 0; ks < 2; ks++) {
            const int kb = ks * 16 + 2 * lc;
            uint32_t af[4][4], bf[4][2];
            #pragma unroll
            for (int mi = 0; mi < 4; mi++) {
                int r0 = wm + mi * 16 + lr;
                af[mi][0] = *(const uint32_t*)(Ad + r0 * HSTR + kb);
                af[mi][1] = *(const uint32_t*)(Ad + (r0 + 8) * HSTR + kb);
                af[mi][2] = *(const uint32_t*)(Ad + r0 * HSTR + kb + 8);
                af[mi][3] = *(const uint32_t*)(Ad + (r0 + 8) * HSTR + kb + 8);
            }
            #pragma unroll
            for (int nj = 0; nj < 4; nj++) {
                int cc = wn + nj * 8 + lr;
                bf[nj][0] = *(const uint32_t*)(Bd + cc * HSTR + kb);
                bf[nj][1] = *(const uint32_t*)(Bd + cc * HSTR + kb + 8);
            }
            #pragma unroll
            for (int mi = 0; mi < 4; mi++)
                #pragma unroll
                for (int nj = 0; nj < 4; nj++)
                    MMA_F16(acc[mi][nj], af[mi], bf[nj]);
        }
        buf ^= 1;
        __syncthreads();   // protect Asm[buf] reuse before next storeA
    }
    #pragma unroll
    for (int mi = 0; mi < 4; mi++) {
        #pragma unroll
        for (int nj = 0; nj < 4; nj++) {
            int r0 = brow + wm + mi * 16 + lr;
            int c0 = bcol + wn + nj * 8 + lc * 2;
            float b0 = bias[c0], b1 = bias[c0 + 1];
            *(float2*)&C[(size_t)r0 * N + c0] = make_float2(acc[mi][nj][0] + b0, acc[mi][nj][1] + b1);
            *(float2*)&C[(size_t)(r0 + 8) * N + c0] = make_float2(acc[mi][nj][2] + b0, acc[mi][nj][3] + b1);
        }
    }
}

// ============ depthwise 3x3, register y-walk ============
__global__ void dwconv3x3(const float* __restrict__ in, const float* __restrict__ w,
                          const float* __restrict__ bias, float* __restrict__ out) {
    int idx = blockIdx.x * 256 + threadIdx.x;
    int c = idx & 255;
    int t = idx >> 8;
    int xx = t % WW, b = t / WW;
    float wt[9];
    #pragma unroll
    for (int i = 0; i < 9; i++) wt[i] = w[i * 256 + c];
    float bz = bias[c];
    const float* base = in + (size_t)b * NTOK * 768 + c;
    float* ob = out + (size_t)b * NTOK * 256 + c;
    bool xl = xx > 0, xr = xx < WW - 1;

    float rA[3] = {0.f, 0.f, 0.f}, rB[3], rC[3];
    {
        const float* rp = base;
        rB[0] = xl ? rp[(xx - 1) * 768] : 0.f;
        rB[1] = rp[xx * 768];
        rB[2] = xr ? rp[(xx + 1) * 768] : 0.f;
    }
    for (int y = 0; y < HH; y++) {
        if (y + 1 < HH) {
            const float* rp = base + (size_t)(y + 1) * WW * 768;
            rC[0] = xl ? rp[(xx - 1) * 768] : 0.f;
            rC[1] = rp[xx * 768];
            rC[2] = xr ? rp[(xx + 1) * 768] : 0.f;
        } else { rC[0] = rC[1] = rC[2] = 0.f; }
        float acc = bz
            + wt[0] * rA[0] + wt[1] * rA[1] + wt[2] * rA[2]
            + wt[3] * rB[0] + wt[4] * rB[1] + wt[5] * rB[2]
            + wt[6] * rC[0] + wt[7] * rC[1] + wt[8] * rC[2];
        ob[(size_t)(y * WW + xx) * 256] = acc;
        rA[0] = rB[0]; rA[1] = rB[1]; rA[2] = rB[2];
        rB[0] = rC[0]; rB[1] = rC[1]; rB[2] = rC[2];
    }
}

// ============ split-K reduce + bias + LayerNorm + GELU -> half ============
__global__ void ln_gelu4(const float* __restrict__ p, const float* __restrict__ srb,
                         const float* __restrict__ g, const float* __restrict__ bb,
                         __half* __restrict__ xb) {
    int row = blockIdx.x;
    int tid = threadIdx.x;
    const size_t S = (size_t)M_SR * 256;
    size_t off = (size_t)row * 256 + tid;
    float v = p[off] + p[S + off] + p[2 * S + off] + p[3 * S + off] + srb[tid];
    __shared__ float s1[256], s2[256];
    s1[tid] = v; s2[tid] = v * v;
    __syncthreads();
    for (int o = 128; o; o >>= 1) {
        if (tid < o) { s1[tid] += s1[tid + o]; s2[tid] += s2[tid + o]; }
        __syncthreads();
    }
    float mu  = s1[0] * (1.f / CH);
    float var = s2[0] * (1.f / CH) - mu * mu;
    float tt = (v - mu) * rsqrtf(var + 1e-5f) * g[tid] + bb[tid];
    xb[off] = __float2half_rn(0.5f * tt * (1.f + erff(tt * 0.70710678118654752f)));
}

// ============ branch-1 attention (tf32 MMA) ============
#define A1_SMEM ((14592 + 7200) * 4)   // 87168 B
__global__ __launch_bounds__(256, 2)
void attn1_mma(const float* __restrict__ pack, const float* __restrict__ kv1,
               float* __restrict__ x1) {
    extern __shared__ float sm[];
    float* Qs = sm;
    float* Ks = sm + 2304;
    float* Ss = sm;
    float* Vs = sm + 14592;
    int bh = blockIdx.y, b = bh >> 2, h = bh & 3;
    int q0 = blockIdx.x * 64;
    int tid = threadIdx.x, lane = tid & 31, warp = tid >> 5;
    int lr = lane >> 2, lc = lane & 3;

    for (int e = tid; e < 64 * 8; e += 256) {
        int r = e >> 3, c4 = e & 7;
        float4 v = *(const float4*)&pack[((size_t)b * NTOK + q0 + r) * 768 + 256 + h * 32 + c4 * 4];
        v.x = rndf(v.x); v.y = rndf(v.y); v.z = rndf(v.z); v.w = rndf(v.w);
        *(float4*)&Qs[r * 36 + c4 * 4] = v;
    }
    for (int e = tid; e < 196 * 32; e += 256) {
        int m = e >> 5, dd = e & 31;
        size_t base = ((size_t)b * N1 + m) * 256 + h * 32 + dd;
        Ks[dd * 228 + m] = rndf(kv1[base]);
        Vs[m * 36 + dd]  = rndf(kv1[base + 128]);
    }
    for (int e = tid; e < 32 * 32; e += 256) {
        int k = e >> 5, c = e & 31;
        Ks[k * 228 + 196 + c] = 0.f;
    }
    if (tid < 128) {
        int m = 196 + (tid >> 5), dd = tid & 31;
        Vs[m * 36 + dd] = 0.f;
    }
    __syncthreads();

    {
        int wm = (warp >> 2) * 32, wn = (warp & 3) * 56;
        float acc[2][7][4];
        #pragma unroll
        for (int i = 0; i < 2; i++)
            #pragma unroll
            for (int j = 0; j < 7; j++)
                #pragma unroll
                for (int r = 0; r < 4; r++) acc[i][j][r] = 0.f;
        #pragma unroll
        for (int ks = 0; ks < 4; ks++) {
            const int k = ks * 8;
            uint32_t af[2][4], bf[7][2];
            #pragma unroll
            for (int mi = 0; mi < 2; mi++) {
                int r0 = wm + mi * 16 + lr;
                af[mi][0] = __float_as_uint(Qs[r0 * 36 + k + lc]);
                af[mi][1] = __float_as_uint(Qs[(r0 + 8) * 36 + k + lc]);
                af[mi][2] = __float_as_uint(Qs[r0 * 36 + k + 4 + lc]);
                af[mi][3] = __float_as_uint(Qs[(r0 + 8) * 36 + k + 4 + lc]);
            }
            #pragma unroll
            for (int nj = 0; nj < 7; nj++) {
                int cc = wn + nj * 8 + lr;
                bf[nj][0] = __float_as_uint(Ks[(k + lc) * 228 + cc]);
                bf[nj][1] = __float_as_uint(Ks[(k + 4 + lc) * 228 + cc]);
            }
            #pragma unroll
            for (int mi = 0; mi < 2; mi++)
                #pragma unroll
                for (int nj = 0; nj < 7; nj++)
                    MMA_TF32(acc[mi][nj], af[mi], bf[nj]);
        }
        __syncthreads();
        #pragma unroll
        for (int mi = 0; mi < 2; mi++)
            #pragma unroll
            for (int nj = 0; nj < 7; nj++) {
                int r0 = wm + mi * 16 + lr;
                int c0 = wn + nj * 8 + lc * 2;
                Ss[r0 * 228 + c0]           = acc[mi][nj][0] * SCALE;
                Ss[r0 * 228 + c0 + 1]       = acc[mi][nj][1] * SCALE;
                Ss[(r0 + 8) * 228 + c0]     = acc[mi][nj][2] * SCALE;
                Ss[(r0 + 8) * 228 + c0 + 1] = acc[mi][nj][3] * SCALE;
            }
    }
    __syncthreads();

    #pragma unroll
    for (int r = 0; r < 8; r++) {
        int row = warp * 8 + r;
        float mx = -1e30f;
        for (int m = lane; m < 196; m += 32) mx = fmaxf(mx, Ss[row * 228 + m]);
        #pragma unroll
        for (int o = 16; o; o >>= 1) mx = fmaxf(mx, __shfl_xor_sync(0xffffffffu, mx, o));
        float sum = 0.f;
        for (int m = lane; m < 196; m += 32) {
            float p = __expf(Ss[row * 228 + m] - mx);
            Ss[row * 228 + m] = p;
            sum += p;
        }
        #pragma unroll
        for (int o = 16; o; o >>= 1) sum += __shfl_xor_sync(0xffffffffu, sum, o);
        float inv = 1.f / sum;
        for (int m = lane; m < 196; m += 32) Ss[row * 228 + m] = rndf(Ss[row * 228 + m] * inv);
    }
    __syncthreads();

    {
        int wm = (warp >> 1) * 16, wn = (warp & 1) * 16;
        float acc[2][4];
        #pragma unroll
        for (int j = 0; j < 2; j++)
            #pragma unroll
            for (int r = 0; r < 4; r++) acc[j][r] = 0.f;
        #pragma unroll 5
        for (int ks = 0; ks < 25; ks++) {
            const int k = ks * 8;
            uint32_t af[4], bf[2][2];
            af[0] = __float_as_uint(Ss[(wm + lr) * 228 + k + lc]);
            af[1] = __float_as_uint(Ss[(wm + 8 + lr) * 228 + k + lc]);
            af[2] = __float_as_uint(Ss[(wm + lr) * 228 + k + 4 + lc]);
            af[3] = __float_as_uint(Ss[(wm + 8 + lr) * 228 + k + 4 + lc]);
            #pragma unroll
            for (int nj = 0; nj < 2; nj++) {
                int cc = wn + nj * 8 + lr;
                bf[nj][0] = __float_as_uint(Vs[(k + lc) * 36 + cc]);
                bf[nj][1] = __float_as_uint(Vs[(k + 4 + lc) * 36 + cc]);
            }
            MMA_TF32(acc[0], af, bf[0]);
            MMA_TF32(acc[1], af, bf[1]);
        }
        #pragma unroll
        for (int nj = 0; nj < 2; nj++) {
            int r0 = q0 + wm + lr;
            int c0 = wn + nj * 8 + lc * 2;
            *(float2*)&x1[((size_t)b * NTOK + r0) * 128 + h * 32 + c0] =
                make_float2(acc[nj][0], acc[nj][1]);
            *(float2*)&x1[((size_t)b * NTOK + r0 + 8) * 128 + h * 32 + c0] =
                make_float2(acc[nj][2], acc[nj][3]);
        }
    }
}

// ============ branch-2 window attention (tf32 MMA), 2 windows/CTA ============
#define A2_WSZ 6496
#define A2_SMEM (2 * A2_WSZ * 4)
__global__ __launch_bounds__(256, 4)
void attn2_mma(const float* __restrict__ pack, float* __restrict__ x2) {
    extern __shared__ float sm[];
    int bh = blockIdx.y, b = bh >> 2, h = bh & 3;
    int tid = threadIdx.x, lane = tid & 31, warp = tid >> 5;
    int wslot = warp >> 2, w4 = warp & 3;
    int lr = lane >> 2, lc = lane & 3;
    int win = blockIdx.x * 2 + wslot;
    int wr = win >> 3, wc = win & 7;
    float* base = sm + wslot * A2_WSZ;
    float* Qs = base;
    float* Kt = base + 2304;
    float* Ss = base;
    float* Vs = base + 4480;
    int wt = tid & 127;

    for (int e = wt; e < 64 * 8; e += 128) {
        int r = e >> 3, c4 = e & 7;
        float4 v = make_float4(0.f, 0.f, 0.f, 0.f);
        if (r < 49) {
            int n = (wr * 7 + r / 7) * 56 + wc * 7 + r % 7;
            v = *(const float4*)&pack[((size_t)b * NTOK + n) * 768 + 384 + h * 32 + c4 * 4];
            v.x = rndf(v.x); v.y = rndf(v.y); v.z = rndf(v.z); v.w = rndf(v.w);
        }
        *(float4*)&Qs[r * 36 + c4 * 4] = v;
    }
    for (int e = wt; e < 56 * 32; e += 128) {
        int m = e >> 5, dd = e & 31;
        float kk = 0.f, vv = 0.f;
        if (m < 49) {
            int n = (wr * 7 + m / 7) * 56 + wc * 7 + m % 7;
            size_t rb = ((size_t)b * NTOK + n) * 768 + 512 + h * 32 + dd;
            kk = rndf(pack[rb]);
            vv = rndf(pack[rb + 128]);
        }
        Kt[dd * 68 + m] = kk;
        Vs[m * 36 + dd] = vv;
    }
    __syncthreads();

    int wm = w4 * 16;
    {
        float acc[7][4];
        #pragma unroll
        for (int j = 0; j < 7; j++)
            #pragma unroll
            for (int r = 0; r < 4; r++) acc[j][r] = 0.f;
        #pragma unroll
        for (int ks = 0; ks < 4; ks++) {
            const int k = ks * 8;
            uint32_t af[4], bf[7][2];
            af[0] = __float_as_uint(Qs[(wm + lr) * 36 + k + lc]);
            af[1] = __float_as_uint(Qs[(wm + 8 + lr) * 36 + k + lc]);
            af[2] = __float_as_uint(Qs[(wm + lr) * 36 + k + 4 + lc]);
            af[3] = __float_as_uint(Qs[(wm + 8 + lr) * 36 + k + 4 + lc]);
            #pragma unroll
            for (int nj = 0; nj < 7; nj++) {
                int cc = nj * 8 + lr;
                bf[nj][0] = __float_as_uint(Kt[(k + lc) * 68 + cc]);
                bf[nj][1] = __float_as_uint(Kt[(k + 4 + lc) * 68 + cc]);
            }
            #pragma unroll
            for (int nj = 0; nj < 7; nj++)
                MMA_TF32(acc[nj], af, bf[nj]);
        }
        __syncthreads();
        #pragma unroll
        for (int nj = 0; nj < 7; nj++) {
            int c0 = nj * 8 + lc * 2;
            Ss[(wm + lr) * 68 + c0]           = acc[nj][0] * SCALE;
            Ss[(wm + lr) * 68 + c0 + 1]       = acc[nj][1] * SCALE;
            Ss[(wm + 8 + lr) * 68 + c0]       = acc[nj][2] * SCALE;
            Ss[(wm + 8 + lr) * 68 + c0 + 1]   = acc[nj][3] * SCALE;
        }
    }
    __syncthreads();

    for (int row = w4; row < 49; row += 4) {
        float mx = -1e30f;
        for (int m = lane; m < 49; m += 32) mx = fmaxf(mx, Ss[row * 68 + m]);
        #pragma unroll
        for (int o = 16; o; o >>= 1) mx = fmaxf(mx, __shfl_xor_sync(0xffffffffu, mx, o));
        float sum = 0.f;
        for (int m = lane; m < 49; m += 32) {
            float p = __expf(Ss[row * 68 + m] - mx);
            Ss[row * 68 + m] = p;
            sum += p;
        }
        #pragma unroll
        for (int o = 16; o; o >>= 1) sum += __shfl_xor_sync(0xffffffffu, sum, o);
        float inv = 1.f / sum;
        for (int m = lane; m < 49; m += 32) Ss[row * 68 + m] = rndf(Ss[row * 68 + m] * inv);
    }
    __syncthreads();

    {
        float acc[4][4];
        #pragma unroll
        for (int j = 0; j < 4; j++)
            #pragma unroll
            for (int r = 0; r < 4; r++) acc[j][r] = 0.f;
        #pragma unroll
        for (int ks = 0; ks < 7; ks++) {
            const int k = ks * 8;
            uint32_t af[4], bf[4][2];
            af[0] = __float_as_uint(Ss[(wm + lr) * 68 + k + lc]);
            af[1] = __float_as_uint(Ss[(wm + 8 + lr) * 68 + k + lc]);
            af[2] = __float_as_uint(Ss[(wm + lr) * 68 + k + 4 + lc]);
            af[3] = __float_as_uint(Ss[(wm + 8 + lr) * 68 + k + 4 + lc]);
            #pragma unroll
            for (int nj = 0; nj < 4; nj++) {
                int cc = nj * 8 + lr;
                bf[nj][0] = __float_as_uint(Vs[(k + lc) * 36 + cc]);
                bf[nj][1] = __float_as_uint(Vs[(k + 4 + lc) * 36 + cc]);
            }
            #pragma unroll
            for (int nj = 0; nj < 4; nj++)
                MMA_TF32(acc[nj], af, bf[nj]);
        }
        int r1 = wm + lr, r2 = wm + 8 + lr;
        #pragma unroll
        for (int nj = 0; nj < 4; nj++) {
            int c0 = nj * 8 + lc * 2;
            if (r1 < 49) {
                int n = (wr * 7 + r1 / 7) * 56 + wc * 7 + r1 % 7;
                *(float2*)&x2[((size_t)b * NTOK + n) * 128 + h * 32 + c0] =
                    make_float2(acc[nj][0], acc[nj][1]);
            }
            if (r2 < 49) {
                int n = (wr * 7 + r2 / 7) * 56 + wc * 7 + r2 % 7;
                *(float2*)&x2[((size_t)b * NTOK + n) * 128 + h * 32 + c0] =
                    make_float2(acc[nj][2], acc[nj][3]);
            }
        }
    }
}

// ---------------- host launch ----------------
extern "C" void kernel_launch(void* const* d_in, const int* in_sizes, int n_in,
                              void* d_out, int out_size) {
    const float* x           = (const float*)d_in[0];
    const float* lepe_lin_w  = (const float*)d_in[1];
    const float* lepe_lin_b  = (const float*)d_in[2];
    const float* lepe_conv_w = (const float*)d_in[3];
    const float* lepe_conv_b = (const float*)d_in[4];
    const float* sr_w        = (const float*)d_in[5];
    const float* sr_b        = (const float*)d_in[6];
    const float* norm_g      = (const float*)d_in[7];
    const float* norm_b      = (const float*)d_in[8];
    const float* q1_w        = (const float*)d_in[9];
    const float* kv1_w       = (const float*)d_in[10];
    const float* q2_w        = (const float*)d_in[11];
    const float* kv2_w       = (const float*)d_in[12];
    const float* proj_w      = (const float*)d_in[13];
    const float* proj_b      = (const float*)d_in[14];
    float* out = (float*)d_out;

    __half *xh, *wpackT, *srwT, *kv1wT, *projwT, *x1s;
    float *bpack, *pack, *lepe, *srp, *kv1, *x1, *x2;
    cudaGetSymbolAddress((void**)&xh,     g_xh);
    cudaGetSymbolAddress((void**)&wpackT, g_wpackT);
    cudaGetSymbolAddress((void**)&bpack,  g_bpack);
    cudaGetSymbolAddress((void**)&srwT,   g_srwT);
    cudaGetSymbolAddress((void**)&kv1wT,  g_kv1wT);
    cudaGetSymbolAddress((void**)&projwT, g_projwT);
    cudaGetSymbolAddress((void**)&pack,   g_pack);
    cudaGetSymbolAddress((void**)&lepe,   g_lepe);
    cudaGetSymbolAddress((void**)&srp,    g_srp);
    cudaGetSymbolAddress((void**)&x1s,    g_x1s);
    cudaGetSymbolAddress((void**)&kv1,    g_kv1);
    cudaGetSymbolAddress((void**)&x1,     g_x1);
    cudaGetSymbolAddress((void**)&x2,     g_x2);

    cudaFuncSetAttribute(tgemm_h,      cudaFuncAttributeMaxDynamicSharedMemorySize, TH_SMEM);
    cudaFuncSetAttribute(tgemm_sr_h,   cudaFuncAttributeMaxDynamicSharedMemorySize, TH_SMEM);
    cudaFuncSetAttribute(tgemm_proj_h, cudaFuncAttributeMaxDynamicSharedMemorySize, TH_SMEM);
    cudaFuncSetAttribute(attn1_mma,    cudaFuncAttributeMaxDynamicSharedMemorySize, A1_SMEM);
    cudaFuncSetAttribute(attn2_mma,    cudaFuncAttributeMaxDynamicSharedMemorySize, A2_SMEM);

    static cudaStream_t s1 = nullptr;
    static cudaEvent_t evF = nullptr, evP = nullptr, evJ = nullptr;
    if (!s1) {
        cudaStreamCreateWithFlags(&s1, cudaStreamNonBlocking);
        cudaEventCreateWithFlags(&evF, cudaEventDisableTiming);
        cudaEventCreateWithFlags(&evP, cudaEventDisableTiming);
        cudaEventCreateWithFlags(&evJ, cudaEventDisableTiming);
    }

    // main: weight pack + x conversion
    pack_weightsT<<<768, 256>>>(lepe_lin_w, lepe_lin_b, q1_w, q2_w, kv2_w, wpackT, bpack);
    cvt_x<<<(M_ALL * 256 / 4) / 256, 256>>>(x, xh);
    cudaEventRecord(evF, 0);

    // s1: sr chain (roundT has no deps; sr GEMM needs xh via evF)
    roundT<<<4096, 256, 0, s1>>>(sr_w, kv1_w, proj_w, srwT, kv1wT, projwT);
    cudaStreamWaitEvent(s1, evF, 0);
    tgemm_sr_h<<<dim3(2, M_SR / 128, 4), 256, TH_SMEM, s1>>>(xh, srwT, srp);
    ln_gelu4<<<M_SR, 256, 0, s1>>>(srp, sr_b, norm_g, norm_b, x1s);
    tgemm_h<<<dim3(2, M_SR / 128), 256, TH_SMEM, s1>>>(x1s, kv1wT, nullptr, kv1, M_SR, 256, 256);

    // main: merged projection GEMM + consumers
    tgemm_h<<<dim3(6, M_ALL / 128), 256, TH_SMEM>>>(xh, wpackT, bpack, pack, M_ALL, 768, 256);
    cudaEventRecord(evP, 0);
    dwconv3x3<<<(BATCH * WW * CH) / 256, 256>>>(pack, lepe_conv_w, lepe_conv_b, lepe);
    attn2_mma<<<dim3(32, BATCH * H2), 256, A2_SMEM>>>(pack, x2);

    // s1: attn1 after pack ready
    cudaStreamWaitEvent(s1, evP, 0);
    attn1_mma<<<dim3(NTOK / 64, BATCH * H2), 256, A1_SMEM, s1>>>(pack, kv1, x1);
    cudaEventRecord(evJ, s1);

    // join + final projection
    cudaStreamWaitEvent(0, evJ, 0);
    tgemm_proj_h<<<dim3(2, M_ALL / 128), 256, TH_SMEM>>>(x1, x2, lepe, projwT, proj_b, out);
}

// round 8
// speedup vs baseline: 4.2090x; 1.0783x over previous
#include <cuda_runtime.h>
#include <cuda_fp16.h>
#include <cstdint>

#define BATCH 32
#define HH 56
#define WW 56
#define NTOK (HH*WW)            // 3136
#define CH 256
#define H2 4
#define M_ALL (BATCH*NTOK)      // 100352
#define N1 196
#define M_SR (BATCH*N1)         // 6272
#define SCALE 0.17677669529663687f

// ---------------- scratch ----------------
__device__ __half g_xh    [(size_t)M_ALL*256];
__device__ __half g_wpackT[(size_t)768*256];
__device__ float  g_bpack [768];
__device__ __half g_srwT  [(size_t)256*4096];
__device__ __half g_kv1wT [(size_t)256*256];
__device__ __half g_projwT[(size_t)256*256];
__device__ __half g_packh [(size_t)M_ALL*768];  // [lepe_lin | q1 | q2 | kv2] (half)
__device__ __half g_lepeh [(size_t)M_ALL*CH];
__device__ float  g_srp   [(size_t)4*M_SR*CH];
__device__ __half g_x1s   [(size_t)M_SR*CH];
__device__ __half g_kv1h  [(size_t)M_SR*CH];
__device__ __half g_x1h   [(size_t)M_ALL*128];
__device__ __half g_x2h   [(size_t)M_ALL*128];

// ---------------- helpers ----------------
#define CP16(dst, src) \
    asm volatile("cp.async.cg.shared.global [%0], [%1], 16;" :: "r"(dst), "l"(src))
#define MMA_F16(c, a, b) \
    asm volatile("mma.sync.aligned.m16n8k16.row.col.f32.f16.f16.f32 " \
                 "{%0,%1,%2,%3},{%4,%5,%6,%7},{%8,%9},{%0,%1,%2,%3};" \
                 : "+f"((c)[0]), "+f"((c)[1]), "+f"((c)[2]), "+f"((c)[3]) \
                 : "r"((a)[0]), "r"((a)[1]), "r"((a)[2]), "r"((a)[3]), \
                   "r"((b)[0]), "r"((b)[1]))

__device__ __forceinline__ uint32_t h2pack(float a, float b) {
    __half2 h = __floats2half2_rn(a, b);
    return *(uint32_t*)&h;
}

// fp16 GEMM tile constants: A and B smem tiles both [128][40] halves
#define HSTR 40
#define HBUF (128*HSTR)                 // 5120 halves = 10240 B
#define TH_SMEM (4*HBUF*2)              // 40960 B

// ============ prep kernels ============
__global__ void cvt_x(const float* __restrict__ x, __half* __restrict__ xh) {
    size_t i = (size_t)blockIdx.x * 256 + threadIdx.x;
    float4 v = ((const float4*)x)[i];
    __half2* o = (__half2*)xh;
    o[2 * i]     = __floats2half2_rn(v.x, v.y);
    o[2 * i + 1] = __floats2half2_rn(v.z, v.w);
}

__global__ void pack_weightsT(const float* __restrict__ lw, const float* __restrict__ lb,
                              const float* __restrict__ q1w, const float* __restrict__ q2w,
                              const float* __restrict__ kvw,
                              __half* __restrict__ wt, float* __restrict__ bp) {
    int idx = blockIdx.x * 256 + threadIdx.x;
    if (idx < 768) bp[idx] = (idx < 256) ? lb[idx] : 0.f;
    if (idx >= 768 * 256) return;
    int c = idx >> 8, k = idx & 255;
    float v;
    if (c < 256)      v = lw[k * 256 + c];
    else if (c < 384) v = q1w[k * 128 + (c - 256)];
    else if (c < 512) v = q2w[k * 128 + (c - 384)];
    else              v = kvw[k * 256 + (c - 512)];
    wt[idx] = __float2half_rn(v);
}

__global__ void roundT(const float* __restrict__ sw, const float* __restrict__ kw,
                       const float* __restrict__ pw,
                       __half* __restrict__ st, __half* __restrict__ kt,
                       __half* __restrict__ pt) {
    int i = blockIdx.x * 256 + threadIdx.x;
    if (i < 256 * 4096) {
        int c = i >> 12, k = i & 4095;
        st[i] = __float2half_rn(sw[k * 256 + c]);
    }
    if (i < 256 * 256) {
        int c = i >> 8, k = i & 255;
        kt[i] = __float2half_rn(kw[k * 256 + c]);
        pt[i] = __float2half_rn(pw[k * 256 + c]);
    }
}

// ============ fp16 GEMM: C[M,N] = A[M,K] @ Bt[N,K]^T (+bias); OH = half output ============
template<bool OH>
__global__ __launch_bounds__(256, 2)
void tgemm_h(const __half* __restrict__ A, const __half* __restrict__ Bt,
             const float* __restrict__ bias, void* __restrict__ Cv,
             int M, int N, int K) {
    extern __shared__ __half hs[];
    const int tid  = threadIdx.x;
    const int lane = tid & 31;
    const int warp = tid >> 5;
    const int wm = (warp >> 2) * 64;
    const int wn = (warp & 3) * 32;
    const int brow = blockIdx.y * 128;
    const int bcol = blockIdx.x * 128;
    const int lr = lane >> 2;
    const int lc = lane & 3;
    const int arow = tid >> 2;
    const int c16 = tid & 3;

    float acc[4][4][4];
    #pragma unroll
    for (int i = 0; i < 4; i++)
        #pragma unroll
        for (int j = 0; j < 4; j++)
            #pragma unroll
            for (int r = 0; r < 4; r++) acc[i][j][r] = 0.f;

    const int KT = K >> 5;
    auto issue = [&](int buf, int k0) {
        __half* Ad = hs + buf * HBUF;
        __half* Bd = hs + 2 * HBUF + buf * HBUF;
        #pragma unroll
        for (int i = 0; i < 2; i++) {
            int row = arow + i * 64;
            uint32_t d = (uint32_t)__cvta_generic_to_shared(Ad + row * HSTR + c16 * 8);
            CP16(d, A + (size_t)(brow + row) * K + k0 + c16 * 8);
        }
        #pragma unroll
        for (int i = 0; i < 2; i++) {
            int row = arow + i * 64;
            uint32_t d = (uint32_t)__cvta_generic_to_shared(Bd + row * HSTR + c16 * 8);
            CP16(d, Bt + (size_t)(bcol + row) * K + k0 + c16 * 8);
        }
        asm volatile("cp.async.commit_group;" ::);
    };

    issue(0, 0);
    int buf = 0;
    for (int kt = 0; kt < KT; kt++) {
        asm volatile("cp.async.wait_group 0;" ::);
        __syncthreads();
        if (kt + 1 < KT) issue(buf ^ 1, (kt + 1) << 5);
        const __half* Ad = hs + buf * HBUF;
        const __half* Bd = hs + 2 * HBUF + buf * HBUF;
        #pragma unroll
        for (int ks = 0; ks < 2; ks++) {
            const int kb = ks * 16 + 2 * lc;
            uint32_t af[4][4], bf[4][2];
            #pragma unroll
            for (int mi = 0; mi < 4; mi++) {
                int r0 = wm + mi * 16 + lr;
                af[mi][0] = *(const uint32_t*)(Ad + r0 * HSTR + kb);
                af[mi][1] = *(const uint32_t*)(Ad + (r0 + 8) * HSTR + kb);
                af[mi][2] = *(const uint32_t*)(Ad + r0 * HSTR + kb + 8);
                af[mi][3] = *(const uint32_t*)(Ad + (r0 + 8) * HSTR + kb + 8);
            }
            #pragma unroll
            for (int nj = 0; nj < 4; nj++) {
                int cc = wn + nj * 8 + lr;
                bf[nj][0] = *(const uint32_t*)(Bd + cc * HSTR + kb);
                bf[nj][1] = *(const uint32_t*)(Bd + cc * HSTR + kb + 8);
            }
            #pragma unroll
            for (int mi = 0; mi < 4; mi++)
                #pragma unroll
                for (int nj = 0; nj < 4; nj++)
                    MMA_F16(acc[mi][nj], af[mi], bf[nj]);
        }
        buf ^= 1;
    }
    #pragma unroll
    for (int mi = 0; mi < 4; mi++) {
        #pragma unroll
        for (int nj = 0; nj < 4; nj++) {
            int r0 = brow + wm + mi * 16 + lr;
            int c0 = bcol + wn + nj * 8 + lc * 2;
            float b0 = 0.f, b1 = 0.f;
            if (bias) { b0 = bias[c0]; b1 = bias[c0 + 1]; }
            if (OH) {
                __half* C = (__half*)Cv;
                *(__half2*)&C[(size_t)r0 * N + c0] =
                    __floats2half2_rn(acc[mi][nj][0] + b0, acc[mi][nj][1] + b1);
                *(__half2*)&C[(size_t)(r0 + 8) * N + c0] =
                    __floats2half2_rn(acc[mi][nj][2] + b0, acc[mi][nj][3] + b1);
            } else {
                float* C = (float*)Cv;
                *(float2*)&C[(size_t)r0 * N + c0] = make_float2(acc[mi][nj][0] + b0, acc[mi][nj][1] + b1);
                *(float2*)&C[(size_t)(r0 + 8) * N + c0] = make_float2(acc[mi][nj][2] + b0, acc[mi][nj][3] + b1);
            }
        }
    }
}

// ============ fp16 sr-conv GEMM, fused im2col over xh, split-K x4 (fp32 partials) ============
__global__ __launch_bounds__(256, 2)
void tgemm_sr_h(const __half* __restrict__ xh, const __half* __restrict__ Bt,
                float* __restrict__ Cp) {
    const int kc = blockIdx.z;
    float* C = Cp + (size_t)kc * M_SR * 256;
    extern __shared__ __half hs[];
    const int tid  = threadIdx.x;
    const int lane = tid & 31;
    const int warp = tid >> 5;
    const int wm = (warp >> 2) * 64;
    const int wn = (warp & 3) * 32;
    const int brow = blockIdx.y * 128;
    const int bcol = blockIdx.x * 128;
    const int lr = lane >> 2;
    const int lc = lane & 3;
    const int arow = tid >> 2;
    const int c16 = tid & 3;

    const __half* px[2];
    #pragma unroll
    for (int i = 0; i < 2; i++) {
        int m = brow + arow + i * 64;
        int b = m / 196, rem = m % 196;
        int oh = rem / 14, ow = rem % 14;
        px[i] = xh + ((size_t)((b * 56 + oh * 4) * 56 + ow * 4)) * 256;
    }

    float acc[4][4][4];
    #pragma unroll
    for (int i = 0; i < 4; i++)
        #pragma unroll
        for (int j = 0; j < 4; j++)
            #pragma unroll
            for (int r = 0; r < 4; r++) acc[i][j][r] = 0.f;

    const int KT = 32;
    auto issue = [&](int buf, int k0) {
        __half* Ad = hs + buf * HBUF;
        __half* Bd = hs + 2 * HBUF + buf * HBUF;
        int kk = kc * 1024 + k0 + c16 * 8;
        int kh = kk >> 10, kw = (kk >> 8) & 3, c = kk & 255;
        int off = (kh * 56 + kw) * 256 + c;
        #pragma unroll
        for (int i = 0; i < 2; i++) {
            int row = arow + i * 64;
            uint32_t d = (uint32_t)__cvta_generic_to_shared(Ad + row * HSTR + c16 * 8);
            CP16(d, px[i] + off);
        }
        #pragma unroll
        for (int i = 0; i < 2; i++) {
            int row = arow + i * 64;
            uint32_t d = (uint32_t)__cvta_generic_to_shared(Bd + row * HSTR + c16 * 8);
            CP16(d, Bt + (size_t)(bcol + row) * 4096 + kc * 1024 + k0 + c16 * 8);
        }
        asm volatile("cp.async.commit_group;" ::);
    };

    issue(0, 0);
    int buf = 0;
    for (int kt = 0; kt < KT; kt++) {
        asm volatile("cp.async.wait_group 0;" ::);
        __syncthreads();
        if (kt + 1 < KT) issue(buf ^ 1, (kt + 1) << 5);
        const __half* Ad = hs + buf * HBUF;
        const __half* Bd = hs + 2 * HBUF + buf * HBUF;
        #pragma unroll
        for (int ks = 0; ks < 2; ks++) {
            const int kb = ks * 16 + 2 * lc;
            uint32_t af[4][4], bf[4][2];
            #pragma unroll
            for (int mi = 0; mi < 4; mi++) {
                int r0 = wm + mi * 16 + lr;
                af[mi][0] = *(const uint32_t*)(Ad + r0 * HSTR + kb);
                af[mi][1] = *(const uint32_t*)(Ad + (r0 + 8) * HSTR + kb);
                af[mi][2] = *(const uint32_t*)(Ad + r0 * HSTR + kb + 8);
                af[mi][3] = *(const uint32_t*)(Ad + (r0 + 8) * HSTR + kb + 8);
            }
            #pragma unroll
            for (int nj = 0; nj < 4; nj++) {
                int cc = wn + nj * 8 + lr;
                bf[nj][0] = *(const uint32_t*)(Bd + cc * HSTR + kb);
                bf[nj][1] = *(const uint32_t*)(Bd + cc * HSTR + kb + 8);
            }
            #pragma unroll
            for (int mi = 0; mi < 4; mi++)
                #pragma unroll
                for (int nj = 0; nj < 4; nj++)
                    MMA_F16(acc[mi][nj], af[mi], bf[nj]);
        }
        buf ^= 1;
    }
    #pragma unroll
    for (int mi = 0; mi < 4; mi++) {
        #pragma unroll
        for (int nj = 0; nj < 4; nj++) {
            int r0 = brow + wm + mi * 16 + lr;
            int c0 = bcol + wn + nj * 8 + lc * 2;
            *(float2*)&C[(size_t)r0 * 256 + c0] = make_float2(acc[mi][nj][0], acc[mi][nj][1]);
            *(float2*)&C[(size_t)(r0 + 8) * 256 + c0] = make_float2(acc[mi][nj][2], acc[mi][nj][3]);
        }
    }
}

// ============ fp16 proj GEMM with fused concat(x1,x2)+lepe (half sources, fp32 out) ============
__global__ __launch_bounds__(256, 2)
void tgemm_proj_h(const __half* __restrict__ x1h, const __half* __restrict__ x2h,
                  const __half* __restrict__ lepeh, const __half* __restrict__ Bt,
                  const float* __restrict__ bias, float* __restrict__ C) {
    const int N = 256, K = 256;
    extern __shared__ __half hs[];
    const int tid  = threadIdx.x;
    const int lane = tid & 31;
    const int warp = tid >> 5;
    const int wm = (warp >> 2) * 64;
    const int wn = (warp & 3) * 32;
    const int brow = blockIdx.y * 128;
    const int bcol = blockIdx.x * 128;
    const int lr = lane >> 2;
    const int lc = lane & 3;
    const int arow = tid >> 2;
    const int c16 = tid & 3;

    float acc[4][4][4];
    #pragma unroll
    for (int i = 0; i < 4; i++)
        #pragma unroll
        for (int j = 0; j < 4; j++)
            #pragma unroll
            for (int r = 0; r < 4; r++) acc[i][j][r] = 0.f;

    auto issueB = [&](int buf, int k0) {
        __half* Bd = hs + 2 * HBUF + buf * HBUF;
        #pragma unroll
        for (int i = 0; i < 2; i++) {
            int row = arow + i * 64;
            uint32_t d = (uint32_t)__cvta_generic_to_shared(Bd + row * HSTR + c16 * 8);
            CP16(d, Bt + (size_t)(bcol + row) * K + k0 + c16 * 8);
        }
        asm volatile("cp.async.commit_group;" ::);
    };

    uint4 ra4[2];
    auto addh = [](uint32_t ua, uint32_t ul) {
        __half2 ha = *(__half2*)&ua, hl = *(__half2*)&ul;
        float2 fa = __half22float2(ha), fl = __half22float2(hl);
        __half2 r = __floats2half2_rn(fa.x + fl.x, fa.y + fl.y);
        return *(uint32_t*)&r;
    };
    auto loadA = [&](int k0) {
        int kk = k0 + c16 * 8;
        #pragma unroll
        for (int i = 0; i < 2; i++) {
            size_t m = (size_t)(brow + arow + i * 64);
            uint4 a = (kk < 128) ? *(const uint4*)&x1h[m * 128 + kk]
                                 : *(const uint4*)&x2h[m * 128 + kk - 128];
            uint4 l = *(const uint4*)&lepeh[m * 256 + kk];
            ra4[i].x = addh(a.x, l.x);
            ra4[i].y = addh(a.y, l.y);
            ra4[i].z = addh(a.z, l.z);
            ra4[i].w = addh(a.w, l.w);
        }
    };
    auto storeA = [&](int buf) {
        __half* Ad = hs + buf * HBUF;
        #pragma unroll
        for (int i = 0; i < 2; i++)
            *(uint4*)(Ad + (arow + i * 64) * HSTR + c16 * 8) = ra4[i];
    };

    issueB(0, 0);
    loadA(0);
    int buf = 0;
    const int KT = K >> 5;
    for (int kt = 0; kt < KT; kt++) {
        storeA(buf);
        asm volatile("cp.async.wait_group 0;" ::);
        __syncthreads();
        if (kt + 1 < KT) { issueB(buf ^ 1, (kt + 1) << 5); loadA((kt + 1) << 5); }
        const __half* Ad = hs + buf * HBUF;
        const __half* Bd = hs + 2 * HBUF + buf * HBUF;
        #pragma unroll
        for (int ks = 0; ks < 2; ks++) {
            const int kb = ks * 16 + 2 * lc;
            uint32_t af[4][4], bf[4][2];
            #pragma unroll
            for (int mi = 0; mi < 4; mi++) {
                int r0 = wm + mi * 16 + lr;
                af[mi][0] = *(const uint32_t*)(Ad + r0 * HSTR + kb);
                af[mi][1] = *(const uint32_t*)(Ad + (r0 + 8) * HSTR + kb);
                af[mi][2] = *(const uint32_t*)(Ad + r0 * HSTR + kb + 8);
                af[mi][3] = *(const uint32_t*)(Ad + (r0 + 8) * HSTR + kb + 8);
            }
            #pragma unroll
            for (int nj = 0; nj < 4; nj++) {
                int cc = wn + nj * 8 + lr;
                bf[nj][0] = *(const uint32_t*)(Bd + cc * HSTR + kb);
                bf[nj][1] = *(const uint32_t*)(Bd + cc * HSTR + kb + 8);
            }
            #pragma unroll
            for (int mi = 0; mi < 4; mi++)
                #pragma unroll
                for (int nj = 0; nj < 4; nj++)
                    MMA_F16(acc[mi][nj], af[mi], bf[nj]);
        }
        buf ^= 1;
        __syncthreads();
    }
    #pragma unroll
    for (int mi = 0; mi < 4; mi++) {
        #pragma unroll
        for (int nj = 0; nj < 4; nj++) {
            int r0 = brow + wm + mi * 16 + lr;
            int c0 = bcol + wn + nj * 8 + lc * 2;
            float b0 = bias[c0], b1 = bias[c0 + 1];
            *(float2*)&C[(size_t)r0 * N + c0] = make_float2(acc[mi][nj][0] + b0, acc[mi][nj][1] + b1);
            *(float2*)&C[(size_t)(r0 + 8) * N + c0] = make_float2(acc[mi][nj][2] + b0, acc[mi][nj][3] + b1);
        }
    }
}

// ============ depthwise 3x3, register y-walk (half in/out) ============
__global__ void dwconv3x3(const __half* __restrict__ in, const float* __restrict__ w,
                          const float* __restrict__ bias, __half* __restrict__ out) {
    int idx = blockIdx.x * 256 + threadIdx.x;
    int c = idx & 255;
    int t = idx >> 8;
    int xx = t % WW, b = t / WW;
    float wt[9];
    #pragma unroll
    for (int i = 0; i < 9; i++) wt[i] = w[i * 256 + c];
    float bz = bias[c];
    const __half* base = in + (size_t)b * NTOK * 768 + c;
    __half* ob = out + (size_t)b * NTOK * 256 + c;
    bool xl = xx > 0, xr = xx < WW - 1;

    float rA[3] = {0.f, 0.f, 0.f}, rB[3], rC[3];
    {
        const __half* rp = base;
        rB[0] = xl ? __half2float(rp[(xx - 1) * 768]) : 0.f;
        rB[1] = __half2float(rp[xx * 768]);
        rB[2] = xr ? __half2float(rp[(xx + 1) * 768]) : 0.f;
    }
    for (int y = 0; y < HH; y++) {
        if (y + 1 < HH) {
            const __half* rp = base + (size_t)(y + 1) * WW * 768;
            rC[0] = xl ? __half2float(rp[(xx - 1) * 768]) : 0.f;
            rC[1] = __half2float(rp[xx * 768]);
            rC[2] = xr ? __half2float(rp[(xx + 1) * 768]) : 0.f;
        } else { rC[0] = rC[1] = rC[2] = 0.f; }
        float acc = bz
            + wt[0] * rA[0] + wt[1] * rA[1] + wt[2] * rA[2]
            + wt[3] * rB[0] + wt[4] * rB[1] + wt[5] * rB[2]
            + wt[6] * rC[0] + wt[7] * rC[1] + wt[8] * rC[2];
        ob[(size_t)(y * WW + xx) * 256] = __float2half_rn(acc);
        rA[0] = rB[0]; rA[1] = rB[1]; rA[2] = rB[2];
        rB[0] = rC[0]; rB[1] = rC[1]; rB[2] = rC[2];
    }
}

// ============ split-K reduce + bias + LayerNorm + GELU -> half ============
__global__ void ln_gelu4(const float* __restrict__ p, const float* __restrict__ srb,
                         const float* __restrict__ g, const float* __restrict__ bb,
                         __half* __restrict__ xb) {
    int row = blockIdx.x;
    int tid = threadIdx.x;
    const size_t S = (size_t)M_SR * 256;
    size_t off = (size_t)row * 256 + tid;
    float v = p[off] + p[S + off] + p[2 * S + off] + p[3 * S + off] + srb[tid];
    __shared__ float s1[256], s2[256];
    s1[tid] = v; s2[tid] = v * v;
    __syncthreads();
    for (int o = 128; o; o >>= 1) {
        if (tid < o) { s1[tid] += s1[tid + o]; s2[tid] += s2[tid + o]; }
        __syncthreads();
    }
    float mu  = s1[0] * (1.f / CH);
    float var = s2[0] * (1.f / CH) - mu * mu;
    float tt = (v - mu) * rsqrtf(var + 1e-5f) * g[tid] + bb[tid];
    xb[off] = __float2half_rn(0.5f * tt * (1.f + erff(tt * 0.70710678118654752f)));
}

// ============ branch-1 attention, fp16 MMA ============
// smem (halves): Qs[64][40]=2560h, Ks[224][40]=8960h, Vt[32][232]=7424h -> 18944h = 37888B
// then Ss fp32 [64][228] = 58368B.  Total 96256B -> occ 2.
#define A1_SMEM 96256
__global__ __launch_bounds__(256, 2)
void attn1_mma(const __half* __restrict__ packh, const __half* __restrict__ kv1h,
               __half* __restrict__ x1h) {
    extern __shared__ __half smh[];
    __half* Qs = smh;                        // [64][40]
    __half* Ks = smh + 2560;                 // [224][40] rows 196..223 zero
    __half* Vt = smh + 2560 + 8960;          // [32][232] cols 196..223 zero
    float*  Ss = (float*)(smh + 18944);      // [64][228]
    int bh = blockIdx.y, b = bh >> 2, h = bh & 3;
    int q0 = blockIdx.x * 64;
    int tid = threadIdx.x, lane = tid & 31, warp = tid >> 5;
    int lr = lane >> 2, lc = lane & 3;

    // Q: 64 rows x 4 x 8-half chunks -> one uint4 per thread
    {
        int r = tid >> 2, ch = tid & 3;
        *(uint4*)&Qs[r * 40 + ch * 8] =
            *(const uint4*)&packh[((size_t)b * NTOK + q0 + r) * 768 + 256 + h * 32 + ch * 8];
    }
    // K: 224 rows x 4 chunks (zero pad rows >=196)
    for (int e = tid; e < 224 * 4; e += 256) {
        int r = e >> 2, ch = e & 3;
        uint4 v = make_uint4(0u, 0u, 0u, 0u);
        if (r < 196)
            v = *(const uint4*)&kv1h[((size_t)b * N1 + r) * 256 + h * 32 + ch * 8];
        *(uint4*)&Ks[r * 40 + ch * 8] = v;
    }
    // V transpose: Vt[d][m]
    for (int e = tid; e < 224 * 32; e += 256) {
        int m = e >> 5, dd = e & 31;
        __half v = __float2half_rn(0.f);
        if (m < 196) v = kv1h[((size_t)b * N1 + m) * 256 + 128 + h * 32 + dd];
        Vt[dd * 232 + m] = v;
    }
    __syncthreads();

    // scores S[64,224] = Q @ K^T ; warp grid 2(m:32) x 4(n:56), ksteps 2
    {
        int wm = (warp >> 2) * 32, wn = (warp & 3) * 56;
        float acc[2][7][4];
        #pragma unroll
        for (int i = 0; i < 2; i++)
            #pragma unroll
            for (int j = 0; j < 7; j++)
                #pragma unroll
                for (int r = 0; r < 4; r++) acc[i][j][r] = 0.f;
        #pragma unroll
        for (int ks = 0; ks < 2; ks++) {
            const int kb = ks * 16 + 2 * lc;
            uint32_t af[2][4], bf[7][2];
            #pragma unroll
            for (int mi = 0; mi < 2; mi++) {
                int r0 = wm + mi * 16 + lr;
                af[mi][0] = *(const uint32_t*)(Qs + r0 * 40 + kb);
                af[mi][1] = *(const uint32_t*)(Qs + (r0 + 8) * 40 + kb);
                af[mi][2] = *(const uint32_t*)(Qs + r0 * 40 + kb + 8);
                af[mi][3] = *(const uint32_t*)(Qs + (r0 + 8) * 40 + kb + 8);
            }
            #pragma unroll
            for (int nj = 0; nj < 7; nj++) {
                int cc = wn + nj * 8 + lr;
                bf[nj][0] = *(const uint32_t*)(Ks + cc * 40 + kb);
                bf[nj][1] = *(const uint32_t*)(Ks + cc * 40 + kb + 8);
            }
            #pragma unroll
            for (int mi = 0; mi < 2; mi++)
                #pragma unroll
                for (int nj = 0; nj < 7; nj++)
                    MMA_F16(acc[mi][nj], af[mi], bf[nj]);
        }
        #pragma unroll
        for (int mi = 0; mi < 2; mi++)
            #pragma unroll
            for (int nj = 0; nj < 7; nj++) {
                int r0 = wm + mi * 16 + lr;
                int c0 = wn + nj * 8 + lc * 2;
                Ss[r0 * 228 + c0]           = acc[mi][nj][0] * SCALE;
                Ss[r0 * 228 + c0 + 1]       = acc[mi][nj][1] * SCALE;
                Ss[(r0 + 8) * 228 + c0]     = acc[mi][nj][2] * SCALE;
                Ss[(r0 + 8) * 228 + c0 + 1] = acc[mi][nj][3] * SCALE;
            }
    }
    __syncthreads();

    // softmax over cols 0..195 (cols 196..223 stay exactly 0)
    #pragma unroll
    for (int r = 0; r < 8; r++) {
        int row = warp * 8 + r;
        float mx = -1e30f;
        for (int m = lane; m < 196; m += 32) mx = fmaxf(mx, Ss[row * 228 + m]);
        #pragma unroll
        for (int o = 16; o; o >>= 1) mx = fmaxf(mx, __shfl_xor_sync(0xffffffffu, mx, o));
        float sum = 0.f;
        for (int m = lane; m < 196; m += 32) {
            float p = __expf(Ss[row * 228 + m] - mx);
            Ss[row * 228 + m] = p;
            sum += p;
        }
        #pragma unroll
        for (int o = 16; o; o >>= 1) sum += __shfl_xor_sync(0xffffffffu, sum, o);
        float inv = 1.f / sum;
        for (int m = lane; m < 196; m += 32) Ss[row * 228 + m] *= inv;
    }
    __syncthreads();

    // out = P[64,224] @ V[224,32]; warp grid 4(m:16) x 2(n:16); ksteps 14; P converted on the fly
    {
        int wm = (warp >> 1) * 16, wn = (warp & 1) * 16;
        float acc[2][4];
        #pragma unroll
        for (int j = 0; j < 2; j++)
            #pragma unroll
            for (int r = 0; r < 4; r++) acc[j][r] = 0.f;
        #pragma unroll 7
        for (int ks = 0; ks < 14; ks++) {
            const int k = ks * 16;
            const float* S0 = Ss + (wm + lr) * 228 + k + 2 * lc;
            const float* S1 = Ss + (wm + 8 + lr) * 228 + k + 2 * lc;
            uint32_t af[4], bf[2][2];
            float2 p0 = *(const float2*)S0;
            float2 p1 = *(const float2*)S1;
            float2 p2 = *(const float2*)(S0 + 8);
            float2 p3 = *(const float2*)(S1 + 8);
            af[0] = h2pack(p0.x, p0.y);
            af[1] = h2pack(p1.x, p1.y);
            af[2] = h2pack(p2.x, p2.y);
            af[3] = h2pack(p3.x, p3.y);
            #pragma unroll
            for (int nj = 0; nj < 2; nj++) {
                int cc = wn + nj * 8 + lr;
                bf[nj][0] = *(const uint32_t*)(Vt + cc * 232 + k + 2 * lc);
                bf[nj][1] = *(const uint32_t*)(Vt + cc * 232 + k + 2 * lc + 8);
            }
            MMA_F16(acc[0], af, bf[0]);
            MMA_F16(acc[1], af, bf[1]);
        }
        #pragma unroll
        for (int nj = 0; nj < 2; nj++) {
            int r0 = q0 + wm + lr;
            int c0 = wn + nj * 8 + lc * 2;
            *(__half2*)&x1h[((size_t)b * NTOK + r0) * 128 + h * 32 + c0] =
                __floats2half2_rn(acc[nj][0], acc[nj][1]);
            *(__half2*)&x1h[((size_t)b * NTOK + r0 + 8) * 128 + h * 32 + c0] =
                __floats2half2_rn(acc[nj][2], acc[nj][3]);
        }
    }
}

// ============ branch-2 window attention, fp16 MMA, 2 windows/CTA ============
// per-window bytes: Qs[64][40]h 5120 + Ks[64][40]h 5120 + Vt[32][72]h 4608 = 14848,
// then Ss fp32 [64][68] = 17408 -> 32256 B.  x2 windows = 64512 B -> occ 3.
#define A2_WBYTES 32256
#define A2_SMEM (2 * A2_WBYTES)
__global__ __launch_bounds__(256, 3)
void attn2_mma(const __half* __restrict__ packh, __half* __restrict__ x2h) {
    extern __shared__ char smc[];
    int bh = blockIdx.y, b = bh >> 2, h = bh & 3;
    int tid = threadIdx.x, lane = tid & 31, warp = tid >> 5;
    int wslot = warp >> 2, w4 = warp & 3;
    int lr = lane >> 2, lc = lane & 3;
    int win = blockIdx.x * 2 + wslot;
    int wr = win >> 3, wc = win & 7;
    char* wbase = smc + wslot * A2_WBYTES;
    __half* Qs = (__half*)wbase;             // [64][40], rows 49..63 zero
    __half* Ks = Qs + 2560;                  // [64][40], rows 49..63 zero
    __half* Vt = Ks + 2560;                  // [32][72], cols 49..63 zero
    float*  Ss = (float*)(wbase + 14848);    // [64][68]
    int wt = tid & 127;

    // Q + K: 64 rows x 4 chunks each
    for (int e = wt; e < 64 * 4; e += 128) {
        int r = e >> 2, ch = e & 3;
        uint4 q = make_uint4(0u, 0u, 0u, 0u), k = q;
        if (r < 49) {
            int n = (wr * 7 + r / 7) * 56 + wc * 7 + r % 7;
            size_t rb = ((size_t)b * NTOK + n) * 768;
            q = *(const uint4*)&packh[rb + 384 + h * 32 + ch * 8];
            k = *(const uint4*)&packh[rb + 512 + h * 32 + ch * 8];
        }
        *(uint4*)&Qs[r * 40 + ch * 8] = q;
        *(uint4*)&Ks[r * 40 + ch * 8] = k;
    }
    // V transpose
    for (int e = wt; e < 64 * 32; e += 128) {
        int m = e >> 5, dd = e & 31;
        __half v = __float2half_rn(0.f);
        if (m < 49) {
            int n = (wr * 7 + m / 7) * 56 + wc * 7 + m % 7;
            v = packh[((size_t)b * NTOK + n) * 768 + 640 + h * 32 + dd];
        }
        Vt[dd * 72 + m] = v;
    }
    __syncthreads();

    // scores: warp w4 owns rows [w4*16, +16), all 8 n-tiles (64 cols); ksteps 2
    int wm = w4 * 16;
    {
        float acc[8][4];
        #pragma unroll
        for (int j = 0; j < 8; j++)
            #pragma unroll
            for (int r = 0; r < 4; r++) acc[j][r] = 0.f;
        #pragma unroll
        for (int ks = 0; ks < 2; ks++) {
            const int kb = ks * 16 + 2 * lc;
            uint32_t af[4], bf[8][2];
            af[0] = *(const uint32_t*)(Qs + (wm + lr) * 40 + kb);
            af[1] = *(const uint32_t*)(Qs + (wm + 8 + lr) * 40 + kb);
            af[2] = *(const uint32_t*)(Qs + (wm + lr) * 40 + kb + 8);
            af[3] = *(const uint32_t*)(Qs + (wm + 8 + lr) * 40 + kb + 8);
            #pragma unroll
            for (int nj = 0; nj < 8; nj++) {
                int cc = nj * 8 + lr;
                bf[nj][0] = *(const uint32_t*)(Ks + cc * 40 + kb);
                bf[nj][1] = *(const uint32_t*)(Ks + cc * 40 + kb + 8);
            }
            #pragma unroll
            for (int nj = 0; nj < 8; nj++)
                MMA_F16(acc[nj], af, bf[nj]);
        }
        #pragma unroll
        for (int nj = 0; nj < 8; nj++) {
            int c0 = nj * 8 + lc * 2;
            Ss[(wm + lr) * 68 + c0]           = acc[nj][0] * SCALE;
            Ss[(wm + lr) * 68 + c0 + 1]       = acc[nj][1] * SCALE;
            Ss[(wm + 8 + lr) * 68 + c0]       = acc[nj][2] * SCALE;
            Ss[(wm + 8 + lr) * 68 + c0 + 1]   = acc[nj][3] * SCALE;
        }
    }
    __syncthreads();

    // softmax rows < 49 over cols 0..48 (cols 49..63 stay exactly 0)
    for (int row = w4; row < 49; row += 4) {
        float mx = -1e30f;
        for (int m = lane; m < 49; m += 32) mx = fmaxf(mx, Ss[row * 68 + m]);
        #pragma unroll
        for (int o = 16; o; o >>= 1) mx = fmaxf(mx, __shfl_xor_sync(0xffffffffu, mx, o));
        float sum = 0.f;
        for (int m = lane; m < 49; m += 32) {
            float p = __expf(Ss[row * 68 + m] - mx);
            Ss[row * 68 + m] = p;
            sum += p;
        }
        #pragma unroll
        for (int o = 16; o; o >>= 1) sum += __shfl_xor_sync(0xffffffffu, sum, o);
        float inv = 1.f / sum;
        for (int m = lane; m < 49; m += 32) Ss[row * 68 + m] *= inv;
    }
    __syncthreads();

    // out = P[64,64] @ V[64,32]; warp 16 rows x 32 d (4 tiles); ksteps 4
    {
        float acc[4][4];
        #pragma unroll
        for (int j = 0; j < 4; j++)
            #pragma unroll
            for (int r = 0; r < 4; r++) acc[j][r] = 0.f;
        #pragma unroll
        for (int ks = 0; ks < 4; ks++) {
            const int k = ks * 16;
            const float* S0 = Ss + (wm + lr) * 68 + k + 2 * lc;
            const float* S1 = Ss + (wm + 8 + lr) * 68 + k + 2 * lc;
            uint32_t af[4], bf[4][2];
            float2 p0 = *(const float2*)S0;
            float2 p1 = *(const float2*)S1;
            float2 p2 = *(const float2*)(S0 + 8);
            float2 p3 = *(const float2*)(S1 + 8);
            af[0] = h2pack(p0.x, p0.y);
            af[1] = h2pack(p1.x, p1.y);
            af[2] = h2pack(p2.x, p2.y);
            af[3] = h2pack(p3.x, p3.y);
            #pragma unroll
            for (int nj = 0; nj < 4; nj++) {
                int cc = nj * 8 + lr;
                bf[nj][0] = *(const uint32_t*)(Vt + cc * 72 + k + 2 * lc);
                bf[nj][1] = *(const uint32_t*)(Vt + cc * 72 + k + 2 * lc + 8);
            }
            #pragma unroll
            for (int nj = 0; nj < 4; nj++)
                MMA_F16(acc[nj], af, bf[nj]);
        }
        int r1 = wm + lr, r2 = wm + 8 + lr;
        #pragma unroll
        for (int nj = 0; nj < 4; nj++) {
            int c0 = nj * 8 + lc * 2;
            if (r1 < 49) {
                int n = (wr * 7 + r1 / 7) * 56 + wc * 7 + r1 % 7;
                *(__half2*)&x2h[((size_t)b * NTOK + n) * 128 + h * 32 + c0] =
                    __floats2half2_rn(acc[nj][0], acc[nj][1]);
            }
            if (r2 < 49) {
                int n = (wr * 7 + r2 / 7) * 56 + wc * 7 + r2 % 7;
                *(__half2*)&x2h[((size_t)b * NTOK + n) * 128 + h * 32 + c0] =
                    __floats2half2_rn(acc[nj][2], acc[nj][3]);
            }
        }
    }
}

// ---------------- host launch ----------------
extern "C" void kernel_launch(void* const* d_in, const int* in_sizes, int n_in,
                              void* d_out, int out_size) {
    const float* x           = (const float*)d_in[0];
    const float* lepe_lin_w  = (const float*)d_in[1];
    const float* lepe_lin_b  = (const float*)d_in[2];
    const float* lepe_conv_w = (const float*)d_in[3];
    const float* lepe_conv_b = (const float*)d_in[4];
    const float* sr_w        = (const float*)d_in[5];
    const float* sr_b        = (const float*)d_in[6];
    const float* norm_g      = (const float*)d_in[7];
    const float* norm_b      = (const float*)d_in[8];
    const float* q1_w        = (const float*)d_in[9];
    const float* kv1_w       = (const float*)d_in[10];
    const float* q2_w        = (const float*)d_in[11];
    const float* kv2_w       = (const float*)d_in[12];
    const float* proj_w      = (const float*)d_in[13];
    const float* proj_b      = (const float*)d_in[14];
    float* out = (float*)d_out;

    __half *xh, *wpackT, *srwT, *kv1wT, *projwT, *packh, *lepeh, *x1s, *kv1h, *x1h, *x2h;
    float *bpack, *srp;
    cudaGetSymbolAddress((void**)&xh,     g_xh);
    cudaGetSymbolAddress((void**)&wpackT, g_wpackT);
    cudaGetSymbolAddress((void**)&bpack,  g_bpack);
    cudaGetSymbolAddress((void**)&srwT,   g_srwT);
    cudaGetSymbolAddress((void**)&kv1wT,  g_kv1wT);
    cudaGetSymbolAddress((void**)&projwT, g_projwT);
    cudaGetSymbolAddress((void**)&packh,  g_packh);
    cudaGetSymbolAddress((void**)&lepeh,  g_lepeh);
    cudaGetSymbolAddress((void**)&srp,    g_srp);
    cudaGetSymbolAddress((void**)&x1s,    g_x1s);
    cudaGetSymbolAddress((void**)&kv1h,   g_kv1h);
    cudaGetSymbolAddress((void**)&x1h,    g_x1h);
    cudaGetSymbolAddress((void**)&x2h,    g_x2h);

    cudaFuncSetAttribute(tgemm_h<true>,  cudaFuncAttributeMaxDynamicSharedMemorySize, TH_SMEM);
    cudaFuncSetAttribute(tgemm_h<false>, cudaFuncAttributeMaxDynamicSharedMemorySize, TH_SMEM);
    cudaFuncSetAttribute(tgemm_sr_h,     cudaFuncAttributeMaxDynamicSharedMemorySize, TH_SMEM);
    cudaFuncSetAttribute(tgemm_proj_h,   cudaFuncAttributeMaxDynamicSharedMemorySize, TH_SMEM);
    cudaFuncSetAttribute(attn1_mma,      cudaFuncAttributeMaxDynamicSharedMemorySize, A1_SMEM);
    cudaFuncSetAttribute(attn2_mma,      cudaFuncAttributeMaxDynamicSharedMemorySize, A2_SMEM);

    static cudaStream_t s1 = nullptr;
    static cudaEvent_t evF = nullptr, evP = nullptr, evJ = nullptr;
    if (!s1) {
        cudaStreamCreateWithFlags(&s1, cudaStreamNonBlocking);
        cudaEventCreateWithFlags(&evF, cudaEventDisableTiming);
        cudaEventCreateWithFlags(&evP, cudaEventDisableTiming);
        cudaEventCreateWithFlags(&evJ, cudaEventDisableTiming);
    }

    // main: weight pack + x conversion
    pack_weightsT<<<768, 256>>>(lepe_lin_w, lepe_lin_b, q1_w, q2_w, kv2_w, wpackT, bpack);
    cvt_x<<<(M_ALL * 256 / 4) / 256, 256>>>(x, xh);
    cudaEventRecord(evF, 0);

    // s1: sr chain
    roundT<<<4096, 256, 0, s1>>>(sr_w, kv1_w, proj_w, srwT, kv1wT, projwT);
    cudaStreamWaitEvent(s1, evF, 0);
    tgemm_sr_h<<<dim3(2, M_SR / 128, 4), 256, TH_SMEM, s1>>>(xh, srwT, srp);
    ln_gelu4<<<M_SR, 256, 0, s1>>>(srp, sr_b, norm_g, norm_b, x1s);
    tgemm_h<true><<<dim3(2, M_SR / 128), 256, TH_SMEM, s1>>>(x1s, kv1wT, nullptr, kv1h, M_SR, 256, 256);

    // main: merged projection GEMM (half out) + consumers
    tgemm_h<true><<<dim3(6, M_ALL / 128), 256, TH_SMEM>>>(xh, wpackT, bpack, packh, M_ALL, 768, 256);
    cudaEventRecord(evP, 0);
    dwconv3x3<<<(BATCH * WW * CH) / 256, 256>>>(packh, lepe_conv_w, lepe_conv_b, lepeh);
    attn2_mma<<<dim3(32, BATCH * H2), 256, A2_SMEM>>>(packh, x2h);

    // s1: attn1 after pack ready
    cudaStreamWaitEvent(s1, evP, 0);
    attn1_mma<<<dim3(NTOK / 64, BATCH * H2), 256, A1_SMEM, s1>>>(packh, kv1h, x1h);
    cudaEventRecord(evJ, s1);

    // join + final projection (fp32 out)
    cudaStreamWaitEvent(0, evJ, 0);
    tgemm_proj_h<<<dim3(2, M_ALL / 128), 256, TH_SMEM>>>(x1h, x2h, lepeh, projwT, proj_b, out);
}